// round 7
// baseline (speedup 1.0000x reference)
#include <cuda_runtime.h>
#include <math.h>

#define H   128
#define GG  20
#define KNN 32
#define MAXN 24000
#define MAXE (MAXN*KNN)

// ---------------- f32x2 packed helpers (FFMA2 — PTX-only on sm_103a) --------
__device__ __forceinline__ unsigned long long pack2(float lo, float hi) {
    unsigned long long r;
    asm("mov.b64 %0, {%1, %2};" : "=l"(r) : "f"(lo), "f"(hi));
    return r;
}
__device__ __forceinline__ unsigned long long dup2(float v) {
    unsigned long long r;
    asm("mov.b64 %0, {%1, %1};" : "=l"(r) : "f"(v));
    return r;
}
__device__ __forceinline__ void unpack2(unsigned long long p, float& lo, float& hi) {
    asm("mov.b64 {%0, %1}, %2;" : "=f"(lo), "=f"(hi) : "l"(p));
}
__device__ __forceinline__ unsigned long long fma2(unsigned long long a, unsigned long long b, unsigned long long c) {
    unsigned long long d;
    asm("fma.rn.f32x2 %0, %1, %2, %3;" : "=l"(d) : "l"(a), "l"(b), "l"(c));
    return d;
}
__device__ __forceinline__ unsigned long long add2(unsigned long long a, unsigned long long b) {
    unsigned long long d;
    asm("add.rn.f32x2 %0, %1, %2;" : "=l"(d) : "l"(a), "l"(b));
    return d;
}

// ---------------- scratch (static __device__, no allocation) ----------------
__device__ __align__(16) float g_pos[MAXN*3];
__device__ __align__(16) float g_h  [MAXN*H];
__device__ __align__(16) float g_A  [MAXN*H];   // h @ W1i + b1   (dst part)
__device__ __align__(16) float g_B  [MAXN*H];   // h @ W1j        (src part)
__device__ __align__(16) float g_mi [MAXN*H];
__device__ int   g_nbr[MAXE];
__device__ float g_attr[(size_t)MAXE*GG];
__device__ float g_pre[16*H];

// ---------------- K1: embeddings + composed (sorted) layout ----------------
__global__ void embed_kernel(const float* __restrict__ ppos, const float* __restrict__ pfeat,
                             const float* __restrict__ lpos, const float* __restrict__ lfeat,
                             const float* __restrict__ pw, const float* __restrict__ pb,
                             const float* __restrict__ lw, const float* __restrict__ lb,
                             int n_prot, int n_lig, int n, int Fp, int Fl)
{
    __shared__ float sf[32];
    int i = blockIdx.x, t = threadIdx.x;
    int b = i / n, j = i - b * n;
    const float *feat, *w, *bias, *pos; int F;
    if (j < n_prot) { int r = b*n_prot + j;            feat = pfeat + (size_t)r*Fp; w = pw; bias = pb; pos = ppos + (size_t)r*3; F = Fp; }
    else            { int r = b*n_lig  + (j - n_prot); feat = lfeat + (size_t)r*Fl; w = lw; bias = lb; pos = lpos + (size_t)r*3; F = Fl; }
    if (t < F) sf[t] = feat[t];
    __syncthreads();
    float acc = bias[t];
    for (int f = 0; f < F; ++f) acc += sf[f] * w[f*H + t];
    g_h[(size_t)i*H + t] = acc;
    if (t < 3) g_pos[i*3 + t] = pos[t];
}

// ---------------- K2: brute-force kNN (float4 smem, stable tie-break) -------
__global__ void knn_kernel(int n)
{
    extern __shared__ float4 spos4[];
    int b = blockIdx.y, tid = threadIdx.x;
    const float* gp = g_pos + (size_t)b*n*3;
    for (int i = tid; i < n; i += blockDim.x)
        spos4[i] = make_float4(gp[i*3], gp[i*3+1], gp[i*3+2], 0.f);
    __syncthreads();
    int c = blockIdx.x*blockDim.x + tid;
    if (c >= n) return;
    float4 pc = spos4[c];
    float bd[KNN]; int bi[KNN];
#pragma unroll
    for (int s = 0; s < KNN; ++s) { bd[s] = 3.402823466e38f; bi[s] = 0x7fffffff; }
    float wd = 3.402823466e38f; int wi = 0x7fffffff; int ws = 0;
    for (int j = 0; j < n; ++j) {
        if (j == c) continue;
        float4 pj = spos4[j];
        float dx = pc.x - pj.x, dy = pc.y - pj.y, dz = pc.z - pj.z;
        float d2 = dx*dx + dy*dy + dz*dz;
        if (d2 < wd || (d2 == wd && j < wi)) {
            bd[ws] = d2; bi[ws] = j;
            wd = bd[0]; wi = bi[0]; ws = 0;
#pragma unroll
            for (int s = 1; s < KNN; ++s)
                if (bd[s] > wd || (bd[s] == wd && bi[s] > wi)) { wd = bd[s]; wi = bi[s]; ws = s; }
        }
    }
    size_t base = ((size_t)(b*n + c))*KNN;
#pragma unroll
    for (int s = 0; s < KNN; ++s) g_nbr[base + s] = b*n + bi[s];
}

// ---------------- K3: Gaussian smearing + zero g_pre ------------------------
__global__ void attr_kernel(int E, float step, float coeff)
{
    int e = blockIdx.x*blockDim.x + threadIdx.x;
    if (e >= E) return;
    if (e < 16*H) g_pre[e] = 0.f;
    int dst = e >> 5;
    int src = g_nbr[e];
    float dx = g_pos[dst*3]   - g_pos[src*3];
    float dy = g_pos[dst*3+1] - g_pos[src*3+1];
    float dz = g_pos[dst*3+2] - g_pos[src*3+2];
    float d = sqrtf(dx*dx + dy*dy + dz*dz);
    size_t o = (size_t)e*GG;
#pragma unroll
    for (int g = 0; g < GG; ++g) {
        float t = d - g*step;
        g_attr[o + g] = expf(coeff*t*t);
    }
}

// ---------------- K4: A = h@W1i + b1, B = h@W1j  (layer 0 only) -------------
__global__ void __launch_bounds__(256) ab_kernel(const float* __restrict__ edge_w1,
                                                 const float* __restrict__ edge_b1, int l)
{
    __shared__ float sHt[128*34];
    int tid = threadIdx.x;
    int nb = blockIdx.x*32;
    for (int i = tid; i < 32*H; i += 256) { int nn = i>>7, k = i&127; sHt[k*34+nn] = g_h[(size_t)(nb+nn)*H + k]; }
    __syncthreads();
    int cg = tid & 15, ng = tid >> 4, col = cg*8;
    const ulonglong2* WA = (const ulonglong2*)(edge_w1 + (size_t)l*276*H + GG*H);
    const ulonglong2* WB = (const ulonglong2*)(edge_w1 + (size_t)l*276*H + (GG+H)*H);
    unsigned long long accA[2][4], accB[2][4];
#pragma unroll
    for (int c2 = 0; c2 < 4; ++c2) {
        unsigned long long b0 = pack2(edge_b1[l*H + col + 2*c2], edge_b1[l*H + col + 2*c2 + 1]);
        accA[0][c2] = b0; accA[1][c2] = b0; accB[0][c2] = 0ull; accB[1][c2] = 0ull;
    }
#pragma unroll 4
    for (int k = 0; k < H; ++k) {
        float2 a = *(const float2*)(sHt + k*34 + ng*2);
        ulonglong2 wa0 = __ldg(WA + k*32 + cg*2);
        ulonglong2 wa1 = __ldg(WA + k*32 + cg*2 + 1);
        ulonglong2 wb0 = __ldg(WB + k*32 + cg*2);
        ulonglong2 wb1 = __ldg(WB + k*32 + cg*2 + 1);
        unsigned long long a0 = dup2(a.x), a1 = dup2(a.y);
        unsigned long long wap[4] = {wa0.x, wa0.y, wa1.x, wa1.y};
        unsigned long long wbp[4] = {wb0.x, wb0.y, wb1.x, wb1.y};
#pragma unroll
        for (int c2 = 0; c2 < 4; ++c2) {
            accA[0][c2] = fma2(a0, wap[c2], accA[0][c2]);
            accA[1][c2] = fma2(a1, wap[c2], accA[1][c2]);
            accB[0][c2] = fma2(a0, wbp[c2], accB[0][c2]);
            accB[1][c2] = fma2(a1, wbp[c2], accB[1][c2]);
        }
    }
#pragma unroll
    for (int r = 0; r < 2; ++r) {
        float va[8], vb[8];
#pragma unroll
        for (int c2 = 0; c2 < 4; ++c2) {
            unpack2(accA[r][c2], va[2*c2], va[2*c2+1]);
            unpack2(accB[r][c2], vb[2*c2], vb[2*c2+1]);
        }
        size_t o = (size_t)(nb + ng*2 + r)*H + col;
        *(float4*)(g_A + o)     = make_float4(va[0],va[1],va[2],va[3]);
        *(float4*)(g_A + o + 4) = make_float4(va[4],va[5],va[6],va[7]);
        *(float4*)(g_B + o)     = make_float4(vb[0],vb[1],vb[2],vb[3]);
        *(float4*)(g_B + o + 4) = make_float4(vb[4],vb[5],vb[6],vb[7]);
    }
}

// ---------------- K5: fused edge MLP + gate + segment-sum -------------------
// 512 threads, 128 edges/block (4 dst), TWO k-phases (sm1 holds 64 k's),
// per-thread tile 4 edges x 8 cols. smem ~59KB -> 2 CTAs = 32 warps/SM.
__global__ __launch_bounds__(512,2) void edge_kernel(const float* __restrict__ edge_w1,
                                                     const float* __restrict__ edge_b2,
                                                     const float* __restrict__ edge_w2v,
                                                     const float* __restrict__ inf_w,
                                                     const float* __restrict__ inf_b, int l)
{
    extern __shared__ float sh[];
    float* sm1   = sh;                 // [64 k][132 e]  (k-major, padded)
    float* sW1e  = sm1 + 64*132;       // 20*128
    float* sattr = sW1e + GG*H;        // 128*20
    float* sA    = sattr + 128*GG;     // 4*128
    float* sb2   = sA + 4*H;           // 128
    float* sinfw = sb2 + H;            // 128
    float* sgate = sinfw + H;          // 128
    float* smi   = sgate + H;          // 4*128
    int*   ssrc  = (int*)(smi + 4*H);  // 128

    int tid = threadIdx.x;
    int e0 = blockIdx.x * 128;
    int d0 = e0 >> 5;
    const float* W1b = edge_w1 + (size_t)l*276*H;
    for (int i = tid; i < GG*H;   i += 512) sW1e[i]  = W1b[i];
    for (int i = tid; i < 128*GG; i += 512) sattr[i] = g_attr[(size_t)e0*GG + i];
    for (int i = tid; i < 4*H;    i += 512) { sA[i] = g_A[(size_t)d0*H + i]; smi[i] = 0.f; }
    if (tid < H) { sb2[tid] = edge_b2[l*H+tid]; sinfw[tid] = inf_w[l*H+tid]; sgate[tid] = inf_b[l]; }
    if (tid < 128) ssrc[tid] = g_nbr[e0 + tid];
    __syncthreads();

    int rg = tid >> 4, cg = tid & 15, col = cg*8;   // rows rg*4..+4, cols col..+8
    const ulonglong2* W2v = (const ulonglong2*)(edge_w2v + (size_t)l*H*H);
    // step-A thread mapping: 4 threads per edge, each covers 16 k's of the phase
    int ea = tid >> 2, q = tid & 3;
    int srcA = ssrc[ea];
    int dA = ea >> 5;
    const float4* Brow = (const float4*)(g_B + (size_t)srcA*H);
    const float* sAd = sA + dA*H;

    unsigned long long accp[4][4];
#pragma unroll
    for (int r = 0; r < 4; ++r)
#pragma unroll
        for (int c2 = 0; c2 < 4; ++c2) accp[r][c2] = 0ull;

    for (int p = 0; p < 2; ++p) {
        // step A: m1[k][e] = relu(attr@W1e + A[dst] + B[src]) for this k-phase
#pragma unroll
        for (int i4 = 0; i4 < 4; ++i4) {
            int kg = p*64 + q*16 + i4*4;
            float4 bv = Brow[kg >> 2];
            unsigned long long v0 = add2(*(const unsigned long long*)(sAd + kg),     pack2(bv.x, bv.y));
            unsigned long long v1 = add2(*(const unsigned long long*)(sAd + kg + 2), pack2(bv.z, bv.w));
#pragma unroll
            for (int g = 0; g < GG; ++g) {
                unsigned long long ag = dup2(sattr[ea*GG + g]);
                v0 = fma2(ag, *(const unsigned long long*)(sW1e + g*H + kg),     v0);
                v1 = fma2(ag, *(const unsigned long long*)(sW1e + g*H + kg + 2), v1);
            }
            float x0, x1, x2, x3;
            unpack2(v0, x0, x1); unpack2(v1, x2, x3);
            int kl = q*16 + i4*4;
            sm1[(kl+0)*132 + ea] = fmaxf(x0, 0.f);
            sm1[(kl+1)*132 + ea] = fmaxf(x1, 0.f);
            sm1[(kl+2)*132 + ea] = fmaxf(x2, 0.f);
            sm1[(kl+3)*132 + ea] = fmaxf(x3, 0.f);
        }
        __syncthreads();

        // step B: accumulate this phase's 64 k's
#pragma unroll 4
        for (int k = 0; k < 64; ++k) {
            float4 a = *(const float4*)(sm1 + k*132 + rg*4);
            ulonglong2 b0 = __ldg(W2v + (p*64+k)*32 + cg*2);
            ulonglong2 b1 = __ldg(W2v + (p*64+k)*32 + cg*2 + 1);
            unsigned long long bp[4] = {b0.x, b0.y, b1.x, b1.y};
            unsigned long long ad[4];
            ad[0] = dup2(a.x); ad[1] = dup2(a.y); ad[2] = dup2(a.z); ad[3] = dup2(a.w);
#pragma unroll
            for (int r = 0; r < 4; ++r)
#pragma unroll
                for (int c2 = 0; c2 < 4; ++c2) accp[r][c2] = fma2(ad[r], bp[c2], accp[r][c2]);
        }
        __syncthreads();   // before next phase's step A overwrites sm1
    }

    // bias + relu
    float acc[4][8];
#pragma unroll
    for (int r = 0; r < 4; ++r) {
#pragma unroll
        for (int c2 = 0; c2 < 4; ++c2) unpack2(accp[r][c2], acc[r][2*c2], acc[r][2*c2+1]);
#pragma unroll
        for (int c = 0; c < 8; ++c) acc[r][c] = fmaxf(acc[r][c] + sb2[col+c], 0.f);
    }

    // step C: gate logits
#pragma unroll
    for (int r = 0; r < 4; ++r) {
        float p = 0.f;
#pragma unroll
        for (int c = 0; c < 8; ++c) p += acc[r][c]*sinfw[col+c];
        atomicAdd(&sgate[rg*4 + r], p);
    }
    __syncthreads();
    if (tid < H) sgate[tid] = 1.f/(1.f + expf(-sgate[tid]));
    __syncthreads();

    // step D: mi[dst] = sum_e m*gate  (4-row group never straddles a dst)
    {
        int d = rg >> 3;
#pragma unroll
        for (int c = 0; c < 8; ++c) {
            float s = 0.f;
#pragma unroll
            for (int r = 0; r < 4; ++r) s += acc[r][c]*sgate[rg*4 + r];
            atomicAdd(&smi[d*H + col + c], s);
        }
    }
    __syncthreads();
    for (int i = tid; i < 4*H; i += 512) g_mi[(size_t)d0*H + i] = smi[i];
}

// ---------------- K6: node MLP + residual + fused next-layer A/B ------------
__global__ void __launch_bounds__(256) node_kernel(const float* __restrict__ nw1,
                                                   const float* __restrict__ nb1,
                                                   const float* __restrict__ nw2,
                                                   const float* __restrict__ nb2,
                                                   const float* __restrict__ edge_w1,
                                                   const float* __restrict__ edge_b1, int l)
{
    __shared__ float sZ[256*34];   // [mi | h] k-major; reused for u, then h_new
    int tid = threadIdx.x;
    int nb = blockIdx.x*32;
    for (int i = tid; i < 32*H; i += 256) {
        int nn = i>>7, k = i&127;
        sZ[k*34 + nn]     = g_mi[(size_t)(nb+nn)*H + k];
        sZ[(H+k)*34 + nn] = g_h [(size_t)(nb+nn)*H + k];
    }
    __syncthreads();
    int cg = tid & 15, ng = tid >> 4, col = cg*8;
    const ulonglong2* W1a = (const ulonglong2*)(nw1 + (size_t)l*2*H*H);
    const ulonglong2* W1b = W1a + H*H/4;
    unsigned long long acc[2][4];
#pragma unroll
    for (int c2 = 0; c2 < 4; ++c2) {
        unsigned long long b = pack2(nb1[l*H + col + 2*c2], nb1[l*H + col + 2*c2 + 1]);
        acc[0][c2] = b; acc[1][c2] = b;
    }
#pragma unroll 4
    for (int k = 0; k < H; ++k) {
        float2 am = *(const float2*)(sZ + k*34 + ng*2);
        float2 ah = *(const float2*)(sZ + (H+k)*34 + ng*2);
        ulonglong2 wa0 = __ldg(W1a + k*32 + cg*2);
        ulonglong2 wa1 = __ldg(W1a + k*32 + cg*2 + 1);
        ulonglong2 wb0 = __ldg(W1b + k*32 + cg*2);
        ulonglong2 wb1 = __ldg(W1b + k*32 + cg*2 + 1);
        unsigned long long m0 = dup2(am.x), m1 = dup2(am.y);
        unsigned long long h0 = dup2(ah.x), h1 = dup2(ah.y);
        unsigned long long wap[4] = {wa0.x, wa0.y, wa1.x, wa1.y};
        unsigned long long wbp[4] = {wb0.x, wb0.y, wb1.x, wb1.y};
#pragma unroll
        for (int c2 = 0; c2 < 4; ++c2) {
            acc[0][c2] = fma2(m0, wap[c2], acc[0][c2]);
            acc[1][c2] = fma2(m1, wap[c2], acc[1][c2]);
            acc[0][c2] = fma2(h0, wbp[c2], acc[0][c2]);
            acc[1][c2] = fma2(h1, wbp[c2], acc[1][c2]);
        }
    }
    __syncthreads();   // done reading sZ
#pragma unroll
    for (int r = 0; r < 2; ++r)
#pragma unroll
        for (int c2 = 0; c2 < 4; ++c2) {
            float lo, hi;
            unpack2(acc[r][c2], lo, hi);
            sZ[(col + 2*c2)*34 + ng*2 + r]     = fmaxf(lo, 0.f);
            sZ[(col + 2*c2 + 1)*34 + ng*2 + r] = fmaxf(hi, 0.f);
        }
    __syncthreads();
    const ulonglong2* W2 = (const ulonglong2*)(nw2 + (size_t)l*H*H);
    unsigned long long acc2[2][4];
#pragma unroll
    for (int c2 = 0; c2 < 4; ++c2) {
        unsigned long long b = pack2(nb2[l*H + col + 2*c2], nb2[l*H + col + 2*c2 + 1]);
        acc2[0][c2] = b; acc2[1][c2] = b;
    }
#pragma unroll 4
    for (int k = 0; k < H; ++k) {
        float2 a  = *(const float2*)(sZ + k*34 + ng*2);
        ulonglong2 w0 = __ldg(W2 + k*32 + cg*2);
        ulonglong2 w1 = __ldg(W2 + k*32 + cg*2 + 1);
        unsigned long long a0 = dup2(a.x), a1 = dup2(a.y);
        unsigned long long wp[4] = {w0.x, w0.y, w1.x, w1.y};
#pragma unroll
        for (int c2 = 0; c2 < 4; ++c2) {
            acc2[0][c2] = fma2(a0, wp[c2], acc2[0][c2]);
            acc2[1][c2] = fma2(a1, wp[c2], acc2[1][c2]);
        }
    }
    float hn[2][8];
#pragma unroll
    for (int r = 0; r < 2; ++r) {
        float v[8];
#pragma unroll
        for (int c2 = 0; c2 < 4; ++c2) unpack2(acc2[r][c2], v[2*c2], v[2*c2+1]);
        size_t o = (size_t)(nb + ng*2 + r)*H + col;
        float4* hp = (float4*)(g_h + o);
        float4 h0 = hp[0], h1 = hp[1];
        hn[r][0] = h0.x + v[0]; hn[r][1] = h0.y + v[1]; hn[r][2] = h0.z + v[2]; hn[r][3] = h0.w + v[3];
        hn[r][4] = h1.x + v[4]; hn[r][5] = h1.y + v[5]; hn[r][6] = h1.z + v[6]; hn[r][7] = h1.w + v[7];
        hp[0] = make_float4(hn[r][0], hn[r][1], hn[r][2], hn[r][3]);
        hp[1] = make_float4(hn[r][4], hn[r][5], hn[r][6], hn[r][7]);
    }

    // ---- fused next-layer A/B (layers 0,1 only) ----
    if (l < 2) {
        __syncthreads();   // everyone done reading sZ (u) in acc2 loop
#pragma unroll
        for (int r = 0; r < 2; ++r)
#pragma unroll
            for (int c = 0; c < 8; ++c) sZ[(col + c)*34 + ng*2 + r] = hn[r][c];
        __syncthreads();
        int nl = l + 1;
        const ulonglong2* WA = (const ulonglong2*)(edge_w1 + (size_t)nl*276*H + GG*H);
        const ulonglong2* WB = (const ulonglong2*)(edge_w1 + (size_t)nl*276*H + (GG+H)*H);
        unsigned long long accA[2][4], accB[2][4];
#pragma unroll
        for (int c2 = 0; c2 < 4; ++c2) {
            unsigned long long b = pack2(edge_b1[nl*H + col + 2*c2], edge_b1[nl*H + col + 2*c2 + 1]);
            accA[0][c2] = b; accA[1][c2] = b; accB[0][c2] = 0ull; accB[1][c2] = 0ull;
        }
#pragma unroll 4
        for (int k = 0; k < H; ++k) {
            float2 a = *(const float2*)(sZ + k*34 + ng*2);
            ulonglong2 wa0 = __ldg(WA + k*32 + cg*2);
            ulonglong2 wa1 = __ldg(WA + k*32 + cg*2 + 1);
            ulonglong2 wb0 = __ldg(WB + k*32 + cg*2);
            ulonglong2 wb1 = __ldg(WB + k*32 + cg*2 + 1);
            unsigned long long a0 = dup2(a.x), a1 = dup2(a.y);
            unsigned long long wap[4] = {wa0.x, wa0.y, wa1.x, wa1.y};
            unsigned long long wbp[4] = {wb0.x, wb0.y, wb1.x, wb1.y};
#pragma unroll
            for (int c2 = 0; c2 < 4; ++c2) {
                accA[0][c2] = fma2(a0, wap[c2], accA[0][c2]);
                accA[1][c2] = fma2(a1, wap[c2], accA[1][c2]);
                accB[0][c2] = fma2(a0, wbp[c2], accB[0][c2]);
                accB[1][c2] = fma2(a1, wbp[c2], accB[1][c2]);
            }
        }
#pragma unroll
        for (int r = 0; r < 2; ++r) {
            float va[8], vb[8];
#pragma unroll
            for (int c2 = 0; c2 < 4; ++c2) {
                unpack2(accA[r][c2], va[2*c2], va[2*c2+1]);
                unpack2(accB[r][c2], vb[2*c2], vb[2*c2+1]);
            }
            size_t o = (size_t)(nb + ng*2 + r)*H + col;
            *(float4*)(g_A + o)     = make_float4(va[0],va[1],va[2],va[3]);
            *(float4*)(g_A + o + 4) = make_float4(va[4],va[5],va[6],va[7]);
            *(float4*)(g_B + o)     = make_float4(vb[0],vb[1],vb[2],vb[3]);
            *(float4*)(g_B + o + 4) = make_float4(vb[4],vb[5],vb[6],vb[7]);
        }
    }
}

// ---------------- K7: per-graph pooling (parallel + atomics) ----------------
__global__ void pool_kernel(int n)
{
    int b = blockIdx.x >> 4, s = blockIdx.x & 15;
    int c = threadIdx.x;  // 128 threads
    float acc = 0.f;
    for (int i = s; i < n; i += 16) acc += g_h[((size_t)b*n + i)*H + c];
    atomicAdd(&g_pre[b*H + c], acc);
}

// ---------------- K8: out_block + output selection ---------------------------
__global__ void out_kernel(const float* __restrict__ w1, const float* __restrict__ b1,
                           const float* __restrict__ w2, const float* __restrict__ b2,
                           const int* __restrict__ kind, float* __restrict__ out, int B)
{
    __shared__ float sU[H]; __shared__ float so[3];
    int t = threadIdx.x;
    for (int b = 0; b < B; ++b) {
        float x = b1[t];
        for (int k = 0; k < H; ++k) x += g_pre[b*H + k]*w1[k*H + t];
        float sp = (x > 0.f) ? x + log1pf(expf(-x)) : log1pf(expf(x));
        sU[t] = sp - 0.6931471805599453f;
        __syncthreads();
        if (t < 3) { float s = b2[t]; for (int k = 0; k < H; ++k) s += sU[k]*w2[k*3 + t]; so[t] = s; }
        __syncthreads();
        if (t == 0) out[b] = so[kind[b] - 1];
        __syncthreads();
    }
}

// ---------------- host ------------------------------------------------------
#define EDGE_SMEM ((64*132 + 20*128 + 128*20 + 4*128 + 128 + 128 + 128 + 4*128 + 128)*4)

extern "C" void kernel_launch(void* const* d_in, const int* in_sizes, int n_in,
                              void* d_out, int out_size)
{
    const float* protein_pos  = (const float*)d_in[0];
    const float* protein_feat = (const float*)d_in[1];
    const float* ligand_pos   = (const float*)d_in[2];
    const float* ligand_feat  = (const float*)d_in[3];
    const int*   output_kind  = (const int*)d_in[6];
    const float* prot_w = (const float*)d_in[7];  const float* prot_b = (const float*)d_in[8];
    const float* lig_w  = (const float*)d_in[9];  const float* lig_b  = (const float*)d_in[10];
    const float* edge_w1 = (const float*)d_in[11]; const float* edge_b1 = (const float*)d_in[12];
    const float* edge_w2 = (const float*)d_in[13]; const float* edge_b2 = (const float*)d_in[14];
    const float* inf_w   = (const float*)d_in[15]; const float* inf_b   = (const float*)d_in[16];
    const float* node_w1 = (const float*)d_in[17]; const float* node_b1 = (const float*)d_in[18];
    const float* node_w2 = (const float*)d_in[19]; const float* node_b2 = (const float*)d_in[20];
    const float* out_w1  = (const float*)d_in[21]; const float* out_b1  = (const float*)d_in[22];
    const float* out_w2  = (const float*)d_in[23]; const float* out_b2  = (const float*)d_in[24];
    float* out = (float*)d_out;

    int Np = in_sizes[0]/3, Nl = in_sizes[2]/3;
    int B  = in_sizes[6];
    int Fp = in_sizes[1]/Np, Fl = in_sizes[3]/Nl;
    int n_prot = Np/B, n_lig = Nl/B;
    int n = n_prot + n_lig;
    int N = Np + Nl;
    int E = N*KNN;

    cudaFuncSetAttribute(edge_kernel, cudaFuncAttributeMaxDynamicSharedMemorySize, EDGE_SMEM);

    embed_kernel<<<N, 128>>>(protein_pos, protein_feat, ligand_pos, ligand_feat,
                             prot_w, prot_b, lig_w, lig_b, n_prot, n_lig, n, Fp, Fl);

    knn_kernel<<<dim3((n + 127)/128, B), 128, n*(int)sizeof(float4)>>>(n);

    float step  = 10.0f/19.0f;           // CUTOFF / (G-1)
    float coeff = -0.5f/(step*step);
    attr_kernel<<<(E + 255)/256, 256>>>(E, step, coeff);

    ab_kernel<<<N/32, 256>>>(edge_w1, edge_b1, 0);
    for (int l = 0; l < 3; ++l) {
        edge_kernel<<<E/128, 512, EDGE_SMEM>>>(edge_w1, edge_b2, edge_w2, inf_w, inf_b, l);
        node_kernel<<<N/32, 256>>>(node_w1, node_b1, node_w2, node_b2, edge_w1, edge_b1, l);
    }

    pool_kernel<<<B*16, 128>>>(n);
    out_kernel<<<1, 128>>>(out_w1, out_b1, out_w2, out_b2, output_kind, out, B);
}

// round 8
// speedup vs baseline: 1.2239x; 1.2239x over previous
#include <cuda_runtime.h>
#include <math.h>

#define H   128
#define GG  20
#define KNN 32
#define MAXN 24000
#define MAXE (MAXN*KNN)

// ---------------- f32x2 packed helpers (FFMA2 — PTX-only on sm_103a) --------
__device__ __forceinline__ unsigned long long pack2(float lo, float hi) {
    unsigned long long r;
    asm("mov.b64 %0, {%1, %2};" : "=l"(r) : "f"(lo), "f"(hi));
    return r;
}
__device__ __forceinline__ unsigned long long dup2(float v) {
    unsigned long long r;
    asm("mov.b64 %0, {%1, %1};" : "=l"(r) : "f"(v));
    return r;
}
__device__ __forceinline__ void unpack2(unsigned long long p, float& lo, float& hi) {
    asm("mov.b64 {%0, %1}, %2;" : "=f"(lo), "=f"(hi) : "l"(p));
}
__device__ __forceinline__ unsigned long long fma2(unsigned long long a, unsigned long long b, unsigned long long c) {
    unsigned long long d;
    asm("fma.rn.f32x2 %0, %1, %2, %3;" : "=l"(d) : "l"(a), "l"(b), "l"(c));
    return d;
}
__device__ __forceinline__ unsigned long long add2(unsigned long long a, unsigned long long b) {
    unsigned long long d;
    asm("add.rn.f32x2 %0, %1, %2;" : "=l"(d) : "l"(a), "l"(b));
    return d;
}

// ---------------- scratch (static __device__, no allocation) ----------------
__device__ __align__(16) float g_pos[MAXN*3];
__device__ __align__(16) float g_h  [MAXN*H];
__device__ __align__(16) float g_A  [MAXN*H];   // h @ W1i + b1   (dst part)
__device__ __align__(16) float g_B  [MAXN*H];   // h @ W1j        (src part)
__device__ __align__(16) float g_mi [MAXN*H];
__device__ int   g_nbr[MAXE];
__device__ float g_attr[(size_t)MAXE*GG];
__device__ float g_pre[16*H];

// ---------------- K1: embeddings + composed (sorted) layout ----------------
__global__ void embed_kernel(const float* __restrict__ ppos, const float* __restrict__ pfeat,
                             const float* __restrict__ lpos, const float* __restrict__ lfeat,
                             const float* __restrict__ pw, const float* __restrict__ pb,
                             const float* __restrict__ lw, const float* __restrict__ lb,
                             int n_prot, int n_lig, int n, int Fp, int Fl)
{
    __shared__ float sf[32];
    int i = blockIdx.x, t = threadIdx.x;
    int b = i / n, j = i - b * n;
    const float *feat, *w, *bias, *pos; int F;
    if (j < n_prot) { int r = b*n_prot + j;            feat = pfeat + (size_t)r*Fp; w = pw; bias = pb; pos = ppos + (size_t)r*3; F = Fp; }
    else            { int r = b*n_lig  + (j - n_prot); feat = lfeat + (size_t)r*Fl; w = lw; bias = lb; pos = lpos + (size_t)r*3; F = Fl; }
    if (t < F) sf[t] = feat[t];
    __syncthreads();
    float acc = bias[t];
    for (int f = 0; f < F; ++f) acc += sf[f] * w[f*H + t];
    g_h[(size_t)i*H + t] = acc;
    if (t < 3) g_pos[i*3 + t] = pos[t];
}

// ---------------- K2: brute-force kNN (float4 smem, stable tie-break) -------
__global__ void knn_kernel(int n)
{
    extern __shared__ float4 spos4[];
    int b = blockIdx.y, tid = threadIdx.x;
    const float* gp = g_pos + (size_t)b*n*3;
    for (int i = tid; i < n; i += blockDim.x)
        spos4[i] = make_float4(gp[i*3], gp[i*3+1], gp[i*3+2], 0.f);
    __syncthreads();
    int c = blockIdx.x*blockDim.x + tid;
    if (c >= n) return;
    float4 pc = spos4[c];
    float bd[KNN]; int bi[KNN];
#pragma unroll
    for (int s = 0; s < KNN; ++s) { bd[s] = 3.402823466e38f; bi[s] = 0x7fffffff; }
    float wd = 3.402823466e38f; int wi = 0x7fffffff; int ws = 0;
    for (int j = 0; j < n; ++j) {
        if (j == c) continue;
        float4 pj = spos4[j];
        float dx = pc.x - pj.x, dy = pc.y - pj.y, dz = pc.z - pj.z;
        float d2 = dx*dx + dy*dy + dz*dz;
        if (d2 < wd || (d2 == wd && j < wi)) {
            bd[ws] = d2; bi[ws] = j;
            wd = bd[0]; wi = bi[0]; ws = 0;
#pragma unroll
            for (int s = 1; s < KNN; ++s)
                if (bd[s] > wd || (bd[s] == wd && bi[s] > wi)) { wd = bd[s]; wi = bi[s]; ws = s; }
        }
    }
    size_t base = ((size_t)(b*n + c))*KNN;
#pragma unroll
    for (int s = 0; s < KNN; ++s) g_nbr[base + s] = b*n + bi[s];
}

// ---------------- K3: Gaussian smearing + zero g_pre ------------------------
__global__ void attr_kernel(int E, float step, float coeff)
{
    int e = blockIdx.x*blockDim.x + threadIdx.x;
    if (e >= E) return;
    if (e < 16*H) g_pre[e] = 0.f;
    int dst = e >> 5;
    int src = g_nbr[e];
    float dx = g_pos[dst*3]   - g_pos[src*3];
    float dy = g_pos[dst*3+1] - g_pos[src*3+1];
    float dz = g_pos[dst*3+2] - g_pos[src*3+2];
    float d = sqrtf(dx*dx + dy*dy + dz*dz);
    size_t o = (size_t)e*GG;
#pragma unroll
    for (int g = 0; g < GG; ++g) {
        float t = d - g*step;
        g_attr[o + g] = expf(coeff*t*t);
    }
}

// ---------------- K4: A = h@W1i + b1, B = h@W1j  (layer 0 only) -------------
__global__ void __launch_bounds__(256) ab_kernel(const float* __restrict__ edge_w1,
                                                 const float* __restrict__ edge_b1, int l)
{
    __shared__ float sHt[128*34];
    int tid = threadIdx.x;
    int nb = blockIdx.x*32;
    for (int i = tid; i < 32*H; i += 256) { int nn = i>>7, k = i&127; sHt[k*34+nn] = g_h[(size_t)(nb+nn)*H + k]; }
    __syncthreads();
    int cg = tid & 15, ng = tid >> 4, col = cg*8;
    const ulonglong2* WA = (const ulonglong2*)(edge_w1 + (size_t)l*276*H + GG*H);
    const ulonglong2* WB = (const ulonglong2*)(edge_w1 + (size_t)l*276*H + (GG+H)*H);
    unsigned long long accA[2][4], accB[2][4];
#pragma unroll
    for (int c2 = 0; c2 < 4; ++c2) {
        unsigned long long b0 = pack2(edge_b1[l*H + col + 2*c2], edge_b1[l*H + col + 2*c2 + 1]);
        accA[0][c2] = b0; accA[1][c2] = b0; accB[0][c2] = 0ull; accB[1][c2] = 0ull;
    }
#pragma unroll 4
    for (int k = 0; k < H; ++k) {
        float2 a = *(const float2*)(sHt + k*34 + ng*2);
        ulonglong2 wa0 = __ldg(WA + k*32 + cg*2);
        ulonglong2 wa1 = __ldg(WA + k*32 + cg*2 + 1);
        ulonglong2 wb0 = __ldg(WB + k*32 + cg*2);
        ulonglong2 wb1 = __ldg(WB + k*32 + cg*2 + 1);
        unsigned long long a0 = dup2(a.x), a1 = dup2(a.y);
        unsigned long long wap[4] = {wa0.x, wa0.y, wa1.x, wa1.y};
        unsigned long long wbp[4] = {wb0.x, wb0.y, wb1.x, wb1.y};
#pragma unroll
        for (int c2 = 0; c2 < 4; ++c2) {
            accA[0][c2] = fma2(a0, wap[c2], accA[0][c2]);
            accA[1][c2] = fma2(a1, wap[c2], accA[1][c2]);
            accB[0][c2] = fma2(a0, wbp[c2], accB[0][c2]);
            accB[1][c2] = fma2(a1, wbp[c2], accB[1][c2]);
        }
    }
#pragma unroll
    for (int r = 0; r < 2; ++r) {
        float va[8], vb[8];
#pragma unroll
        for (int c2 = 0; c2 < 4; ++c2) {
            unpack2(accA[r][c2], va[2*c2], va[2*c2+1]);
            unpack2(accB[r][c2], vb[2*c2], vb[2*c2+1]);
        }
        size_t o = (size_t)(nb + ng*2 + r)*H + col;
        *(float4*)(g_A + o)     = make_float4(va[0],va[1],va[2],va[3]);
        *(float4*)(g_A + o + 4) = make_float4(va[4],va[5],va[6],va[7]);
        *(float4*)(g_B + o)     = make_float4(vb[0],vb[1],vb[2],vb[3]);
        *(float4*)(g_B + o + 4) = make_float4(vb[4],vb[5],vb[6],vb[7]);
    }
}

// ---------------- K5: fused edge MLP + gate + segment-sum -------------------
// 256 threads, 128 edges/block (4 dst), 8x8 per-thread tile (one W2 load per
// 8 rows), sm1 split into TWO 64-k phases => smem ~60KB so 2 CTAs leave
// ~106KB L1D and the 64KB W2 stays L1-resident.
__global__ __launch_bounds__(256,2) void edge_kernel(const float* __restrict__ edge_w1,
                                                     const float* __restrict__ edge_b2,
                                                     const float* __restrict__ edge_w2v,
                                                     const float* __restrict__ inf_w,
                                                     const float* __restrict__ inf_b, int l)
{
    extern __shared__ float sh[];
    float* sm1   = sh;                 // [64 k][132 e]  (k-major, padded)
    float* sW1e  = sm1 + 64*132;       // 20*128
    float* sattr = sW1e + GG*H;        // 128*20
    float* sA    = sattr + 128*GG;     // 4*128
    float* sb2   = sA + 4*H;           // 128
    float* sinfw = sb2 + H;            // 128
    float* sgate = sinfw + H;          // 128
    float* smi   = sgate + H;          // 4*128
    int*   ssrc  = (int*)(smi + 4*H);  // 128

    int tid = threadIdx.x;
    int e0 = blockIdx.x * 128;
    int d0 = e0 >> 5;
    const float* W1b = edge_w1 + (size_t)l*276*H;
    for (int i = tid; i < GG*H;   i += 256) sW1e[i]  = W1b[i];
    for (int i = tid; i < 128*GG; i += 256) sattr[i] = g_attr[(size_t)e0*GG + i];
    for (int i = tid; i < 4*H;    i += 256) { sA[i] = g_A[(size_t)d0*H + i]; smi[i] = 0.f; }
    if (tid < H) { sb2[tid] = edge_b2[l*H+tid]; sinfw[tid] = inf_w[l*H+tid]; sgate[tid] = inf_b[l]; }
    if (tid < 128) ssrc[tid] = g_nbr[e0 + tid];
    __syncthreads();

    int rg = tid >> 4, cg = tid & 15, col = cg*8;   // rows rg*8..+8, cols col..+8
    const ulonglong2* W2v = (const ulonglong2*)(edge_w2v + (size_t)l*H*H);
    // step-A mapping: 2 threads per edge, each covers 32 k's of the 64-k phase
    int ea = tid >> 1, half = tid & 1;
    int srcA = ssrc[ea];
    int dA = ea >> 5;
    const float4* Brow = (const float4*)(g_B + (size_t)srcA*H);
    const float* sAd = sA + dA*H;
    unsigned long long a20d[GG];
#pragma unroll
    for (int g = 0; g < GG; ++g) a20d[g] = dup2(sattr[ea*GG + g]);

    unsigned long long accp[8][4];
#pragma unroll
    for (int r = 0; r < 8; ++r)
#pragma unroll
        for (int c2 = 0; c2 < 4; ++c2) accp[r][c2] = 0ull;

    for (int p = 0; p < 2; ++p) {
        // step A: m1[k][e] = relu(attr@W1e + A[dst] + B[src]) for this k-phase
#pragma unroll
        for (int i4 = 0; i4 < 8; ++i4) {
            int kl = half*32 + i4*4;     // k within phase
            int kg = p*64 + kl;          // global k
            float4 bv = Brow[kg >> 2];
            unsigned long long v0 = add2(*(const unsigned long long*)(sAd + kg),     pack2(bv.x, bv.y));
            unsigned long long v1 = add2(*(const unsigned long long*)(sAd + kg + 2), pack2(bv.z, bv.w));
#pragma unroll
            for (int g = 0; g < GG; ++g) {
                v0 = fma2(a20d[g], *(const unsigned long long*)(sW1e + g*H + kg),     v0);
                v1 = fma2(a20d[g], *(const unsigned long long*)(sW1e + g*H + kg + 2), v1);
            }
            float x0, x1, x2, x3;
            unpack2(v0, x0, x1); unpack2(v1, x2, x3);
            sm1[(kl+0)*132 + ea] = fmaxf(x0, 0.f);
            sm1[(kl+1)*132 + ea] = fmaxf(x1, 0.f);
            sm1[(kl+2)*132 + ea] = fmaxf(x2, 0.f);
            sm1[(kl+3)*132 + ea] = fmaxf(x3, 0.f);
        }
        __syncthreads();

        // step B: accumulate this phase's 64 k's (W2 rows hit L1)
#pragma unroll 4
        for (int k = 0; k < 64; ++k) {
            float4 a0 = *(const float4*)(sm1 + k*132 + rg*8);
            float4 a1 = *(const float4*)(sm1 + k*132 + rg*8 + 4);
            ulonglong2 b0 = __ldg(W2v + (p*64+k)*32 + cg*2);
            ulonglong2 b1 = __ldg(W2v + (p*64+k)*32 + cg*2 + 1);
            unsigned long long bp[4] = {b0.x, b0.y, b1.x, b1.y};
            unsigned long long ad[8];
            ad[0] = dup2(a0.x); ad[1] = dup2(a0.y); ad[2] = dup2(a0.z); ad[3] = dup2(a0.w);
            ad[4] = dup2(a1.x); ad[5] = dup2(a1.y); ad[6] = dup2(a1.z); ad[7] = dup2(a1.w);
#pragma unroll
            for (int r = 0; r < 8; ++r)
#pragma unroll
                for (int c2 = 0; c2 < 4; ++c2) accp[r][c2] = fma2(ad[r], bp[c2], accp[r][c2]);
        }
        if (p == 0) __syncthreads();   // before next phase's step A overwrites sm1
    }

    // bias + relu
    float acc[8][8];
#pragma unroll
    for (int r = 0; r < 8; ++r) {
#pragma unroll
        for (int c2 = 0; c2 < 4; ++c2) unpack2(accp[r][c2], acc[r][2*c2], acc[r][2*c2+1]);
#pragma unroll
        for (int c = 0; c < 8; ++c) acc[r][c] = fmaxf(acc[r][c] + sb2[col+c], 0.f);
    }

    // step C: gate logits (reduce over feature dim via shared atomics)
#pragma unroll
    for (int r = 0; r < 8; ++r) {
        float p = 0.f;
#pragma unroll
        for (int c = 0; c < 8; ++c) p += acc[r][c]*sinfw[col+c];
        atomicAdd(&sgate[rg*8 + r], p);
    }
    __syncthreads();
    if (tid < H) sgate[tid] = 1.f/(1.f + expf(-sgate[tid]));
    __syncthreads();

    // step D: mi[dst] = sum_e m*gate  (8-row group never straddles a dst)
    {
        int d = rg >> 2;
#pragma unroll
        for (int c = 0; c < 8; ++c) {
            float s = 0.f;
#pragma unroll
            for (int r = 0; r < 8; ++r) s += acc[r][c]*sgate[rg*8 + r];
            atomicAdd(&smi[d*H + col + c], s);
        }
    }
    __syncthreads();
    for (int i = tid; i < 4*H; i += 256) g_mi[(size_t)d0*H + i] = smi[i];
}

// ---------------- K6: node MLP + residual + fused next-layer A/B ------------
__global__ void __launch_bounds__(256) node_kernel(const float* __restrict__ nw1,
                                                   const float* __restrict__ nb1,
                                                   const float* __restrict__ nw2,
                                                   const float* __restrict__ nb2,
                                                   const float* __restrict__ edge_w1,
                                                   const float* __restrict__ edge_b1, int l)
{
    __shared__ float sZ[256*34];   // [mi | h] k-major; reused for u, then h_new
    int tid = threadIdx.x;
    int nb = blockIdx.x*32;
    for (int i = tid; i < 32*H; i += 256) {
        int nn = i>>7, k = i&127;
        sZ[k*34 + nn]     = g_mi[(size_t)(nb+nn)*H + k];
        sZ[(H+k)*34 + nn] = g_h [(size_t)(nb+nn)*H + k];
    }
    __syncthreads();
    int cg = tid & 15, ng = tid >> 4, col = cg*8;
    const ulonglong2* W1a = (const ulonglong2*)(nw1 + (size_t)l*2*H*H);
    const ulonglong2* W1b = W1a + H*H/4;
    unsigned long long acc[2][4];
#pragma unroll
    for (int c2 = 0; c2 < 4; ++c2) {
        unsigned long long b = pack2(nb1[l*H + col + 2*c2], nb1[l*H + col + 2*c2 + 1]);
        acc[0][c2] = b; acc[1][c2] = b;
    }
#pragma unroll 4
    for (int k = 0; k < H; ++k) {
        float2 am = *(const float2*)(sZ + k*34 + ng*2);
        float2 ah = *(const float2*)(sZ + (H+k)*34 + ng*2);
        ulonglong2 wa0 = __ldg(W1a + k*32 + cg*2);
        ulonglong2 wa1 = __ldg(W1a + k*32 + cg*2 + 1);
        ulonglong2 wb0 = __ldg(W1b + k*32 + cg*2);
        ulonglong2 wb1 = __ldg(W1b + k*32 + cg*2 + 1);
        unsigned long long m0 = dup2(am.x), m1 = dup2(am.y);
        unsigned long long h0 = dup2(ah.x), h1 = dup2(ah.y);
        unsigned long long wap[4] = {wa0.x, wa0.y, wa1.x, wa1.y};
        unsigned long long wbp[4] = {wb0.x, wb0.y, wb1.x, wb1.y};
#pragma unroll
        for (int c2 = 0; c2 < 4; ++c2) {
            acc[0][c2] = fma2(m0, wap[c2], acc[0][c2]);
            acc[1][c2] = fma2(m1, wap[c2], acc[1][c2]);
            acc[0][c2] = fma2(h0, wbp[c2], acc[0][c2]);
            acc[1][c2] = fma2(h1, wbp[c2], acc[1][c2]);
        }
    }
    __syncthreads();   // done reading sZ
#pragma unroll
    for (int r = 0; r < 2; ++r)
#pragma unroll
        for (int c2 = 0; c2 < 4; ++c2) {
            float lo, hi;
            unpack2(acc[r][c2], lo, hi);
            sZ[(col + 2*c2)*34 + ng*2 + r]     = fmaxf(lo, 0.f);
            sZ[(col + 2*c2 + 1)*34 + ng*2 + r] = fmaxf(hi, 0.f);
        }
    __syncthreads();
    const ulonglong2* W2 = (const ulonglong2*)(nw2 + (size_t)l*H*H);
    unsigned long long acc2[2][4];
#pragma unroll
    for (int c2 = 0; c2 < 4; ++c2) {
        unsigned long long b = pack2(nb2[l*H + col + 2*c2], nb2[l*H + col + 2*c2 + 1]);
        acc2[0][c2] = b; acc2[1][c2] = b;
    }
#pragma unroll 4
    for (int k = 0; k < H; ++k) {
        float2 a  = *(const float2*)(sZ + k*34 + ng*2);
        ulonglong2 w0 = __ldg(W2 + k*32 + cg*2);
        ulonglong2 w1 = __ldg(W2 + k*32 + cg*2 + 1);
        unsigned long long a0 = dup2(a.x), a1 = dup2(a.y);
        unsigned long long wp[4] = {w0.x, w0.y, w1.x, w1.y};
#pragma unroll
        for (int c2 = 0; c2 < 4; ++c2) {
            acc2[0][c2] = fma2(a0, wp[c2], acc2[0][c2]);
            acc2[1][c2] = fma2(a1, wp[c2], acc2[1][c2]);
        }
    }
    float hn[2][8];
#pragma unroll
    for (int r = 0; r < 2; ++r) {
        float v[8];
#pragma unroll
        for (int c2 = 0; c2 < 4; ++c2) unpack2(acc2[r][c2], v[2*c2], v[2*c2+1]);
        size_t o = (size_t)(nb + ng*2 + r)*H + col;
        float4* hp = (float4*)(g_h + o);
        float4 h0 = hp[0], h1 = hp[1];
        hn[r][0] = h0.x + v[0]; hn[r][1] = h0.y + v[1]; hn[r][2] = h0.z + v[2]; hn[r][3] = h0.w + v[3];
        hn[r][4] = h1.x + v[4]; hn[r][5] = h1.y + v[5]; hn[r][6] = h1.z + v[6]; hn[r][7] = h1.w + v[7];
        hp[0] = make_float4(hn[r][0], hn[r][1], hn[r][2], hn[r][3]);
        hp[1] = make_float4(hn[r][4], hn[r][5], hn[r][6], hn[r][7]);
    }

    // ---- fused next-layer A/B (layers 0,1 only) ----
    if (l < 2) {
        __syncthreads();   // everyone done reading sZ (u) in acc2 loop
#pragma unroll
        for (int r = 0; r < 2; ++r)
#pragma unroll
            for (int c = 0; c < 8; ++c) sZ[(col + c)*34 + ng*2 + r] = hn[r][c];
        __syncthreads();
        int nl = l + 1;
        const ulonglong2* WA = (const ulonglong2*)(edge_w1 + (size_t)nl*276*H + GG*H);
        const ulonglong2* WB = (const ulonglong2*)(edge_w1 + (size_t)nl*276*H + (GG+H)*H);
        unsigned long long accA[2][4], accB[2][4];
#pragma unroll
        for (int c2 = 0; c2 < 4; ++c2) {
            unsigned long long b = pack2(edge_b1[nl*H + col + 2*c2], edge_b1[nl*H + col + 2*c2 + 1]);
            accA[0][c2] = b; accA[1][c2] = b; accB[0][c2] = 0ull; accB[1][c2] = 0ull;
        }
#pragma unroll 4
        for (int k = 0; k < H; ++k) {
            float2 a = *(const float2*)(sZ + k*34 + ng*2);
            ulonglong2 wa0 = __ldg(WA + k*32 + cg*2);
            ulonglong2 wa1 = __ldg(WA + k*32 + cg*2 + 1);
            ulonglong2 wb0 = __ldg(WB + k*32 + cg*2);
            ulonglong2 wb1 = __ldg(WB + k*32 + cg*2 + 1);
            unsigned long long a0 = dup2(a.x), a1 = dup2(a.y);
            unsigned long long wap[4] = {wa0.x, wa0.y, wa1.x, wa1.y};
            unsigned long long wbp[4] = {wb0.x, wb0.y, wb1.x, wb1.y};
#pragma unroll
            for (int c2 = 0; c2 < 4; ++c2) {
                accA[0][c2] = fma2(a0, wap[c2], accA[0][c2]);
                accA[1][c2] = fma2(a1, wap[c2], accA[1][c2]);
                accB[0][c2] = fma2(a0, wbp[c2], accB[0][c2]);
                accB[1][c2] = fma2(a1, wbp[c2], accB[1][c2]);
            }
        }
#pragma unroll
        for (int r = 0; r < 2; ++r) {
            float va[8], vb[8];
#pragma unroll
            for (int c2 = 0; c2 < 4; ++c2) {
                unpack2(accA[r][c2], va[2*c2], va[2*c2+1]);
                unpack2(accB[r][c2], vb[2*c2], vb[2*c2+1]);
            }
            size_t o = (size_t)(nb + ng*2 + r)*H + col;
            *(float4*)(g_A + o)     = make_float4(va[0],va[1],va[2],va[3]);
            *(float4*)(g_A + o + 4) = make_float4(va[4],va[5],va[6],va[7]);
            *(float4*)(g_B + o)     = make_float4(vb[0],vb[1],vb[2],vb[3]);
            *(float4*)(g_B + o + 4) = make_float4(vb[4],vb[5],vb[6],vb[7]);
        }
    }
}

// ---------------- K7: per-graph pooling (parallel + atomics) ----------------
__global__ void pool_kernel(int n)
{
    int b = blockIdx.x >> 4, s = blockIdx.x & 15;
    int c = threadIdx.x;  // 128 threads
    float acc = 0.f;
    for (int i = s; i < n; i += 16) acc += g_h[((size_t)b*n + i)*H + c];
    atomicAdd(&g_pre[b*H + c], acc);
}

// ---------------- K8: out_block + output selection ---------------------------
__global__ void out_kernel(const float* __restrict__ w1, const float* __restrict__ b1,
                           const float* __restrict__ w2, const float* __restrict__ b2,
                           const int* __restrict__ kind, float* __restrict__ out, int B)
{
    __shared__ float sU[H]; __shared__ float so[3];
    int t = threadIdx.x;
    for (int b = 0; b < B; ++b) {
        float x = b1[t];
        for (int k = 0; k < H; ++k) x += g_pre[b*H + k]*w1[k*H + t];
        float sp = (x > 0.f) ? x + log1pf(expf(-x)) : log1pf(expf(x));
        sU[t] = sp - 0.6931471805599453f;
        __syncthreads();
        if (t < 3) { float s = b2[t]; for (int k = 0; k < H; ++k) s += sU[k]*w2[k*3 + t]; so[t] = s; }
        __syncthreads();
        if (t == 0) out[b] = so[kind[b] - 1];
        __syncthreads();
    }
}

// ---------------- host ------------------------------------------------------
#define EDGE_SMEM ((64*132 + 20*128 + 128*20 + 4*128 + 128 + 128 + 128 + 4*128 + 128)*4)

extern "C" void kernel_launch(void* const* d_in, const int* in_sizes, int n_in,
                              void* d_out, int out_size)
{
    const float* protein_pos  = (const float*)d_in[0];
    const float* protein_feat = (const float*)d_in[1];
    const float* ligand_pos   = (const float*)d_in[2];
    const float* ligand_feat  = (const float*)d_in[3];
    const int*   output_kind  = (const int*)d_in[6];
    const float* prot_w = (const float*)d_in[7];  const float* prot_b = (const float*)d_in[8];
    const float* lig_w  = (const float*)d_in[9];  const float* lig_b  = (const float*)d_in[10];
    const float* edge_w1 = (const float*)d_in[11]; const float* edge_b1 = (const float*)d_in[12];
    const float* edge_w2 = (const float*)d_in[13]; const float* edge_b2 = (const float*)d_in[14];
    const float* inf_w   = (const float*)d_in[15]; const float* inf_b   = (const float*)d_in[16];
    const float* node_w1 = (const float*)d_in[17]; const float* node_b1 = (const float*)d_in[18];
    const float* node_w2 = (const float*)d_in[19]; const float* node_b2 = (const float*)d_in[20];
    const float* out_w1  = (const float*)d_in[21]; const float* out_b1  = (const float*)d_in[22];
    const float* out_w2  = (const float*)d_in[23]; const float* out_b2  = (const float*)d_in[24];
    float* out = (float*)d_out;

    int Np = in_sizes[0]/3, Nl = in_sizes[2]/3;
    int B  = in_sizes[6];
    int Fp = in_sizes[1]/Np, Fl = in_sizes[3]/Nl;
    int n_prot = Np/B, n_lig = Nl/B;
    int n = n_prot + n_lig;
    int N = Np + Nl;
    int E = N*KNN;

    cudaFuncSetAttribute(edge_kernel, cudaFuncAttributeMaxDynamicSharedMemorySize, EDGE_SMEM);

    embed_kernel<<<N, 128>>>(protein_pos, protein_feat, ligand_pos, ligand_feat,
                             prot_w, prot_b, lig_w, lig_b, n_prot, n_lig, n, Fp, Fl);

    knn_kernel<<<dim3((n + 127)/128, B), 128, n*(int)sizeof(float4)>>>(n);

    float step  = 10.0f/19.0f;           // CUTOFF / (G-1)
    float coeff = -0.5f/(step*step);
    attr_kernel<<<(E + 255)/256, 256>>>(E, step, coeff);

    ab_kernel<<<N/32, 256>>>(edge_w1, edge_b1, 0);
    for (int l = 0; l < 3; ++l) {
        edge_kernel<<<E/128, 256, EDGE_SMEM>>>(edge_w1, edge_b2, edge_w2, inf_w, inf_b, l);
        node_kernel<<<N/32, 256>>>(node_w1, node_b1, node_w2, node_b2, edge_w1, edge_b1, l);
    }

    pool_kernel<<<B*16, 128>>>(n);
    out_kernel<<<1, 128>>>(out_w1, out_b1, out_w2, out_b2, output_kind, out, B);
}

// round 10
// speedup vs baseline: 1.3005x; 1.0626x over previous
#include <cuda_runtime.h>
#include <cuda_bf16.h>
#include <mma.h>
#include <math.h>

#define H   128
#define GG  20
#define KNN 32
#define MAXN 24000
#define MAXE (MAXN*KNN)

using namespace nvcuda;

// ---------------- f32x2 packed helpers --------------------------------------
__device__ __forceinline__ unsigned long long pack2(float lo, float hi) {
    unsigned long long r;
    asm("mov.b64 %0, {%1, %2};" : "=l"(r) : "f"(lo), "f"(hi));
    return r;
}
__device__ __forceinline__ unsigned long long dup2(float v) {
    unsigned long long r;
    asm("mov.b64 %0, {%1, %1};" : "=l"(r) : "f"(v));
    return r;
}
__device__ __forceinline__ void unpack2(unsigned long long p, float& lo, float& hi) {
    asm("mov.b64 {%0, %1}, %2;" : "=f"(lo), "=f"(hi) : "l"(p));
}
__device__ __forceinline__ unsigned long long fma2(unsigned long long a, unsigned long long b, unsigned long long c) {
    unsigned long long d;
    asm("fma.rn.f32x2 %0, %1, %2, %3;" : "=l"(d) : "l"(a), "l"(b), "l"(c));
    return d;
}
__device__ __forceinline__ unsigned long long add2(unsigned long long a, unsigned long long b) {
    unsigned long long d;
    asm("add.rn.f32x2 %0, %1, %2;" : "=l"(d) : "l"(a), "l"(b));
    return d;
}

// ---------------- scratch ----------------------------------------------------
__device__ __align__(16) float g_pos[MAXN*3];
__device__ __align__(16) float g_h  [MAXN*H];
__device__ __align__(16) float g_A  [MAXN*H];
__device__ __align__(16) float g_B  [MAXN*H];
__device__ __align__(16) float g_mi [MAXN*H];
__device__ int   g_nbr[MAXE];
__device__ float g_attr[(size_t)MAXE*GG];
__device__ float g_pre[16*H];
// baked W2^T as bf16 hi/lo: [layer][hi/lo][n=128][k=128]
__device__ __align__(16) unsigned short g_w2bf[3*2*16384];

// ---------------- K1: embeddings --------------------------------------------
__global__ void embed_kernel(const float* __restrict__ ppos, const float* __restrict__ pfeat,
                             const float* __restrict__ lpos, const float* __restrict__ lfeat,
                             const float* __restrict__ pw, const float* __restrict__ pb,
                             const float* __restrict__ lw, const float* __restrict__ lb,
                             int n_prot, int n_lig, int n, int Fp, int Fl)
{
    __shared__ float sf[32];
    int i = blockIdx.x, t = threadIdx.x;
    int b = i / n, j = i - b * n;
    const float *feat, *w, *bias, *pos; int F;
    if (j < n_prot) { int r = b*n_prot + j;            feat = pfeat + (size_t)r*Fp; w = pw; bias = pb; pos = ppos + (size_t)r*3; F = Fp; }
    else            { int r = b*n_lig  + (j - n_prot); feat = lfeat + (size_t)r*Fl; w = lw; bias = lb; pos = lpos + (size_t)r*3; F = Fl; }
    if (t < F) sf[t] = feat[t];
    __syncthreads();
    float acc = bias[t];
    for (int f = 0; f < F; ++f) acc += sf[f] * w[f*H + t];
    g_h[(size_t)i*H + t] = acc;
    if (t < 3) g_pos[i*3 + t] = pos[t];
}

// ---------------- K2: kNN ----------------------------------------------------
__global__ void knn_kernel(int n)
{
    extern __shared__ float4 spos4[];
    int b = blockIdx.y, tid = threadIdx.x;
    const float* gp = g_pos + (size_t)b*n*3;
    for (int i = tid; i < n; i += blockDim.x)
        spos4[i] = make_float4(gp[i*3], gp[i*3+1], gp[i*3+2], 0.f);
    __syncthreads();
    int c = blockIdx.x*blockDim.x + tid;
    if (c >= n) return;
    float4 pc = spos4[c];
    float bd[KNN]; int bi[KNN];
#pragma unroll
    for (int s = 0; s < KNN; ++s) { bd[s] = 3.402823466e38f; bi[s] = 0x7fffffff; }
    float wd = 3.402823466e38f; int wi = 0x7fffffff; int ws = 0;
    for (int j = 0; j < n; ++j) {
        if (j == c) continue;
        float4 pj = spos4[j];
        float dx = pc.x - pj.x, dy = pc.y - pj.y, dz = pc.z - pj.z;
        float d2 = dx*dx + dy*dy + dz*dz;
        if (d2 < wd || (d2 == wd && j < wi)) {
            bd[ws] = d2; bi[ws] = j;
            wd = bd[0]; wi = bi[0]; ws = 0;
#pragma unroll
            for (int s = 1; s < KNN; ++s)
                if (bd[s] > wd || (bd[s] == wd && bi[s] > wi)) { wd = bd[s]; wi = bi[s]; ws = s; }
        }
    }
    size_t base = ((size_t)(b*n + c))*KNN;
#pragma unroll
    for (int s = 0; s < KNN; ++s) g_nbr[base + s] = b*n + bi[s];
}

// ---------------- K3: Gaussian smearing + zero g_pre ------------------------
__global__ void attr_kernel(int E, float step, float coeff)
{
    int e = blockIdx.x*blockDim.x + threadIdx.x;
    if (e >= E) return;
    if (e < 16*H) g_pre[e] = 0.f;
    int dst = e >> 5;
    int src = g_nbr[e];
    float dx = g_pos[dst*3]   - g_pos[src*3];
    float dy = g_pos[dst*3+1] - g_pos[src*3+1];
    float dz = g_pos[dst*3+2] - g_pos[src*3+2];
    float d = sqrtf(dx*dx + dy*dy + dz*dz);
    size_t o = (size_t)e*GG;
#pragma unroll
    for (int g = 0; g < GG; ++g) {
        float t = d - g*step;
        g_attr[o + g] = expf(coeff*t*t);
    }
}

// ---------------- K3b: bake W2^T bf16 hi/lo ----------------------------------
// layout: g_w2bf[(l*2+p)*16384 + n*128 + k]
__global__ void w2prep_kernel(const float* __restrict__ edge_w2)
{
    int l = blockIdx.x >> 7, nr = blockIdx.x & 127, k = threadIdx.x;
    float v = edge_w2[((size_t)l*H + k)*H + nr];
    __nv_bfloat16 hb = __float2bfloat16(v);
    float r = v - __bfloat162float(hb);
    __nv_bfloat16 lb = __float2bfloat16(r);
    g_w2bf[(l*2+0)*16384 + nr*128 + k] = __bfloat16_as_ushort(hb);
    g_w2bf[(l*2+1)*16384 + nr*128 + k] = __bfloat16_as_ushort(lb);
}

// ---------------- K4: A = h@W1i + b1, B = h@W1j ------------------------------
__global__ void __launch_bounds__(256) ab_kernel(const float* __restrict__ edge_w1,
                                                 const float* __restrict__ edge_b1, int l)
{
    __shared__ float sHt[128*34];
    int tid = threadIdx.x;
    int nb = blockIdx.x*32;
    for (int i = tid; i < 32*H; i += 256) { int nn = i>>7, k = i&127; sHt[k*34+nn] = g_h[(size_t)(nb+nn)*H + k]; }
    __syncthreads();
    int cg = tid & 15, ng = tid >> 4, col = cg*8;
    const ulonglong2* WA = (const ulonglong2*)(edge_w1 + (size_t)l*276*H + GG*H);
    const ulonglong2* WB = (const ulonglong2*)(edge_w1 + (size_t)l*276*H + (GG+H)*H);
    unsigned long long accA[2][4], accB[2][4];
#pragma unroll
    for (int c2 = 0; c2 < 4; ++c2) {
        unsigned long long b0 = pack2(edge_b1[l*H + col + 2*c2], edge_b1[l*H + col + 2*c2 + 1]);
        accA[0][c2] = b0; accA[1][c2] = b0; accB[0][c2] = 0ull; accB[1][c2] = 0ull;
    }
#pragma unroll 4
    for (int k = 0; k < H; ++k) {
        float2 a = *(const float2*)(sHt + k*34 + ng*2);
        ulonglong2 wa0 = __ldg(WA + k*32 + cg*2);
        ulonglong2 wa1 = __ldg(WA + k*32 + cg*2 + 1);
        ulonglong2 wb0 = __ldg(WB + k*32 + cg*2);
        ulonglong2 wb1 = __ldg(WB + k*32 + cg*2 + 1);
        unsigned long long a0 = dup2(a.x), a1 = dup2(a.y);
        unsigned long long wap[4] = {wa0.x, wa0.y, wa1.x, wa1.y};
        unsigned long long wbp[4] = {wb0.x, wb0.y, wb1.x, wb1.y};
#pragma unroll
        for (int c2 = 0; c2 < 4; ++c2) {
            accA[0][c2] = fma2(a0, wap[c2], accA[0][c2]);
            accA[1][c2] = fma2(a1, wap[c2], accA[1][c2]);
            accB[0][c2] = fma2(a0, wbp[c2], accB[0][c2]);
            accB[1][c2] = fma2(a1, wbp[c2], accB[1][c2]);
        }
    }
#pragma unroll
    for (int r = 0; r < 2; ++r) {
        float va[8], vb[8];
#pragma unroll
        for (int c2 = 0; c2 < 4; ++c2) {
            unpack2(accA[r][c2], va[2*c2], va[2*c2+1]);
            unpack2(accB[r][c2], vb[2*c2], vb[2*c2+1]);
        }
        size_t o = (size_t)(nb + ng*2 + r)*H + col;
        *(float4*)(g_A + o)     = make_float4(va[0],va[1],va[2],va[3]);
        *(float4*)(g_A + o + 4) = make_float4(va[4],va[5],va[6],va[7]);
        *(float4*)(g_B + o)     = make_float4(vb[0],vb[1],vb[2],vb[3]);
        *(float4*)(g_B + o + 4) = make_float4(vb[4],vb[5],vb[6],vb[7]);
    }
}

// ---------------- K5: edge MLP via WMMA bf16 hi/lo ---------------------------
// SMEM byte offsets.  A/B tiles: bf16 [row][136] (ld=136 elems, 272 B/row).
#define A_HI_OFF  0
#define A_LO_OFF  34816
#define B_HI_OFF  69632
#define B_LO_OFF  104448
#define SW1E_OFF  139264
#define SATTR_OFF (SW1E_OFF + GG*H*4)
#define SAV_OFF   (SATTR_OFF + 128*GG*4)
#define SB2_OFF   (SAV_OFF + 4*H*4)
#define SINFW_OFF (SB2_OFF + H*4)
#define SGATE_OFF (SINFW_OFF + H*4)
#define SMI_OFF   (SGATE_OFF + H*4)
#define SSRC_OFF  (SMI_OFF + 4*H*4)
#define EDGE_SMEM (SSRC_OFF + 128*4)
#define LDAB 136

__global__ void __launch_bounds__(256,1) edge_kernel(const float* __restrict__ edge_w1,
                                                     const float* __restrict__ edge_b2,
                                                     const float* __restrict__ inf_w,
                                                     const float* __restrict__ inf_b, int l)
{
    extern __shared__ __align__(16) char sh[];
    __nv_bfloat16* sAhi = (__nv_bfloat16*)(sh + A_HI_OFF);
    __nv_bfloat16* sAlo = (__nv_bfloat16*)(sh + A_LO_OFF);
    __nv_bfloat16* sBhi = (__nv_bfloat16*)(sh + B_HI_OFF);
    __nv_bfloat16* sBlo = (__nv_bfloat16*)(sh + B_LO_OFF);
    float* sW1e  = (float*)(sh + SW1E_OFF);
    float* sattr = (float*)(sh + SATTR_OFF);
    float* sAv   = (float*)(sh + SAV_OFF);
    float* sb2   = (float*)(sh + SB2_OFF);
    float* sinfw = (float*)(sh + SINFW_OFF);
    float* sgate = (float*)(sh + SGATE_OFF);
    float* smi   = (float*)(sh + SMI_OFF);
    int*   ssrc  = (int*)(sh + SSRC_OFF);
    float* D     = (float*)(sh + A_HI_OFF);   // reused after MMA: [128][132] f32

    int tid = threadIdx.x;
    int wrp = tid >> 5;
    int e0 = blockIdx.x * 128;
    int d0 = e0 >> 5;

    // stage W2^T hi/lo into padded shared rows
    {
        const uint4* gh = (const uint4*)(g_w2bf + (size_t)(l*2+0)*16384);
        const uint4* gl = (const uint4*)(g_w2bf + (size_t)(l*2+1)*16384);
        for (int i = tid; i < 2048; i += 256) {
            int row = i >> 4, q = i & 15;
            ((uint4*)((char*)sBhi + row*272))[q] = gh[row*16 + q];
            ((uint4*)((char*)sBlo + row*272))[q] = gl[row*16 + q];
        }
    }
    const float* W1b = edge_w1 + (size_t)l*276*H;
    for (int i = tid; i < GG*H;   i += 256) sW1e[i]  = W1b[i];
    for (int i = tid; i < 128*GG; i += 256) sattr[i] = g_attr[(size_t)e0*GG + i];
    for (int i = tid; i < 4*H;    i += 256) { sAv[i] = g_A[(size_t)d0*H + i]; smi[i] = 0.f; }
    if (tid < H) { sb2[tid] = edge_b2[l*H+tid]; sinfw[tid] = inf_w[l*H+tid]; sgate[tid] = inf_b[l]; }
    if (tid < 128) ssrc[tid] = g_nbr[e0 + tid];
    __syncthreads();

    // step A: m1 = relu(attr@W1e + A[dst] + B[src]) -> bf16 hi/lo [e][k]
    {
        int ea = tid >> 1, half = tid & 1;
        int srcA = ssrc[ea];
        const float4* Brow = (const float4*)(g_B + (size_t)srcA*H);
        const float* sAd = sAv + (ea>>5)*H;
        unsigned long long a20d[GG];
#pragma unroll
        for (int g = 0; g < GG; ++g) a20d[g] = dup2(sattr[ea*GG + g]);
#pragma unroll 2
        for (int i4 = 0; i4 < 16; ++i4) {
            int k0 = half*64 + i4*4;
            float4 bv = Brow[k0 >> 2];
            unsigned long long v0 = add2(*(const unsigned long long*)(sAd + k0),     pack2(bv.x, bv.y));
            unsigned long long v1 = add2(*(const unsigned long long*)(sAd + k0 + 2), pack2(bv.z, bv.w));
#pragma unroll
            for (int g = 0; g < GG; ++g) {
                v0 = fma2(a20d[g], *(const unsigned long long*)(sW1e + g*H + k0),     v0);
                v1 = fma2(a20d[g], *(const unsigned long long*)(sW1e + g*H + k0 + 2), v1);
            }
            float x0, x1, x2, x3;
            unpack2(v0, x0, x1); unpack2(v1, x2, x3);
            x0 = fmaxf(x0, 0.f); x1 = fmaxf(x1, 0.f); x2 = fmaxf(x2, 0.f); x3 = fmaxf(x3, 0.f);
            __nv_bfloat16 h0 = __float2bfloat16(x0), h1 = __float2bfloat16(x1);
            __nv_bfloat16 h2 = __float2bfloat16(x2), h3 = __float2bfloat16(x3);
            __nv_bfloat16 l0 = __float2bfloat16(x0 - __bfloat162float(h0));
            __nv_bfloat16 l1 = __float2bfloat16(x1 - __bfloat162float(h1));
            __nv_bfloat16 l2 = __float2bfloat16(x2 - __bfloat162float(h2));
            __nv_bfloat16 l3 = __float2bfloat16(x3 - __bfloat162float(h3));
            unsigned hi01 = ((unsigned)__bfloat16_as_ushort(h1) << 16) | __bfloat16_as_ushort(h0);
            unsigned hi23 = ((unsigned)__bfloat16_as_ushort(h3) << 16) | __bfloat16_as_ushort(h2);
            unsigned lo01 = ((unsigned)__bfloat16_as_ushort(l1) << 16) | __bfloat16_as_ushort(l0);
            unsigned lo23 = ((unsigned)__bfloat16_as_ushort(l3) << 16) | __bfloat16_as_ushort(l2);
            unsigned boff = ea*272 + k0*2;   // byte offset, 8B aligned
            *(uint2*)((char*)sAhi + boff) = make_uint2(hi01, hi23);
            *(uint2*)((char*)sAlo + boff) = make_uint2(lo01, lo23);
        }
    }
    __syncthreads();

    // MMA: warp (rg, cgf) -> edges rg*32..+32, cols cgf*64..+64
    {
        int rg = wrp & 3, cgf = wrp >> 2;
        int er = rg*32, nc = cgf*64;
        wmma::fragment<wmma::accumulator,16,16,16,float> acc[2][4];
#pragma unroll
        for (int i = 0; i < 2; ++i)
#pragma unroll
            for (int j = 0; j < 4; ++j) wmma::fill_fragment(acc[i][j], 0.f);
#pragma unroll
        for (int k0 = 0; k0 < 128; k0 += 16) {
            wmma::fragment<wmma::matrix_a,16,16,16,__nv_bfloat16,wmma::row_major> ah[2], al[2];
            wmma::fragment<wmma::matrix_b,16,16,16,__nv_bfloat16,wmma::col_major> bh[4], bl[4];
#pragma unroll
            for (int i = 0; i < 2; ++i) {
                wmma::load_matrix_sync(ah[i], sAhi + (er + i*16)*LDAB + k0, LDAB);
                wmma::load_matrix_sync(al[i], sAlo + (er + i*16)*LDAB + k0, LDAB);
            }
#pragma unroll
            for (int j = 0; j < 4; ++j) {
                wmma::load_matrix_sync(bh[j], sBhi + (nc + j*16)*LDAB + k0, LDAB);
                wmma::load_matrix_sync(bl[j], sBlo + (nc + j*16)*LDAB + k0, LDAB);
            }
#pragma unroll
            for (int i = 0; i < 2; ++i)
#pragma unroll
                for (int j = 0; j < 4; ++j) {
                    wmma::mma_sync(acc[i][j], ah[i], bh[j], acc[i][j]);
                    wmma::mma_sync(acc[i][j], ah[i], bl[j], acc[i][j]);
                    wmma::mma_sync(acc[i][j], al[i], bh[j], acc[i][j]);
                }
        }
        __syncthreads();   // done reading A/B; reuse region as D
#pragma unroll
        for (int i = 0; i < 2; ++i)
#pragma unroll
            for (int j = 0; j < 4; ++j)
                wmma::store_matrix_sync(D + (er + i*16)*132 + nc + j*16, acc[i][j],
                                        132, wmma::mem_row_major);
    }
    __syncthreads();

    // epilogue stage 1: bias + relu + gate logits (2 threads per edge)
    {
        int e = tid >> 1, c0 = (tid & 1)*64;
        float p = 0.f;
#pragma unroll 8
        for (int c = 0; c < 64; ++c) {
            float v = D[e*132 + c0 + c] + sb2[c0 + c];
            v = fmaxf(v, 0.f);
            D[e*132 + c0 + c] = v;
            p += v * sinfw[c0 + c];
        }
        atomicAdd(&sgate[e], p);
    }
    __syncthreads();
    if (tid < 128) sgate[tid] = 1.f/(1.f + expf(-sgate[tid]));
    __syncthreads();

    // epilogue stage 2: mi[d][c] = sum_e m[e][c]*gate[e]
    {
        int c = tid & 127, hf = tid >> 7;
#pragma unroll
        for (int d = 0; d < 4; ++d) {
            float s = 0.f;
#pragma unroll 4
            for (int j = 0; j < 16; ++j) {
                int e = d*32 + hf*16 + j;
                s += D[e*132 + c] * sgate[e];
            }
            atomicAdd(&smi[d*H + c], s);
        }
    }
    __syncthreads();
    for (int i = tid; i < 4*H; i += 256) g_mi[(size_t)d0*H + i] = smi[i];
}

// ---------------- K6: node MLP + residual (R6 version) ----------------------
__global__ void __launch_bounds__(256) node_kernel(const float* __restrict__ nw1,
                                                   const float* __restrict__ nb1,
                                                   const float* __restrict__ nw2,
                                                   const float* __restrict__ nb2, int l)
{
    __shared__ float sZ[256*34];
    int tid = threadIdx.x;
    int nb = blockIdx.x*32;
    for (int i = tid; i < 32*H; i += 256) {
        int nn = i>>7, k = i&127;
        sZ[k*34 + nn]     = g_mi[(size_t)(nb+nn)*H + k];
        sZ[(H+k)*34 + nn] = g_h [(size_t)(nb+nn)*H + k];
    }
    __syncthreads();
    int cg = tid & 15, ng = tid >> 4, col = cg*8;
    const ulonglong2* W1a = (const ulonglong2*)(nw1 + (size_t)l*2*H*H);
    const ulonglong2* W1b = W1a + H*H/4;
    unsigned long long acc[2][4];
#pragma unroll
    for (int c2 = 0; c2 < 4; ++c2) {
        unsigned long long b = pack2(nb1[l*H + col + 2*c2], nb1[l*H + col + 2*c2 + 1]);
        acc[0][c2] = b; acc[1][c2] = b;
    }
#pragma unroll 4
    for (int k = 0; k < H; ++k) {
        float2 am = *(const float2*)(sZ + k*34 + ng*2);
        float2 ah = *(const float2*)(sZ + (H+k)*34 + ng*2);
        ulonglong2 wa0 = __ldg(W1a + k*32 + cg*2);
        ulonglong2 wa1 = __ldg(W1a + k*32 + cg*2 + 1);
        ulonglong2 wb0 = __ldg(W1b + k*32 + cg*2);
        ulonglong2 wb1 = __ldg(W1b + k*32 + cg*2 + 1);
        unsigned long long m0 = dup2(am.x), m1 = dup2(am.y);
        unsigned long long h0 = dup2(ah.x), h1 = dup2(ah.y);
        unsigned long long wap[4] = {wa0.x, wa0.y, wa1.x, wa1.y};
        unsigned long long wbp[4] = {wb0.x, wb0.y, wb1.x, wb1.y};
#pragma unroll
        for (int c2 = 0; c2 < 4; ++c2) {
            acc[0][c2] = fma2(m0, wap[c2], acc[0][c2]);
            acc[1][c2] = fma2(m1, wap[c2], acc[1][c2]);
            acc[0][c2] = fma2(h0, wbp[c2], acc[0][c2]);
            acc[1][c2] = fma2(h1, wbp[c2], acc[1][c2]);
        }
    }
    __syncthreads();
#pragma unroll
    for (int r = 0; r < 2; ++r)
#pragma unroll
        for (int c2 = 0; c2 < 4; ++c2) {
            float lo, hi;
            unpack2(acc[r][c2], lo, hi);
            sZ[(col + 2*c2)*34 + ng*2 + r]     = fmaxf(lo, 0.f);
            sZ[(col + 2*c2 + 1)*34 + ng*2 + r] = fmaxf(hi, 0.f);
        }
    __syncthreads();
    const ulonglong2* W2 = (const ulonglong2*)(nw2 + (size_t)l*H*H);
    unsigned long long acc2[2][4];
#pragma unroll
    for (int c2 = 0; c2 < 4; ++c2) {
        unsigned long long b = pack2(nb2[l*H + col + 2*c2], nb2[l*H + col + 2*c2 + 1]);
        acc2[0][c2] = b; acc2[1][c2] = b;
    }
#pragma unroll 4
    for (int k = 0; k < H; ++k) {
        float2 a  = *(const float2*)(sZ + k*34 + ng*2);
        ulonglong2 w0 = __ldg(W2 + k*32 + cg*2);
        ulonglong2 w1 = __ldg(W2 + k*32 + cg*2 + 1);
        unsigned long long a0 = dup2(a.x), a1 = dup2(a.y);
        unsigned long long wp[4] = {w0.x, w0.y, w1.x, w1.y};
#pragma unroll
        for (int c2 = 0; c2 < 4; ++c2) {
            acc2[0][c2] = fma2(a0, wp[c2], acc2[0][c2]);
            acc2[1][c2] = fma2(a1, wp[c2], acc2[1][c2]);
        }
    }
#pragma unroll
    for (int r = 0; r < 2; ++r) {
        float v[8];
#pragma unroll
        for (int c2 = 0; c2 < 4; ++c2) unpack2(acc2[r][c2], v[2*c2], v[2*c2+1]);
        size_t o = (size_t)(nb + ng*2 + r)*H + col;
        float4* hp = (float4*)(g_h + o);
        float4 h0 = hp[0], h1 = hp[1];
        h0.x += v[0]; h0.y += v[1]; h0.z += v[2]; h0.w += v[3];
        h1.x += v[4]; h1.y += v[5]; h1.z += v[6]; h1.w += v[7];
        hp[0] = h0; hp[1] = h1;
    }
}

// ---------------- K7/K8 ------------------------------------------------------
__global__ void pool_kernel(int n)
{
    int b = blockIdx.x >> 4, s = blockIdx.x & 15;
    int c = threadIdx.x;
    float acc = 0.f;
    for (int i = s; i < n; i += 16) acc += g_h[((size_t)b*n + i)*H + c];
    atomicAdd(&g_pre[b*H + c], acc);
}

__global__ void out_kernel(const float* __restrict__ w1, const float* __restrict__ b1,
                           const float* __restrict__ w2, const float* __restrict__ b2,
                           const int* __restrict__ kind, float* __restrict__ out, int B)
{
    __shared__ float sU[H]; __shared__ float so[3];
    int t = threadIdx.x;
    for (int b = 0; b < B; ++b) {
        float x = b1[t];
        for (int k = 0; k < H; ++k) x += g_pre[b*H + k]*w1[k*H + t];
        float sp = (x > 0.f) ? x + log1pf(expf(-x)) : log1pf(expf(x));
        sU[t] = sp - 0.6931471805599453f;
        __syncthreads();
        if (t < 3) { float s = b2[t]; for (int k = 0; k < H; ++k) s += sU[k]*w2[k*3 + t]; so[t] = s; }
        __syncthreads();
        if (t == 0) out[b] = so[kind[b] - 1];
        __syncthreads();
    }
}

// ---------------- host ------------------------------------------------------
extern "C" void kernel_launch(void* const* d_in, const int* in_sizes, int n_in,
                              void* d_out, int out_size)
{
    const float* protein_pos  = (const float*)d_in[0];
    const float* protein_feat = (const float*)d_in[1];
    const float* ligand_pos   = (const float*)d_in[2];
    const float* ligand_feat  = (const float*)d_in[3];
    const int*   output_kind  = (const int*)d_in[6];
    const float* prot_w = (const float*)d_in[7];  const float* prot_b = (const float*)d_in[8];
    const float* lig_w  = (const float*)d_in[9];  const float* lig_b  = (const float*)d_in[10];
    const float* edge_w1 = (const float*)d_in[11]; const float* edge_b1 = (const float*)d_in[12];
    const float* edge_w2 = (const float*)d_in[13]; const float* edge_b2 = (const float*)d_in[14];
    const float* inf_w   = (const float*)d_in[15]; const float* inf_b   = (const float*)d_in[16];
    const float* node_w1 = (const float*)d_in[17]; const float* node_b1 = (const float*)d_in[18];
    const float* node_w2 = (const float*)d_in[19]; const float* node_b2 = (const float*)d_in[20];
    const float* out_w1  = (const float*)d_in[21]; const float* out_b1  = (const float*)d_in[22];
    const float* out_w2  = (const float*)d_in[23]; const float* out_b2  = (const float*)d_in[24];
    float* out = (float*)d_out;

    int Np = in_sizes[0]/3, Nl = in_sizes[2]/3;
    int B  = in_sizes[6];
    int Fp = in_sizes[1]/Np, Fl = in_sizes[3]/Nl;
    int n_prot = Np/B, n_lig = Nl/B;
    int n = n_prot + n_lig;
    int N = Np + Nl;
    int E = N*KNN;

    cudaFuncSetAttribute(edge_kernel, cudaFuncAttributeMaxDynamicSharedMemorySize, EDGE_SMEM);

    embed_kernel<<<N, 128>>>(protein_pos, protein_feat, ligand_pos, ligand_feat,
                             prot_w, prot_b, lig_w, lig_b, n_prot, n_lig, n, Fp, Fl);

    knn_kernel<<<dim3((n + 127)/128, B), 128, n*(int)sizeof(float4)>>>(n);

    w2prep_kernel<<<3*128, 128>>>(edge_w2);

    float step  = 10.0f/19.0f;
    float coeff = -0.5f/(step*step);
    attr_kernel<<<(E + 255)/256, 256>>>(E, step, coeff);

    ab_kernel<<<N/32, 256>>>(edge_w1, edge_b1, 0);
    for (int l = 0; l < 3; ++l) {
        edge_kernel<<<E/128, 256, EDGE_SMEM>>>(edge_w1, edge_b2, inf_w, inf_b, l);
        node_kernel<<<N/32, 256>>>(node_w1, node_b1, node_w2, node_b2, l);
        if (l < 2) ab_kernel<<<N/32, 256>>>(edge_w1, edge_b1, l + 1);
    }

    pool_kernel<<<B*16, 128>>>(n);
    out_kernel<<<1, 128>>>(out_w1, out_b1, out_w2, out_b2, output_kind, out, B);
}

// round 11
// speedup vs baseline: 1.4119x; 1.0856x over previous
#include <cuda_runtime.h>
#include <cuda_bf16.h>
#include <mma.h>
#include <math.h>

#define H   128
#define GG  20
#define KNN 32
#define MAXN 24000
#define MAXE (MAXN*KNN)

using namespace nvcuda;

// ---------------- f32x2 packed helpers --------------------------------------
__device__ __forceinline__ unsigned long long pack2(float lo, float hi) {
    unsigned long long r;
    asm("mov.b64 %0, {%1, %2};" : "=l"(r) : "f"(lo), "f"(hi));
    return r;
}
__device__ __forceinline__ unsigned long long dup2(float v) {
    unsigned long long r;
    asm("mov.b64 %0, {%1, %1};" : "=l"(r) : "f"(v));
    return r;
}
__device__ __forceinline__ void unpack2(unsigned long long p, float& lo, float& hi) {
    asm("mov.b64 {%0, %1}, %2;" : "=f"(lo), "=f"(hi) : "l"(p));
}
__device__ __forceinline__ unsigned long long fma2(unsigned long long a, unsigned long long b, unsigned long long c) {
    unsigned long long d;
    asm("fma.rn.f32x2 %0, %1, %2, %3;" : "=l"(d) : "l"(a), "l"(b), "l"(c));
    return d;
}
__device__ __forceinline__ unsigned long long add2(unsigned long long a, unsigned long long b) {
    unsigned long long d;
    asm("add.rn.f32x2 %0, %1, %2;" : "=l"(d) : "l"(a), "l"(b));
    return d;
}

// ---------------- scratch ----------------------------------------------------
__device__ __align__(16) float g_pos[MAXN*3];
__device__ __align__(16) float g_h  [MAXN*H];
__device__ __align__(16) float g_A  [MAXN*H];
__device__ __align__(16) float g_B  [MAXN*H];
__device__ __align__(16) float g_mi [MAXN*H];
__device__ int   g_nbr[MAXE];
__device__ float g_attr[(size_t)MAXE*GG];
__device__ float g_pre[16*H];
// baked W2^T as bf16 hi/lo: [layer][hi/lo][n=128][k=128]
__device__ __align__(16) unsigned short g_w2bf[3*2*16384];
// baked W1e as bf16 hi/lo col-major: [layer][hi/lo][n=128][kpad=32]
__device__ __align__(16) unsigned short g_w1ebf[3*2*4096];

// ---------------- K1: embeddings --------------------------------------------
__global__ void embed_kernel(const float* __restrict__ ppos, const float* __restrict__ pfeat,
                             const float* __restrict__ lpos, const float* __restrict__ lfeat,
                             const float* __restrict__ pw, const float* __restrict__ pb,
                             const float* __restrict__ lw, const float* __restrict__ lb,
                             int n_prot, int n_lig, int n, int Fp, int Fl)
{
    __shared__ float sf[32];
    int i = blockIdx.x, t = threadIdx.x;
    int b = i / n, j = i - b * n;
    const float *feat, *w, *bias, *pos; int F;
    if (j < n_prot) { int r = b*n_prot + j;            feat = pfeat + (size_t)r*Fp; w = pw; bias = pb; pos = ppos + (size_t)r*3; F = Fp; }
    else            { int r = b*n_lig  + (j - n_prot); feat = lfeat + (size_t)r*Fl; w = lw; bias = lb; pos = lpos + (size_t)r*3; F = Fl; }
    if (t < F) sf[t] = feat[t];
    __syncthreads();
    float acc = bias[t];
    for (int f = 0; f < F; ++f) acc += sf[f] * w[f*H + t];
    g_h[(size_t)i*H + t] = acc;
    if (t < 3) g_pos[i*3 + t] = pos[t];
}

// ---------------- K2: kNN ----------------------------------------------------
__global__ void knn_kernel(int n)
{
    extern __shared__ float4 spos4[];
    int b = blockIdx.y, tid = threadIdx.x;
    const float* gp = g_pos + (size_t)b*n*3;
    for (int i = tid; i < n; i += blockDim.x)
        spos4[i] = make_float4(gp[i*3], gp[i*3+1], gp[i*3+2], 0.f);
    __syncthreads();
    int c = blockIdx.x*blockDim.x + tid;
    if (c >= n) return;
    float4 pc = spos4[c];
    float bd[KNN]; int bi[KNN];
#pragma unroll
    for (int s = 0; s < KNN; ++s) { bd[s] = 3.402823466e38f; bi[s] = 0x7fffffff; }
    float wd = 3.402823466e38f; int wi = 0x7fffffff; int ws = 0;
    for (int j = 0; j < n; ++j) {
        if (j == c) continue;
        float4 pj = spos4[j];
        float dx = pc.x - pj.x, dy = pc.y - pj.y, dz = pc.z - pj.z;
        float d2 = dx*dx + dy*dy + dz*dz;
        if (d2 < wd || (d2 == wd && j < wi)) {
            bd[ws] = d2; bi[ws] = j;
            wd = bd[0]; wi = bi[0]; ws = 0;
#pragma unroll
            for (int s = 1; s < KNN; ++s)
                if (bd[s] > wd || (bd[s] == wd && bi[s] > wi)) { wd = bd[s]; wi = bi[s]; ws = s; }
        }
    }
    size_t base = ((size_t)(b*n + c))*KNN;
#pragma unroll
    for (int s = 0; s < KNN; ++s) g_nbr[base + s] = b*n + bi[s];
}

// ---------------- K3: Gaussian smearing + zero g_pre ------------------------
__global__ void attr_kernel(int E, float step, float coeff)
{
    int e = blockIdx.x*blockDim.x + threadIdx.x;
    if (e >= E) return;
    if (e < 16*H) g_pre[e] = 0.f;
    int dst = e >> 5;
    int src = g_nbr[e];
    float dx = g_pos[dst*3]   - g_pos[src*3];
    float dy = g_pos[dst*3+1] - g_pos[src*3+1];
    float dz = g_pos[dst*3+2] - g_pos[src*3+2];
    float d = sqrtf(dx*dx + dy*dy + dz*dz);
    size_t o = (size_t)e*GG;
#pragma unroll
    for (int g = 0; g < GG; ++g) {
        float t = d - g*step;
        g_attr[o + g] = expf(coeff*t*t);
    }
}

// ---------------- K3b: bake W2^T and W1e bf16 hi/lo --------------------------
__global__ void w2prep_kernel(const float* __restrict__ edge_w2,
                              const float* __restrict__ edge_w1)
{
    int l = blockIdx.x >> 7, nr = blockIdx.x & 127, k = threadIdx.x;
    float v = edge_w2[((size_t)l*H + k)*H + nr];
    __nv_bfloat16 hb = __float2bfloat16(v);
    float r = v - __bfloat162float(hb);
    __nv_bfloat16 lb = __float2bfloat16(r);
    g_w2bf[(l*2+0)*16384 + nr*128 + k] = __bfloat16_as_ushort(hb);
    g_w2bf[(l*2+1)*16384 + nr*128 + k] = __bfloat16_as_ushort(lb);
    if (k < 32) {
        float w = (k < GG) ? edge_w1[(size_t)l*276*H + k*H + nr] : 0.f;
        __nv_bfloat16 wh = __float2bfloat16(w);
        float wr = w - __bfloat162float(wh);
        __nv_bfloat16 wl = __float2bfloat16(wr);
        g_w1ebf[(l*2+0)*4096 + nr*32 + k] = __bfloat16_as_ushort(wh);
        g_w1ebf[(l*2+1)*4096 + nr*32 + k] = __bfloat16_as_ushort(wl);
    }
}

// ---------------- K4: A = h@W1i + b1, B = h@W1j ------------------------------
__global__ void __launch_bounds__(256) ab_kernel(const float* __restrict__ edge_w1,
                                                 const float* __restrict__ edge_b1, int l)
{
    __shared__ float sHt[128*34];
    int tid = threadIdx.x;
    int nb = blockIdx.x*32;
    for (int i = tid; i < 32*H; i += 256) { int nn = i>>7, k = i&127; sHt[k*34+nn] = g_h[(size_t)(nb+nn)*H + k]; }
    __syncthreads();
    int cg = tid & 15, ng = tid >> 4, col = cg*8;
    const ulonglong2* WA = (const ulonglong2*)(edge_w1 + (size_t)l*276*H + GG*H);
    const ulonglong2* WB = (const ulonglong2*)(edge_w1 + (size_t)l*276*H + (GG+H)*H);
    unsigned long long accA[2][4], accB[2][4];
#pragma unroll
    for (int c2 = 0; c2 < 4; ++c2) {
        unsigned long long b0 = pack2(edge_b1[l*H + col + 2*c2], edge_b1[l*H + col + 2*c2 + 1]);
        accA[0][c2] = b0; accA[1][c2] = b0; accB[0][c2] = 0ull; accB[1][c2] = 0ull;
    }
#pragma unroll 4
    for (int k = 0; k < H; ++k) {
        float2 a = *(const float2*)(sHt + k*34 + ng*2);
        ulonglong2 wa0 = __ldg(WA + k*32 + cg*2);
        ulonglong2 wa1 = __ldg(WA + k*32 + cg*2 + 1);
        ulonglong2 wb0 = __ldg(WB + k*32 + cg*2);
        ulonglong2 wb1 = __ldg(WB + k*32 + cg*2 + 1);
        unsigned long long a0 = dup2(a.x), a1 = dup2(a.y);
        unsigned long long wap[4] = {wa0.x, wa0.y, wa1.x, wa1.y};
        unsigned long long wbp[4] = {wb0.x, wb0.y, wb1.x, wb1.y};
#pragma unroll
        for (int c2 = 0; c2 < 4; ++c2) {
            accA[0][c2] = fma2(a0, wap[c2], accA[0][c2]);
            accA[1][c2] = fma2(a1, wap[c2], accA[1][c2]);
            accB[0][c2] = fma2(a0, wbp[c2], accB[0][c2]);
            accB[1][c2] = fma2(a1, wbp[c2], accB[1][c2]);
        }
    }
#pragma unroll
    for (int r = 0; r < 2; ++r) {
        float va[8], vb[8];
#pragma unroll
        for (int c2 = 0; c2 < 4; ++c2) {
            unpack2(accA[r][c2], va[2*c2], va[2*c2+1]);
            unpack2(accB[r][c2], vb[2*c2], vb[2*c2+1]);
        }
        size_t o = (size_t)(nb + ng*2 + r)*H + col;
        *(float4*)(g_A + o)     = make_float4(va[0],va[1],va[2],va[3]);
        *(float4*)(g_A + o + 4) = make_float4(va[4],va[5],va[6],va[7]);
        *(float4*)(g_B + o)     = make_float4(vb[0],vb[1],vb[2],vb[3]);
        *(float4*)(g_B + o + 4) = make_float4(vb[4],vb[5],vb[6],vb[7]);
    }
}

// ---------------- K5: edge MLP, both GEMMs on WMMA ---------------------------
// smem byte offsets
#define D_OFF     0
#define B_HI_OFF  67584
#define B_LO_OFF  102400
#define M1_HI_OFF 137216
#define M1_LO_OFF 172032
#define ATTRH_OFF 137216
#define ATTRL_OFF 147456
#define W1EH_OFF  157696
#define W1EL_OFF  167936
#define SA_OFF    206848
#define SB2_OFF   208896
#define SINFW_OFF 209408
#define SGATE_OFF 209920
#define SMI_OFF   210432
#define SSRC_OFF  212480
#define EDGE_SMEM 212992
#define LDAB  136
#define LDATT 40

__global__ void __launch_bounds__(256,1) edge_kernel(const float* __restrict__ edge_b2,
                                                     const float* __restrict__ inf_w,
                                                     const float* __restrict__ inf_b, int l)
{
    extern __shared__ __align__(16) char sh[];
    float* D = (float*)(sh + D_OFF);                    // [128][132] f32
    __nv_bfloat16* sBhi = (__nv_bfloat16*)(sh + B_HI_OFF);
    __nv_bfloat16* sBlo = (__nv_bfloat16*)(sh + B_LO_OFF);
    __nv_bfloat16* sM1hi = (__nv_bfloat16*)(sh + M1_HI_OFF);
    __nv_bfloat16* sM1lo = (__nv_bfloat16*)(sh + M1_LO_OFF);
    __nv_bfloat16* sAtH = (__nv_bfloat16*)(sh + ATTRH_OFF);
    __nv_bfloat16* sAtL = (__nv_bfloat16*)(sh + ATTRL_OFF);
    __nv_bfloat16* sWeH = (__nv_bfloat16*)(sh + W1EH_OFF);
    __nv_bfloat16* sWeL = (__nv_bfloat16*)(sh + W1EL_OFF);
    float* sAv   = (float*)(sh + SA_OFF);
    float* sb2   = (float*)(sh + SB2_OFF);
    float* sinfw = (float*)(sh + SINFW_OFF);
    float* sgate = (float*)(sh + SGATE_OFF);
    float* smi   = (float*)(sh + SMI_OFF);
    int*   ssrc  = (int*)(sh + SSRC_OFF);

    int tid = threadIdx.x;
    int wrp = tid >> 5;
    int e0 = blockIdx.x * 128;
    int d0 = e0 >> 5;

    // stage W2^T hi/lo (row-padded to 272B)
    {
        const uint4* gh = (const uint4*)(g_w2bf + (size_t)(l*2+0)*16384);
        const uint4* gl = (const uint4*)(g_w2bf + (size_t)(l*2+1)*16384);
        for (int i = tid; i < 2048; i += 256) {
            int row = i >> 4, q = i & 15;
            ((uint4*)((char*)sBhi + row*272))[q] = gh[row*16 + q];
            ((uint4*)((char*)sBlo + row*272))[q] = gl[row*16 + q];
        }
    }
    // stage W1e hi/lo (gmem ld=32 -> smem ld=40)
    {
        const char* gwh = (const char*)(g_w1ebf + (size_t)(l*2+0)*4096);
        const char* gwl = (const char*)(g_w1ebf + (size_t)(l*2+1)*4096);
        for (int i = tid; i < 2048; i += 256) {
            int nr = i >> 4, k2 = i & 15;
            *(unsigned*)((char*)sWeH + nr*80 + k2*4) = *(const unsigned*)(gwh + nr*64 + k2*4);
            *(unsigned*)((char*)sWeL + nr*80 + k2*4) = *(const unsigned*)(gwl + nr*64 + k2*4);
        }
    }
    // convert attr -> bf16 hi/lo tiles [e][kpad=32], ld=40
    for (int i = tid; i < 2048; i += 256) {
        int el = i >> 4, k2 = i & 15;
        int k = k2*2;
        float f0 = (k   < GG) ? g_attr[(size_t)(e0+el)*GG + k]     : 0.f;
        float f1 = (k+1 < GG) ? g_attr[(size_t)(e0+el)*GG + k + 1] : 0.f;
        __nv_bfloat16 h0 = __float2bfloat16(f0), h1 = __float2bfloat16(f1);
        __nv_bfloat16 l0 = __float2bfloat16(f0 - __bfloat162float(h0));
        __nv_bfloat16 l1 = __float2bfloat16(f1 - __bfloat162float(h1));
        *(unsigned*)((char*)sAtH + el*80 + k2*4) =
            ((unsigned)__bfloat16_as_ushort(h1) << 16) | __bfloat16_as_ushort(h0);
        *(unsigned*)((char*)sAtL + el*80 + k2*4) =
            ((unsigned)__bfloat16_as_ushort(l1) << 16) | __bfloat16_as_ushort(l0);
    }
    for (int i = tid; i < 4*H; i += 256) { sAv[i] = g_A[(size_t)d0*H + i]; smi[i] = 0.f; }
    if (tid < H) { sb2[tid] = edge_b2[l*H+tid]; sinfw[tid] = inf_w[l*H+tid]; sgate[tid] = inf_b[l]; }
    if (tid < 128) ssrc[tid] = g_nbr[e0 + tid];
    __syncthreads();

    // GEMM1: G = attr @ W1e  (k=32, 3 hi/lo products) -> D f32
    {
        int rg = wrp & 3, cgf = wrp >> 2;
        int er = rg*32, nc = cgf*64;
        wmma::fragment<wmma::accumulator,16,16,16,float> acc[2][4];
#pragma unroll
        for (int i = 0; i < 2; ++i)
#pragma unroll
            for (int j = 0; j < 4; ++j) wmma::fill_fragment(acc[i][j], 0.f);
#pragma unroll
        for (int k0 = 0; k0 < 32; k0 += 16) {
            wmma::fragment<wmma::matrix_a,16,16,16,__nv_bfloat16,wmma::row_major> ah[2], al[2];
            wmma::fragment<wmma::matrix_b,16,16,16,__nv_bfloat16,wmma::col_major> bh[4], bl[4];
#pragma unroll
            for (int i = 0; i < 2; ++i) {
                wmma::load_matrix_sync(ah[i], sAtH + (er + i*16)*LDATT + k0, LDATT);
                wmma::load_matrix_sync(al[i], sAtL + (er + i*16)*LDATT + k0, LDATT);
            }
#pragma unroll
            for (int j = 0; j < 4; ++j) {
                wmma::load_matrix_sync(bh[j], sWeH + (nc + j*16)*LDATT + k0, LDATT);
                wmma::load_matrix_sync(bl[j], sWeL + (nc + j*16)*LDATT + k0, LDATT);
            }
#pragma unroll
            for (int i = 0; i < 2; ++i)
#pragma unroll
                for (int j = 0; j < 4; ++j) {
                    wmma::mma_sync(acc[i][j], ah[i], bh[j], acc[i][j]);
                    wmma::mma_sync(acc[i][j], ah[i], bl[j], acc[i][j]);
                    wmma::mma_sync(acc[i][j], al[i], bh[j], acc[i][j]);
                }
        }
#pragma unroll
        for (int i = 0; i < 2; ++i)
#pragma unroll
            for (int j = 0; j < 4; ++j)
                wmma::store_matrix_sync(D + (er + i*16)*132 + nc + j*16, acc[i][j],
                                        132, wmma::mem_row_major);
    }
    __syncthreads();

    // lite pass: m1 = relu(G + A[dst] + B[src]) -> bf16 hi/lo tiles
    {
        int e = tid >> 1, half = tid & 1;
        int srcA = ssrc[e];
        const float4* Brow = (const float4*)(g_B + (size_t)srcA*H);
        const float* sAd = sAv + (e>>5)*H;
#pragma unroll 4
        for (int i4 = 0; i4 < 16; ++i4) {
            int k0 = half*64 + i4*4;
            float4 bv = Brow[k0 >> 2];
            float4 gv = *(const float4*)(D + e*132 + k0);
            float x0 = fmaxf(gv.x + sAd[k0]   + bv.x, 0.f);
            float x1 = fmaxf(gv.y + sAd[k0+1] + bv.y, 0.f);
            float x2 = fmaxf(gv.z + sAd[k0+2] + bv.z, 0.f);
            float x3 = fmaxf(gv.w + sAd[k0+3] + bv.w, 0.f);
            __nv_bfloat16 h0 = __float2bfloat16(x0), h1 = __float2bfloat16(x1);
            __nv_bfloat16 h2 = __float2bfloat16(x2), h3 = __float2bfloat16(x3);
            __nv_bfloat16 l0 = __float2bfloat16(x0 - __bfloat162float(h0));
            __nv_bfloat16 l1 = __float2bfloat16(x1 - __bfloat162float(h1));
            __nv_bfloat16 l2 = __float2bfloat16(x2 - __bfloat162float(h2));
            __nv_bfloat16 l3 = __float2bfloat16(x3 - __bfloat162float(h3));
            unsigned hi01 = ((unsigned)__bfloat16_as_ushort(h1) << 16) | __bfloat16_as_ushort(h0);
            unsigned hi23 = ((unsigned)__bfloat16_as_ushort(h3) << 16) | __bfloat16_as_ushort(h2);
            unsigned lo01 = ((unsigned)__bfloat16_as_ushort(l1) << 16) | __bfloat16_as_ushort(l0);
            unsigned lo23 = ((unsigned)__bfloat16_as_ushort(l3) << 16) | __bfloat16_as_ushort(l2);
            unsigned boff = e*272 + k0*2;
            *(uint2*)((char*)sM1hi + boff) = make_uint2(hi01, hi23);
            *(uint2*)((char*)sM1lo + boff) = make_uint2(lo01, lo23);
        }
    }
    __syncthreads();

    // GEMM2: m = m1 @ W2  (k=128, 3 hi/lo products) -> D f32
    {
        int rg = wrp & 3, cgf = wrp >> 2;
        int er = rg*32, nc = cgf*64;
        wmma::fragment<wmma::accumulator,16,16,16,float> acc[2][4];
#pragma unroll
        for (int i = 0; i < 2; ++i)
#pragma unroll
            for (int j = 0; j < 4; ++j) wmma::fill_fragment(acc[i][j], 0.f);
#pragma unroll
        for (int k0 = 0; k0 < 128; k0 += 16) {
            wmma::fragment<wmma::matrix_a,16,16,16,__nv_bfloat16,wmma::row_major> ah[2], al[2];
            wmma::fragment<wmma::matrix_b,16,16,16,__nv_bfloat16,wmma::col_major> bh[4], bl[4];
#pragma unroll
            for (int i = 0; i < 2; ++i) {
                wmma::load_matrix_sync(ah[i], sM1hi + (er + i*16)*LDAB + k0, LDAB);
                wmma::load_matrix_sync(al[i], sM1lo + (er + i*16)*LDAB + k0, LDAB);
            }
#pragma unroll
            for (int j = 0; j < 4; ++j) {
                wmma::load_matrix_sync(bh[j], sBhi + (nc + j*16)*LDAB + k0, LDAB);
                wmma::load_matrix_sync(bl[j], sBlo + (nc + j*16)*LDAB + k0, LDAB);
            }
#pragma unroll
            for (int i = 0; i < 2; ++i)
#pragma unroll
                for (int j = 0; j < 4; ++j) {
                    wmma::mma_sync(acc[i][j], ah[i], bh[j], acc[i][j]);
                    wmma::mma_sync(acc[i][j], ah[i], bl[j], acc[i][j]);
                    wmma::mma_sync(acc[i][j], al[i], bh[j], acc[i][j]);
                }
        }
#pragma unroll
        for (int i = 0; i < 2; ++i)
#pragma unroll
            for (int j = 0; j < 4; ++j)
                wmma::store_matrix_sync(D + (er + i*16)*132 + nc + j*16, acc[i][j],
                                        132, wmma::mem_row_major);
    }
    __syncthreads();

    // epilogue stage 1: bias + relu + gate logits (2 threads per edge)
    {
        int e = tid >> 1, c0 = (tid & 1)*64;
        float p = 0.f;
#pragma unroll 8
        for (int c = 0; c < 64; ++c) {
            float v = D[e*132 + c0 + c] + sb2[c0 + c];
            v = fmaxf(v, 0.f);
            D[e*132 + c0 + c] = v;
            p += v * sinfw[c0 + c];
        }
        atomicAdd(&sgate[e], p);
    }
    __syncthreads();
    if (tid < 128) sgate[tid] = 1.f/(1.f + expf(-sgate[tid]));
    __syncthreads();

    // epilogue stage 2: mi[d][c] = sum_e m[e][c]*gate[e]
    {
        int c = tid & 127, hf = tid >> 7;
#pragma unroll
        for (int d = 0; d < 4; ++d) {
            float s = 0.f;
#pragma unroll 4
            for (int j = 0; j < 16; ++j) {
                int e = d*32 + hf*16 + j;
                s += D[e*132 + c] * sgate[e];
            }
            atomicAdd(&smi[d*H + c], s);
        }
    }
    __syncthreads();
    for (int i = tid; i < 4*H; i += 256) g_mi[(size_t)d0*H + i] = smi[i];
}

// ---------------- K6: node MLP + residual, 64-node tiles ---------------------
#define LDZ 68
#define NODE_SMEM (256*LDZ*4)
__global__ void __launch_bounds__(256) node_kernel(const float* __restrict__ nw1,
                                                   const float* __restrict__ nb1,
                                                   const float* __restrict__ nw2,
                                                   const float* __restrict__ nb2, int l)
{
    extern __shared__ float sZ[];   // [256 k][68]  ([mi | h] k-major; reused for u)
    int tid = threadIdx.x;
    int nb = blockIdx.x*64;
    for (int i = tid; i < 64*H; i += 256) {
        int nn = i>>7, k = i&127;
        sZ[k*LDZ + nn]     = g_mi[(size_t)(nb+nn)*H + k];
        sZ[(H+k)*LDZ + nn] = g_h [(size_t)(nb+nn)*H + k];
    }
    __syncthreads();
    int cg = tid & 15, ng = tid >> 4, col = cg*8;
    const ulonglong2* W1a = (const ulonglong2*)(nw1 + (size_t)l*2*H*H);
    const ulonglong2* W1b = W1a + H*H/4;
    unsigned long long acc[4][4];
#pragma unroll
    for (int c2 = 0; c2 < 4; ++c2) {
        unsigned long long b = pack2(nb1[l*H + col + 2*c2], nb1[l*H + col + 2*c2 + 1]);
#pragma unroll
        for (int r = 0; r < 4; ++r) acc[r][c2] = b;
    }
#pragma unroll 2
    for (int k = 0; k < H; ++k) {
        float4 am = *(const float4*)(sZ + k*LDZ + ng*4);
        float4 ah = *(const float4*)(sZ + (H+k)*LDZ + ng*4);
        ulonglong2 wa0 = __ldg(W1a + k*32 + cg*2);
        ulonglong2 wa1 = __ldg(W1a + k*32 + cg*2 + 1);
        ulonglong2 wb0 = __ldg(W1b + k*32 + cg*2);
        ulonglong2 wb1 = __ldg(W1b + k*32 + cg*2 + 1);
        unsigned long long mm[4] = {dup2(am.x), dup2(am.y), dup2(am.z), dup2(am.w)};
        unsigned long long hh[4] = {dup2(ah.x), dup2(ah.y), dup2(ah.z), dup2(ah.w)};
        unsigned long long wap[4] = {wa0.x, wa0.y, wa1.x, wa1.y};
        unsigned long long wbp[4] = {wb0.x, wb0.y, wb1.x, wb1.y};
#pragma unroll
        for (int r = 0; r < 4; ++r)
#pragma unroll
            for (int c2 = 0; c2 < 4; ++c2) {
                acc[r][c2] = fma2(mm[r], wap[c2], acc[r][c2]);
                acc[r][c2] = fma2(hh[r], wbp[c2], acc[r][c2]);
            }
    }
    __syncthreads();   // done reading sZ
#pragma unroll
    for (int r = 0; r < 4; ++r)
#pragma unroll
        for (int c2 = 0; c2 < 4; ++c2) {
            float lo, hi;
            unpack2(acc[r][c2], lo, hi);
            sZ[(col + 2*c2)*LDZ + ng*4 + r]     = fmaxf(lo, 0.f);
            sZ[(col + 2*c2 + 1)*LDZ + ng*4 + r] = fmaxf(hi, 0.f);
        }
    __syncthreads();
    const ulonglong2* W2 = (const ulonglong2*)(nw2 + (size_t)l*H*H);
    unsigned long long acc2[4][4];
#pragma unroll
    for (int c2 = 0; c2 < 4; ++c2) {
        unsigned long long b = pack2(nb2[l*H + col + 2*c2], nb2[l*H + col + 2*c2 + 1]);
#pragma unroll
        for (int r = 0; r < 4; ++r) acc2[r][c2] = b;
    }
#pragma unroll 4
    for (int k = 0; k < H; ++k) {
        float4 a = *(const float4*)(sZ + k*LDZ + ng*4);
        ulonglong2 w0 = __ldg(W2 + k*32 + cg*2);
        ulonglong2 w1 = __ldg(W2 + k*32 + cg*2 + 1);
        unsigned long long ad[4] = {dup2(a.x), dup2(a.y), dup2(a.z), dup2(a.w)};
        unsigned long long wp[4] = {w0.x, w0.y, w1.x, w1.y};
#pragma unroll
        for (int r = 0; r < 4; ++r)
#pragma unroll
            for (int c2 = 0; c2 < 4; ++c2) acc2[r][c2] = fma2(ad[r], wp[c2], acc2[r][c2]);
    }
#pragma unroll
    for (int r = 0; r < 4; ++r) {
        float v[8];
#pragma unroll
        for (int c2 = 0; c2 < 4; ++c2) unpack2(acc2[r][c2], v[2*c2], v[2*c2+1]);
        size_t o = (size_t)(nb + ng*4 + r)*H + col;
        float4* hp = (float4*)(g_h + o);
        float4 h0 = hp[0], h1 = hp[1];
        h0.x += v[0]; h0.y += v[1]; h0.z += v[2]; h0.w += v[3];
        h1.x += v[4]; h1.y += v[5]; h1.z += v[6]; h1.w += v[7];
        hp[0] = h0; hp[1] = h1;
    }
}

// ---------------- K7/K8 ------------------------------------------------------
__global__ void pool_kernel(int n)
{
    int b = blockIdx.x >> 4, s = blockIdx.x & 15;
    int c = threadIdx.x;
    float acc = 0.f;
    for (int i = s; i < n; i += 16) acc += g_h[((size_t)b*n + i)*H + c];
    atomicAdd(&g_pre[b*H + c], acc);
}

__global__ void out_kernel(const float* __restrict__ w1, const float* __restrict__ b1,
                           const float* __restrict__ w2, const float* __restrict__ b2,
                           const int* __restrict__ kind, float* __restrict__ out, int B)
{
    __shared__ float sU[H]; __shared__ float so[3];
    int t = threadIdx.x;
    for (int b = 0; b < B; ++b) {
        float x = b1[t];
        for (int k = 0; k < H; ++k) x += g_pre[b*H + k]*w1[k*H + t];
        float sp = (x > 0.f) ? x + log1pf(expf(-x)) : log1pf(expf(x));
        sU[t] = sp - 0.6931471805599453f;
        __syncthreads();
        if (t < 3) { float s = b2[t]; for (int k = 0; k < H; ++k) s += sU[k]*w2[k*3 + t]; so[t] = s; }
        __syncthreads();
        if (t == 0) out[b] = so[kind[b] - 1];
        __syncthreads();
    }
}

// ---------------- host ------------------------------------------------------
extern "C" void kernel_launch(void* const* d_in, const int* in_sizes, int n_in,
                              void* d_out, int out_size)
{
    const float* protein_pos  = (const float*)d_in[0];
    const float* protein_feat = (const float*)d_in[1];
    const float* ligand_pos   = (const float*)d_in[2];
    const float* ligand_feat  = (const float*)d_in[3];
    const int*   output_kind  = (const int*)d_in[6];
    const float* prot_w = (const float*)d_in[7];  const float* prot_b = (const float*)d_in[8];
    const float* lig_w  = (const float*)d_in[9];  const float* lig_b  = (const float*)d_in[10];
    const float* edge_w1 = (const float*)d_in[11]; const float* edge_b1 = (const float*)d_in[12];
    const float* edge_w2 = (const float*)d_in[13]; const float* edge_b2 = (const float*)d_in[14];
    const float* inf_w   = (const float*)d_in[15]; const float* inf_b   = (const float*)d_in[16];
    const float* node_w1 = (const float*)d_in[17]; const float* node_b1 = (const float*)d_in[18];
    const float* node_w2 = (const float*)d_in[19]; const float* node_b2 = (const float*)d_in[20];
    const float* out_w1  = (const float*)d_in[21]; const float* out_b1  = (const float*)d_in[22];
    const float* out_w2  = (const float*)d_in[23]; const float* out_b2  = (const float*)d_in[24];
    float* out = (float*)d_out;

    int Np = in_sizes[0]/3, Nl = in_sizes[2]/3;
    int B  = in_sizes[6];
    int Fp = in_sizes[1]/Np, Fl = in_sizes[3]/Nl;
    int n_prot = Np/B, n_lig = Nl/B;
    int n = n_prot + n_lig;
    int N = Np + Nl;
    int E = N*KNN;

    cudaFuncSetAttribute(edge_kernel, cudaFuncAttributeMaxDynamicSharedMemorySize, EDGE_SMEM);
    cudaFuncSetAttribute(node_kernel, cudaFuncAttributeMaxDynamicSharedMemorySize, NODE_SMEM);

    embed_kernel<<<N, 128>>>(protein_pos, protein_feat, ligand_pos, ligand_feat,
                             prot_w, prot_b, lig_w, lig_b, n_prot, n_lig, n, Fp, Fl);

    knn_kernel<<<dim3((n + 127)/128, B), 128, n*(int)sizeof(float4)>>>(n);

    w2prep_kernel<<<3*128, 128>>>(edge_w2, edge_w1);

    float step  = 10.0f/19.0f;
    float coeff = -0.5f/(step*step);
    attr_kernel<<<(E + 255)/256, 256>>>(E, step, coeff);

    ab_kernel<<<N/32, 256>>>(edge_w1, edge_b1, 0);
    for (int l = 0; l < 3; ++l) {
        edge_kernel<<<E/128, 256, EDGE_SMEM>>>(edge_b2, inf_w, inf_b, l);
        node_kernel<<<N/64, 256, NODE_SMEM>>>(node_w1, node_b1, node_w2, node_b2, l);
        if (l < 2) ab_kernel<<<N/32, 256>>>(edge_w1, edge_b1, l + 1);
    }

    pool_kernel<<<B*16, 128>>>(n);
    out_kernel<<<1, 128>>>(out_w1, out_b1, out_w2, out_b2, output_kind, out, B);
}

// round 12
// speedup vs baseline: 1.4157x; 1.0027x over previous
#include <cuda_runtime.h>
#include <cuda_bf16.h>
#include <mma.h>
#include <math.h>

#define H   128
#define GG  20
#define KNN 32
#define MAXN 24000
#define MAXE (MAXN*KNN)

using namespace nvcuda;

// ---------------- f32x2 packed helpers --------------------------------------
__device__ __forceinline__ unsigned long long pack2(float lo, float hi) {
    unsigned long long r;
    asm("mov.b64 %0, {%1, %2};" : "=l"(r) : "f"(lo), "f"(hi));
    return r;
}
__device__ __forceinline__ unsigned long long dup2(float v) {
    unsigned long long r;
    asm("mov.b64 %0, {%1, %1};" : "=l"(r) : "f"(v));
    return r;
}
__device__ __forceinline__ void unpack2(unsigned long long p, float& lo, float& hi) {
    asm("mov.b64 {%0, %1}, %2;" : "=f"(lo), "=f"(hi) : "l"(p));
}
__device__ __forceinline__ unsigned long long fma2(unsigned long long a, unsigned long long b, unsigned long long c) {
    unsigned long long d;
    asm("fma.rn.f32x2 %0, %1, %2, %3;" : "=l"(d) : "l"(a), "l"(b), "l"(c));
    return d;
}
__device__ __forceinline__ unsigned long long add2(unsigned long long a, unsigned long long b) {
    unsigned long long d;
    asm("add.rn.f32x2 %0, %1, %2;" : "=l"(d) : "l"(a), "l"(b));
    return d;
}

// ---------------- scratch ----------------------------------------------------
__device__ __align__(16) float g_pos[MAXN*3];
__device__ __align__(16) float g_h  [MAXN*H];
__device__ __align__(16) float g_A  [MAXN*H];
__device__ __align__(16) float g_B  [MAXN*H];
__device__ __align__(16) float g_mi [MAXN*H];
__device__ int   g_nbr[MAXE];
__device__ float g_attr[(size_t)MAXE*GG];
__device__ float g_pre[16*H];
// baked W2^T as bf16 hi/lo: [layer][hi/lo][n=128][k=128]
__device__ __align__(16) unsigned short g_w2bf[3*2*16384];
// baked W1e as bf16 hi/lo col-major: [layer][hi/lo][n=128][kpad=32]
__device__ __align__(16) unsigned short g_w1ebf[3*2*4096];

// ---------------- K1: embeddings --------------------------------------------
__global__ void embed_kernel(const float* __restrict__ ppos, const float* __restrict__ pfeat,
                             const float* __restrict__ lpos, const float* __restrict__ lfeat,
                             const float* __restrict__ pw, const float* __restrict__ pb,
                             const float* __restrict__ lw, const float* __restrict__ lb,
                             int n_prot, int n_lig, int n, int Fp, int Fl)
{
    __shared__ float sf[32];
    int i = blockIdx.x, t = threadIdx.x;
    int b = i / n, j = i - b * n;
    const float *feat, *w, *bias, *pos; int F;
    if (j < n_prot) { int r = b*n_prot + j;            feat = pfeat + (size_t)r*Fp; w = pw; bias = pb; pos = ppos + (size_t)r*3; F = Fp; }
    else            { int r = b*n_lig  + (j - n_prot); feat = lfeat + (size_t)r*Fl; w = lw; bias = lb; pos = lpos + (size_t)r*3; F = Fl; }
    if (t < F) sf[t] = feat[t];
    __syncthreads();
    float acc = bias[t];
    for (int f = 0; f < F; ++f) acc += sf[f] * w[f*H + t];
    g_h[(size_t)i*H + t] = acc;
    if (t < 3) g_pos[i*3 + t] = pos[t];
}

// ---------------- K2: kNN ----------------------------------------------------
__global__ void knn_kernel(int n)
{
    extern __shared__ float4 spos4[];
    int b = blockIdx.y, tid = threadIdx.x;
    const float* gp = g_pos + (size_t)b*n*3;
    for (int i = tid; i < n; i += blockDim.x)
        spos4[i] = make_float4(gp[i*3], gp[i*3+1], gp[i*3+2], 0.f);
    __syncthreads();
    int c = blockIdx.x*blockDim.x + tid;
    if (c >= n) return;
    float4 pc = spos4[c];
    float bd[KNN]; int bi[KNN];
#pragma unroll
    for (int s = 0; s < KNN; ++s) { bd[s] = 3.402823466e38f; bi[s] = 0x7fffffff; }
    float wd = 3.402823466e38f; int wi = 0x7fffffff; int ws = 0;
    for (int j = 0; j < n; ++j) {
        if (j == c) continue;
        float4 pj = spos4[j];
        float dx = pc.x - pj.x, dy = pc.y - pj.y, dz = pc.z - pj.z;
        float d2 = dx*dx + dy*dy + dz*dz;
        if (d2 < wd || (d2 == wd && j < wi)) {
            bd[ws] = d2; bi[ws] = j;
            wd = bd[0]; wi = bi[0]; ws = 0;
#pragma unroll
            for (int s = 1; s < KNN; ++s)
                if (bd[s] > wd || (bd[s] == wd && bi[s] > wi)) { wd = bd[s]; wi = bi[s]; ws = s; }
        }
    }
    size_t base = ((size_t)(b*n + c))*KNN;
#pragma unroll
    for (int s = 0; s < KNN; ++s) g_nbr[base + s] = b*n + bi[s];
}

// ---------------- K3: Gaussian smearing + zero g_pre ------------------------
__global__ void attr_kernel(int E, float step, float coeff)
{
    int e = blockIdx.x*blockDim.x + threadIdx.x;
    if (e >= E) return;
    if (e < 16*H) g_pre[e] = 0.f;
    int dst = e >> 5;
    int src = g_nbr[e];
    float dx = g_pos[dst*3]   - g_pos[src*3];
    float dy = g_pos[dst*3+1] - g_pos[src*3+1];
    float dz = g_pos[dst*3+2] - g_pos[src*3+2];
    float d = sqrtf(dx*dx + dy*dy + dz*dz);
    size_t o = (size_t)e*GG;
#pragma unroll
    for (int g = 0; g < GG; ++g) {
        float t = d - g*step;
        g_attr[o + g] = expf(coeff*t*t);
    }
}

// ---------------- K3b: bake W2^T and W1e bf16 hi/lo --------------------------
__global__ void w2prep_kernel(const float* __restrict__ edge_w2,
                              const float* __restrict__ edge_w1)
{
    int l = blockIdx.x >> 7, nr = blockIdx.x & 127, k = threadIdx.x;
    float v = edge_w2[((size_t)l*H + k)*H + nr];
    __nv_bfloat16 hb = __float2bfloat16(v);
    float r = v - __bfloat162float(hb);
    __nv_bfloat16 lb = __float2bfloat16(r);
    g_w2bf[(l*2+0)*16384 + nr*128 + k] = __bfloat16_as_ushort(hb);
    g_w2bf[(l*2+1)*16384 + nr*128 + k] = __bfloat16_as_ushort(lb);
    if (k < 32) {
        float w = (k < GG) ? edge_w1[(size_t)l*276*H + k*H + nr] : 0.f;
        __nv_bfloat16 wh = __float2bfloat16(w);
        float wr = w - __bfloat162float(wh);
        __nv_bfloat16 wl = __float2bfloat16(wr);
        g_w1ebf[(l*2+0)*4096 + nr*32 + k] = __bfloat16_as_ushort(wh);
        g_w1ebf[(l*2+1)*4096 + nr*32 + k] = __bfloat16_as_ushort(wl);
    }
}

// ---------------- K4: A = h@W1i + b1, B = h@W1j ------------------------------
__global__ void __launch_bounds__(256) ab_kernel(const float* __restrict__ edge_w1,
                                                 const float* __restrict__ edge_b1, int l)
{
    __shared__ float sHt[128*34];
    int tid = threadIdx.x;
    int nb = blockIdx.x*32;
    for (int i = tid; i < 32*H; i += 256) { int nn = i>>7, k = i&127; sHt[k*34+nn] = g_h[(size_t)(nb+nn)*H + k]; }
    __syncthreads();
    int cg = tid & 15, ng = tid >> 4, col = cg*8;
    const ulonglong2* WA = (const ulonglong2*)(edge_w1 + (size_t)l*276*H + GG*H);
    const ulonglong2* WB = (const ulonglong2*)(edge_w1 + (size_t)l*276*H + (GG+H)*H);
    unsigned long long accA[2][4], accB[2][4];
#pragma unroll
    for (int c2 = 0; c2 < 4; ++c2) {
        unsigned long long b0 = pack2(edge_b1[l*H + col + 2*c2], edge_b1[l*H + col + 2*c2 + 1]);
        accA[0][c2] = b0; accA[1][c2] = b0; accB[0][c2] = 0ull; accB[1][c2] = 0ull;
    }
#pragma unroll 4
    for (int k = 0; k < H; ++k) {
        float2 a = *(const float2*)(sHt + k*34 + ng*2);
        ulonglong2 wa0 = __ldg(WA + k*32 + cg*2);
        ulonglong2 wa1 = __ldg(WA + k*32 + cg*2 + 1);
        ulonglong2 wb0 = __ldg(WB + k*32 + cg*2);
        ulonglong2 wb1 = __ldg(WB + k*32 + cg*2 + 1);
        unsigned long long a0 = dup2(a.x), a1 = dup2(a.y);
        unsigned long long wap[4] = {wa0.x, wa0.y, wa1.x, wa1.y};
        unsigned long long wbp[4] = {wb0.x, wb0.y, wb1.x, wb1.y};
#pragma unroll
        for (int c2 = 0; c2 < 4; ++c2) {
            accA[0][c2] = fma2(a0, wap[c2], accA[0][c2]);
            accA[1][c2] = fma2(a1, wap[c2], accA[1][c2]);
            accB[0][c2] = fma2(a0, wbp[c2], accB[0][c2]);
            accB[1][c2] = fma2(a1, wbp[c2], accB[1][c2]);
        }
    }
#pragma unroll
    for (int r = 0; r < 2; ++r) {
        float va[8], vb[8];
#pragma unroll
        for (int c2 = 0; c2 < 4; ++c2) {
            unpack2(accA[r][c2], va[2*c2], va[2*c2+1]);
            unpack2(accB[r][c2], vb[2*c2], vb[2*c2+1]);
        }
        size_t o = (size_t)(nb + ng*2 + r)*H + col;
        *(float4*)(g_A + o)     = make_float4(va[0],va[1],va[2],va[3]);
        *(float4*)(g_A + o + 4) = make_float4(va[4],va[5],va[6],va[7]);
        *(float4*)(g_B + o)     = make_float4(vb[0],vb[1],vb[2],vb[3]);
        *(float4*)(g_B + o + 4) = make_float4(vb[4],vb[5],vb[6],vb[7]);
    }
}

// ---------------- K5: edge MLP, both GEMMs on WMMA ---------------------------
// smem byte offsets
#define D_OFF     0
#define B_HI_OFF  67584
#define B_LO_OFF  102400
#define M1_HI_OFF 137216
#define M1_LO_OFF 172032
#define ATTRH_OFF 137216
#define ATTRL_OFF 147456
#define W1EH_OFF  157696
#define W1EL_OFF  167936
#define SA_OFF    206848
#define SB2_OFF   208896
#define SINFW_OFF 209408
#define SGATE_OFF 209920
#define SMI_OFF   210432
#define SSRC_OFF  212480
#define EDGE_SMEM 212992
#define LDAB  136
#define LDATT 40

__global__ void __launch_bounds__(256,1) edge_kernel(const float* __restrict__ edge_b2,
                                                     const float* __restrict__ inf_w,
                                                     const float* __restrict__ inf_b, int l)
{
    extern __shared__ __align__(16) char sh[];
    float* D = (float*)(sh + D_OFF);                    // [128][132] f32
    __nv_bfloat16* sBhi = (__nv_bfloat16*)(sh + B_HI_OFF);
    __nv_bfloat16* sBlo = (__nv_bfloat16*)(sh + B_LO_OFF);
    __nv_bfloat16* sM1hi = (__nv_bfloat16*)(sh + M1_HI_OFF);
    __nv_bfloat16* sM1lo = (__nv_bfloat16*)(sh + M1_LO_OFF);
    __nv_bfloat16* sAtH = (__nv_bfloat16*)(sh + ATTRH_OFF);
    __nv_bfloat16* sAtL = (__nv_bfloat16*)(sh + ATTRL_OFF);
    __nv_bfloat16* sWeH = (__nv_bfloat16*)(sh + W1EH_OFF);
    __nv_bfloat16* sWeL = (__nv_bfloat16*)(sh + W1EL_OFF);
    float* sAv   = (float*)(sh + SA_OFF);
    float* sb2   = (float*)(sh + SB2_OFF);
    float* sinfw = (float*)(sh + SINFW_OFF);
    float* sgate = (float*)(sh + SGATE_OFF);
    float* smi   = (float*)(sh + SMI_OFF);
    int*   ssrc  = (int*)(sh + SSRC_OFF);

    int tid = threadIdx.x;
    int wrp = tid >> 5;
    int e0 = blockIdx.x * 128;
    int d0 = e0 >> 5;

    // stage W2^T hi/lo (row-padded to 272B)
    {
        const uint4* gh = (const uint4*)(g_w2bf + (size_t)(l*2+0)*16384);
        const uint4* gl = (const uint4*)(g_w2bf + (size_t)(l*2+1)*16384);
        for (int i = tid; i < 2048; i += 256) {
            int row = i >> 4, q = i & 15;
            ((uint4*)((char*)sBhi + row*272))[q] = gh[row*16 + q];
            ((uint4*)((char*)sBlo + row*272))[q] = gl[row*16 + q];
        }
    }
    // stage W1e hi/lo (gmem ld=32 -> smem ld=40)
    {
        const char* gwh = (const char*)(g_w1ebf + (size_t)(l*2+0)*4096);
        const char* gwl = (const char*)(g_w1ebf + (size_t)(l*2+1)*4096);
        for (int i = tid; i < 2048; i += 256) {
            int nr = i >> 4, k2 = i & 15;
            *(unsigned*)((char*)sWeH + nr*80 + k2*4) = *(const unsigned*)(gwh + nr*64 + k2*4);
            *(unsigned*)((char*)sWeL + nr*80 + k2*4) = *(const unsigned*)(gwl + nr*64 + k2*4);
        }
    }
    // convert attr -> bf16 hi/lo tiles [e][kpad=32], ld=40
    for (int i = tid; i < 2048; i += 256) {
        int el = i >> 4, k2 = i & 15;
        int k = k2*2;
        float f0 = (k   < GG) ? g_attr[(size_t)(e0+el)*GG + k]     : 0.f;
        float f1 = (k+1 < GG) ? g_attr[(size_t)(e0+el)*GG + k + 1] : 0.f;
        __nv_bfloat16 h0 = __float2bfloat16(f0), h1 = __float2bfloat16(f1);
        __nv_bfloat16 l0 = __float2bfloat16(f0 - __bfloat162float(h0));
        __nv_bfloat16 l1 = __float2bfloat16(f1 - __bfloat162float(h1));
        *(unsigned*)((char*)sAtH + el*80 + k2*4) =
            ((unsigned)__bfloat16_as_ushort(h1) << 16) | __bfloat16_as_ushort(h0);
        *(unsigned*)((char*)sAtL + el*80 + k2*4) =
            ((unsigned)__bfloat16_as_ushort(l1) << 16) | __bfloat16_as_ushort(l0);
    }
    for (int i = tid; i < 4*H; i += 256) { sAv[i] = g_A[(size_t)d0*H + i]; smi[i] = 0.f; }
    if (tid < H) { sb2[tid] = edge_b2[l*H+tid]; sinfw[tid] = inf_w[l*H+tid]; sgate[tid] = inf_b[l]; }
    if (tid < 128) ssrc[tid] = g_nbr[e0 + tid];
    __syncthreads();

    // GEMM1: G = attr @ W1e  (k=32, 3 hi/lo products) -> D f32
    {
        int rg = wrp & 3, cgf = wrp >> 2;
        int er = rg*32, nc = cgf*64;
        wmma::fragment<wmma::accumulator,16,16,16,float> acc[2][4];
#pragma unroll
        for (int i = 0; i < 2; ++i)
#pragma unroll
            for (int j = 0; j < 4; ++j) wmma::fill_fragment(acc[i][j], 0.f);
#pragma unroll
        for (int k0 = 0; k0 < 32; k0 += 16) {
            wmma::fragment<wmma::matrix_a,16,16,16,__nv_bfloat16,wmma::row_major> ah[2], al[2];
            wmma::fragment<wmma::matrix_b,16,16,16,__nv_bfloat16,wmma::col_major> bh[4], bl[4];
#pragma unroll
            for (int i = 0; i < 2; ++i) {
                wmma::load_matrix_sync(ah[i], sAtH + (er + i*16)*LDATT + k0, LDATT);
                wmma::load_matrix_sync(al[i], sAtL + (er + i*16)*LDATT + k0, LDATT);
            }
#pragma unroll
            for (int j = 0; j < 4; ++j) {
                wmma::load_matrix_sync(bh[j], sWeH + (nc + j*16)*LDATT + k0, LDATT);
                wmma::load_matrix_sync(bl[j], sWeL + (nc + j*16)*LDATT + k0, LDATT);
            }
#pragma unroll
            for (int i = 0; i < 2; ++i)
#pragma unroll
                for (int j = 0; j < 4; ++j) {
                    wmma::mma_sync(acc[i][j], ah[i], bh[j], acc[i][j]);
                    wmma::mma_sync(acc[i][j], ah[i], bl[j], acc[i][j]);
                    wmma::mma_sync(acc[i][j], al[i], bh[j], acc[i][j]);
                }
        }
#pragma unroll
        for (int i = 0; i < 2; ++i)
#pragma unroll
            for (int j = 0; j < 4; ++j)
                wmma::store_matrix_sync(D + (er + i*16)*132 + nc + j*16, acc[i][j],
                                        132, wmma::mem_row_major);
    }
    __syncthreads();

    // lite pass: m1 = relu(G + A[dst] + B[src]) -> bf16 hi/lo tiles
    {
        int e = tid >> 1, half = tid & 1;
        int srcA = ssrc[e];
        const float4* Brow = (const float4*)(g_B + (size_t)srcA*H);
        const float* sAd = sAv + (e>>5)*H;
#pragma unroll 4
        for (int i4 = 0; i4 < 16; ++i4) {
            int k0 = half*64 + i4*4;
            float4 bv = Brow[k0 >> 2];
            float4 gv = *(const float4*)(D + e*132 + k0);
            float x0 = fmaxf(gv.x + sAd[k0]   + bv.x, 0.f);
            float x1 = fmaxf(gv.y + sAd[k0+1] + bv.y, 0.f);
            float x2 = fmaxf(gv.z + sAd[k0+2] + bv.z, 0.f);
            float x3 = fmaxf(gv.w + sAd[k0+3] + bv.w, 0.f);
            __nv_bfloat16 h0 = __float2bfloat16(x0), h1 = __float2bfloat16(x1);
            __nv_bfloat16 h2 = __float2bfloat16(x2), h3 = __float2bfloat16(x3);
            __nv_bfloat16 l0 = __float2bfloat16(x0 - __bfloat162float(h0));
            __nv_bfloat16 l1 = __float2bfloat16(x1 - __bfloat162float(h1));
            __nv_bfloat16 l2 = __float2bfloat16(x2 - __bfloat162float(h2));
            __nv_bfloat16 l3 = __float2bfloat16(x3 - __bfloat162float(h3));
            unsigned hi01 = ((unsigned)__bfloat16_as_ushort(h1) << 16) | __bfloat16_as_ushort(h0);
            unsigned hi23 = ((unsigned)__bfloat16_as_ushort(h3) << 16) | __bfloat16_as_ushort(h2);
            unsigned lo01 = ((unsigned)__bfloat16_as_ushort(l1) << 16) | __bfloat16_as_ushort(l0);
            unsigned lo23 = ((unsigned)__bfloat16_as_ushort(l3) << 16) | __bfloat16_as_ushort(l2);
            unsigned boff = e*272 + k0*2;
            *(uint2*)((char*)sM1hi + boff) = make_uint2(hi01, hi23);
            *(uint2*)((char*)sM1lo + boff) = make_uint2(lo01, lo23);
        }
    }
    __syncthreads();

    // GEMM2: m = m1 @ W2  (k=128, 3 hi/lo products) -> D f32
    {
        int rg = wrp & 3, cgf = wrp >> 2;
        int er = rg*32, nc = cgf*64;
        wmma::fragment<wmma::accumulator,16,16,16,float> acc[2][4];
#pragma unroll
        for (int i = 0; i < 2; ++i)
#pragma unroll
            for (int j = 0; j < 4; ++j) wmma::fill_fragment(acc[i][j], 0.f);
#pragma unroll
        for (int k0 = 0; k0 < 128; k0 += 16) {
            wmma::fragment<wmma::matrix_a,16,16,16,__nv_bfloat16,wmma::row_major> ah[2], al[2];
            wmma::fragment<wmma::matrix_b,16,16,16,__nv_bfloat16,wmma::col_major> bh[4], bl[4];
#pragma unroll
            for (int i = 0; i < 2; ++i) {
                wmma::load_matrix_sync(ah[i], sM1hi + (er + i*16)*LDAB + k0, LDAB);
                wmma::load_matrix_sync(al[i], sM1lo + (er + i*16)*LDAB + k0, LDAB);
            }
#pragma unroll
            for (int j = 0; j < 4; ++j) {
                wmma::load_matrix_sync(bh[j], sBhi + (nc + j*16)*LDAB + k0, LDAB);
                wmma::load_matrix_sync(bl[j], sBlo + (nc + j*16)*LDAB + k0, LDAB);
            }
#pragma unroll
            for (int i = 0; i < 2; ++i)
#pragma unroll
                for (int j = 0; j < 4; ++j) {
                    wmma::mma_sync(acc[i][j], ah[i], bh[j], acc[i][j]);
                    wmma::mma_sync(acc[i][j], ah[i], bl[j], acc[i][j]);
                    wmma::mma_sync(acc[i][j], al[i], bh[j], acc[i][j]);
                }
        }
#pragma unroll
        for (int i = 0; i < 2; ++i)
#pragma unroll
            for (int j = 0; j < 4; ++j)
                wmma::store_matrix_sync(D + (er + i*16)*132 + nc + j*16, acc[i][j],
                                        132, wmma::mem_row_major);
    }
    __syncthreads();

    // epilogue stage 1: bias + relu + gate logits (2 threads per edge)
    {
        int e = tid >> 1, c0 = (tid & 1)*64;
        float p = 0.f;
#pragma unroll 8
        for (int c = 0; c < 64; ++c) {
            float v = D[e*132 + c0 + c] + sb2[c0 + c];
            v = fmaxf(v, 0.f);
            D[e*132 + c0 + c] = v;
            p += v * sinfw[c0 + c];
        }
        atomicAdd(&sgate[e], p);
    }
    __syncthreads();
    if (tid < 128) sgate[tid] = 1.f/(1.f + expf(-sgate[tid]));
    __syncthreads();

    // epilogue stage 2: mi[d][c] = sum_e m[e][c]*gate[e]
    {
        int c = tid & 127, hf = tid >> 7;
#pragma unroll
        for (int d = 0; d < 4; ++d) {
            float s = 0.f;
#pragma unroll 4
            for (int j = 0; j < 16; ++j) {
                int e = d*32 + hf*16 + j;
                s += D[e*132 + c] * sgate[e];
            }
            atomicAdd(&smi[d*H + c], s);
        }
    }
    __syncthreads();
    for (int i = tid; i < 4*H; i += 256) g_mi[(size_t)d0*H + i] = smi[i];
}

// ---------------- K6: node MLP + residual, 64-node tiles ---------------------
#define LDZ 68
#define NODE_SMEM (256*LDZ*4)
__global__ void __launch_bounds__(256) node_kernel(const float* __restrict__ nw1,
                                                   const float* __restrict__ nb1,
                                                   const float* __restrict__ nw2,
                                                   const float* __restrict__ nb2, int l)
{
    extern __shared__ float sZ[];   // [256 k][68]  ([mi | h] k-major; reused for u)
    int tid = threadIdx.x;
    int nb = blockIdx.x*64;
    for (int i = tid; i < 64*H; i += 256) {
        int nn = i>>7, k = i&127;
        sZ[k*LDZ + nn]     = g_mi[(size_t)(nb+nn)*H + k];
        sZ[(H+k)*LDZ + nn] = g_h [(size_t)(nb+nn)*H + k];
    }
    __syncthreads();
    int cg = tid & 15, ng = tid >> 4, col = cg*8;
    const ulonglong2* W1a = (const ulonglong2*)(nw1 + (size_t)l*2*H*H);
    const ulonglong2* W1b = W1a + H*H/4;
    unsigned long long acc[4][4];
#pragma unroll
    for (int c2 = 0; c2 < 4; ++c2) {
        unsigned long long b = pack2(nb1[l*H + col + 2*c2], nb1[l*H + col + 2*c2 + 1]);
#pragma unroll
        for (int r = 0; r < 4; ++r) acc[r][c2] = b;
    }
#pragma unroll 2
    for (int k = 0; k < H; ++k) {
        float4 am = *(const float4*)(sZ + k*LDZ + ng*4);
        float4 ah = *(const float4*)(sZ + (H+k)*LDZ + ng*4);
        ulonglong2 wa0 = __ldg(W1a + k*32 + cg*2);
        ulonglong2 wa1 = __ldg(W1a + k*32 + cg*2 + 1);
        ulonglong2 wb0 = __ldg(W1b + k*32 + cg*2);
        ulonglong2 wb1 = __ldg(W1b + k*32 + cg*2 + 1);
        unsigned long long mm[4] = {dup2(am.x), dup2(am.y), dup2(am.z), dup2(am.w)};
        unsigned long long hh[4] = {dup2(ah.x), dup2(ah.y), dup2(ah.z), dup2(ah.w)};
        unsigned long long wap[4] = {wa0.x, wa0.y, wa1.x, wa1.y};
        unsigned long long wbp[4] = {wb0.x, wb0.y, wb1.x, wb1.y};
#pragma unroll
        for (int r = 0; r < 4; ++r)
#pragma unroll
            for (int c2 = 0; c2 < 4; ++c2) {
                acc[r][c2] = fma2(mm[r], wap[c2], acc[r][c2]);
                acc[r][c2] = fma2(hh[r], wbp[c2], acc[r][c2]);
            }
    }
    __syncthreads();   // done reading sZ
#pragma unroll
    for (int r = 0; r < 4; ++r)
#pragma unroll
        for (int c2 = 0; c2 < 4; ++c2) {
            float lo, hi;
            unpack2(acc[r][c2], lo, hi);
            sZ[(col + 2*c2)*LDZ + ng*4 + r]     = fmaxf(lo, 0.f);
            sZ[(col + 2*c2 + 1)*LDZ + ng*4 + r] = fmaxf(hi, 0.f);
        }
    __syncthreads();
    const ulonglong2* W2 = (const ulonglong2*)(nw2 + (size_t)l*H*H);
    unsigned long long acc2[4][4];
#pragma unroll
    for (int c2 = 0; c2 < 4; ++c2) {
        unsigned long long b = pack2(nb2[l*H + col + 2*c2], nb2[l*H + col + 2*c2 + 1]);
#pragma unroll
        for (int r = 0; r < 4; ++r) acc2[r][c2] = b;
    }
#pragma unroll 4
    for (int k = 0; k < H; ++k) {
        float4 a = *(const float4*)(sZ + k*LDZ + ng*4);
        ulonglong2 w0 = __ldg(W2 + k*32 + cg*2);
        ulonglong2 w1 = __ldg(W2 + k*32 + cg*2 + 1);
        unsigned long long ad[4] = {dup2(a.x), dup2(a.y), dup2(a.z), dup2(a.w)};
        unsigned long long wp[4] = {w0.x, w0.y, w1.x, w1.y};
#pragma unroll
        for (int r = 0; r < 4; ++r)
#pragma unroll
            for (int c2 = 0; c2 < 4; ++c2) acc2[r][c2] = fma2(ad[r], wp[c2], acc2[r][c2]);
    }
#pragma unroll
    for (int r = 0; r < 4; ++r) {
        float v[8];
#pragma unroll
        for (int c2 = 0; c2 < 4; ++c2) unpack2(acc2[r][c2], v[2*c2], v[2*c2+1]);
        size_t o = (size_t)(nb + ng*4 + r)*H + col;
        float4* hp = (float4*)(g_h + o);
        float4 h0 = hp[0], h1 = hp[1];
        h0.x += v[0]; h0.y += v[1]; h0.z += v[2]; h0.w += v[3];
        h1.x += v[4]; h1.y += v[5]; h1.z += v[6]; h1.w += v[7];
        hp[0] = h0; hp[1] = h1;
    }
}

// ---------------- K7/K8 ------------------------------------------------------
__global__ void pool_kernel(int n)
{
    int b = blockIdx.x >> 4, s = blockIdx.x & 15;
    int c = threadIdx.x;
    float acc = 0.f;
    for (int i = s; i < n; i += 16) acc += g_h[((size_t)b*n + i)*H + c];
    atomicAdd(&g_pre[b*H + c], acc);
}

__global__ void out_kernel(const float* __restrict__ w1, const float* __restrict__ b1,
                           const float* __restrict__ w2, const float* __restrict__ b2,
                           const int* __restrict__ kind, float* __restrict__ out, int B)
{
    __shared__ float sU[H]; __shared__ float so[3];
    int t = threadIdx.x;
    for (int b = 0; b < B; ++b) {
        float x = b1[t];
        for (int k = 0; k < H; ++k) x += g_pre[b*H + k]*w1[k*H + t];
        float sp = (x > 0.f) ? x + log1pf(expf(-x)) : log1pf(expf(x));
        sU[t] = sp - 0.6931471805599453f;
        __syncthreads();
        if (t < 3) { float s = b2[t]; for (int k = 0; k < H; ++k) s += sU[k]*w2[k*3 + t]; so[t] = s; }
        __syncthreads();
        if (t == 0) out[b] = so[kind[b] - 1];
        __syncthreads();
    }
}

// ---------------- host ------------------------------------------------------
extern "C" void kernel_launch(void* const* d_in, const int* in_sizes, int n_in,
                              void* d_out, int out_size)
{
    const float* protein_pos  = (const float*)d_in[0];
    const float* protein_feat = (const float*)d_in[1];
    const float* ligand_pos   = (const float*)d_in[2];
    const float* ligand_feat  = (const float*)d_in[3];
    const int*   output_kind  = (const int*)d_in[6];
    const float* prot_w = (const float*)d_in[7];  const float* prot_b = (const float*)d_in[8];
    const float* lig_w  = (const float*)d_in[9];  const float* lig_b  = (const float*)d_in[10];
    const float* edge_w1 = (const float*)d_in[11]; const float* edge_b1 = (const float*)d_in[12];
    const float* edge_w2 = (const float*)d_in[13]; const float* edge_b2 = (const float*)d_in[14];
    const float* inf_w   = (const float*)d_in[15]; const float* inf_b   = (const float*)d_in[16];
    const float* node_w1 = (const float*)d_in[17]; const float* node_b1 = (const float*)d_in[18];
    const float* node_w2 = (const float*)d_in[19]; const float* node_b2 = (const float*)d_in[20];
    const float* out_w1  = (const float*)d_in[21]; const float* out_b1  = (const float*)d_in[22];
    const float* out_w2  = (const float*)d_in[23]; const float* out_b2  = (const float*)d_in[24];
    float* out = (float*)d_out;

    int Np = in_sizes[0]/3, Nl = in_sizes[2]/3;
    int B  = in_sizes[6];
    int Fp = in_sizes[1]/Np, Fl = in_sizes[3]/Nl;
    int n_prot = Np/B, n_lig = Nl/B;
    int n = n_prot + n_lig;
    int N = Np + Nl;
    int E = N*KNN;

    cudaFuncSetAttribute(edge_kernel, cudaFuncAttributeMaxDynamicSharedMemorySize, EDGE_SMEM);
    cudaFuncSetAttribute(node_kernel, cudaFuncAttributeMaxDynamicSharedMemorySize, NODE_SMEM);

    embed_kernel<<<N, 128>>>(protein_pos, protein_feat, ligand_pos, ligand_feat,
                             prot_w, prot_b, lig_w, lig_b, n_prot, n_lig, n, Fp, Fl);

    knn_kernel<<<dim3((n + 127)/128, B), 128, n*(int)sizeof(float4)>>>(n);

    w2prep_kernel<<<3*128, 128>>>(edge_w2, edge_w1);

    float step  = 10.0f/19.0f;
    float coeff = -0.5f/(step*step);
    attr_kernel<<<(E + 255)/256, 256>>>(E, step, coeff);

    ab_kernel<<<N/32, 256>>>(edge_w1, edge_b1, 0);
    for (int l = 0; l < 3; ++l) {
        edge_kernel<<<E/128, 256, EDGE_SMEM>>>(edge_b2, inf_w, inf_b, l);
        node_kernel<<<N/64, 256, NODE_SMEM>>>(node_w1, node_b1, node_w2, node_b2, l);
        if (l < 2) ab_kernel<<<N/32, 256>>>(edge_w1, edge_b1, l + 1);
    }

    pool_kernel<<<B*16, 128>>>(n);
    out_kernel<<<1, 128>>>(out_w1, out_b1, out_w2, out_b2, output_kind, out, B);
}

// round 13
// speedup vs baseline: 1.5047x; 1.0628x over previous
#include <cuda_runtime.h>
#include <cuda_bf16.h>
#include <mma.h>
#include <math.h>

#define H   128
#define GG  20
#define KNN 32
#define MAXN 24000
#define MAXE (MAXN*KNN)

using namespace nvcuda;

// ---------------- f32x2 packed helpers --------------------------------------
__device__ __forceinline__ unsigned long long pack2(float lo, float hi) {
    unsigned long long r;
    asm("mov.b64 %0, {%1, %2};" : "=l"(r) : "f"(lo), "f"(hi));
    return r;
}
__device__ __forceinline__ unsigned long long dup2(float v) {
    unsigned long long r;
    asm("mov.b64 %0, {%1, %1};" : "=l"(r) : "f"(v));
    return r;
}
__device__ __forceinline__ void unpack2(unsigned long long p, float& lo, float& hi) {
    asm("mov.b64 {%0, %1}, %2;" : "=f"(lo), "=f"(hi) : "l"(p));
}
__device__ __forceinline__ unsigned long long fma2(unsigned long long a, unsigned long long b, unsigned long long c) {
    unsigned long long d;
    asm("fma.rn.f32x2 %0, %1, %2, %3;" : "=l"(d) : "l"(a), "l"(b), "l"(c));
    return d;
}
__device__ __forceinline__ unsigned long long add2(unsigned long long a, unsigned long long b) {
    unsigned long long d;
    asm("add.rn.f32x2 %0, %1, %2;" : "=l"(d) : "l"(a), "l"(b));
    return d;
}
__device__ __forceinline__ unsigned smem_u32(const void* p) {
    unsigned a;
    asm("{ .reg .u64 t; cvta.to.shared.u64 t, %1; cvt.u32.u64 %0, t; }" : "=r"(a) : "l"(p));
    return a;
}
__device__ __forceinline__ void cp16(unsigned dst, const void* src) {
    asm volatile("cp.async.cg.shared.global [%0], [%1], 16;" :: "r"(dst), "l"(src) : "memory");
}

// ---------------- scratch ----------------------------------------------------
__device__ __align__(16) float g_pos[MAXN*3];
__device__ __align__(16) float g_h  [MAXN*H];
__device__ __align__(16) float g_A  [MAXN*H];
__device__ __align__(16) float g_B  [MAXN*H];
__device__ __align__(16) float g_mi [MAXN*H];
__device__ int   g_nbr[MAXE];
__device__ float g_attr[(size_t)MAXE*GG];
__device__ float g_pre[16*H];
// baked W2^T as bf16 hi/lo: [layer][hi/lo][n=128][k=128]
__device__ __align__(16) unsigned short g_w2bf[3*2*16384];
// baked W1e as bf16 hi/lo col-major: [layer][hi/lo][n=128][kpad=32]
__device__ __align__(16) unsigned short g_w1ebf[3*2*4096];
// baked [W1i|W1j] augmented (k=128 row = bias) bf16 hi/lo: [l][p][n=256][k=144]
__device__ __align__(16) unsigned short g_w1ab[3*2*256*144];

// ---------------- K1: embeddings --------------------------------------------
__global__ void embed_kernel(const float* __restrict__ ppos, const float* __restrict__ pfeat,
                             const float* __restrict__ lpos, const float* __restrict__ lfeat,
                             const float* __restrict__ pw, const float* __restrict__ pb,
                             const float* __restrict__ lw, const float* __restrict__ lb,
                             int n_prot, int n_lig, int n, int Fp, int Fl)
{
    __shared__ float sf[32];
    int i = blockIdx.x, t = threadIdx.x;
    int b = i / n, j = i - b * n;
    const float *feat, *w, *bias, *pos; int F;
    if (j < n_prot) { int r = b*n_prot + j;            feat = pfeat + (size_t)r*Fp; w = pw; bias = pb; pos = ppos + (size_t)r*3; F = Fp; }
    else            { int r = b*n_lig  + (j - n_prot); feat = lfeat + (size_t)r*Fl; w = lw; bias = lb; pos = lpos + (size_t)r*3; F = Fl; }
    if (t < F) sf[t] = feat[t];
    __syncthreads();
    float acc = bias[t];
    for (int f = 0; f < F; ++f) acc += sf[f] * w[f*H + t];
    g_h[(size_t)i*H + t] = acc;
    if (t < 3) g_pos[i*3 + t] = pos[t];
}

// ---------------- K2: kNN ----------------------------------------------------
__global__ void knn_kernel(int n)
{
    extern __shared__ float4 spos4[];
    int b = blockIdx.y, tid = threadIdx.x;
    const float* gp = g_pos + (size_t)b*n*3;
    for (int i = tid; i < n; i += blockDim.x)
        spos4[i] = make_float4(gp[i*3], gp[i*3+1], gp[i*3+2], 0.f);
    __syncthreads();
    int c = blockIdx.x*blockDim.x + tid;
    if (c >= n) return;
    float4 pc = spos4[c];
    float bd[KNN]; int bi[KNN];
#pragma unroll
    for (int s = 0; s < KNN; ++s) { bd[s] = 3.402823466e38f; bi[s] = 0x7fffffff; }
    float wd = 3.402823466e38f; int wi = 0x7fffffff; int ws = 0;
    for (int j = 0; j < n; ++j) {
        if (j == c) continue;
        float4 pj = spos4[j];
        float dx = pc.x - pj.x, dy = pc.y - pj.y, dz = pc.z - pj.z;
        float d2 = dx*dx + dy*dy + dz*dz;
        if (d2 < wd || (d2 == wd && j < wi)) {
            bd[ws] = d2; bi[ws] = j;
            wd = bd[0]; wi = bi[0]; ws = 0;
#pragma unroll
            for (int s = 1; s < KNN; ++s)
                if (bd[s] > wd || (bd[s] == wd && bi[s] > wi)) { wd = bd[s]; wi = bi[s]; ws = s; }
        }
    }
    size_t base = ((size_t)(b*n + c))*KNN;
#pragma unroll
    for (int s = 0; s < KNN; ++s) g_nbr[base + s] = b*n + bi[s];
}

// ---------------- K3: Gaussian smearing + zero g_pre ------------------------
__global__ void attr_kernel(int E, float step, float coeff)
{
    int e = blockIdx.x*blockDim.x + threadIdx.x;
    if (e >= E) return;
    if (e < 16*H) g_pre[e] = 0.f;
    int dst = e >> 5;
    int src = g_nbr[e];
    float dx = g_pos[dst*3]   - g_pos[src*3];
    float dy = g_pos[dst*3+1] - g_pos[src*3+1];
    float dz = g_pos[dst*3+2] - g_pos[src*3+2];
    float d = sqrtf(dx*dx + dy*dy + dz*dz);
    size_t o = (size_t)e*GG;
#pragma unroll
    for (int g = 0; g < GG; ++g) {
        float t = d - g*step;
        g_attr[o + g] = expf(coeff*t*t);
    }
}

// ---------------- K3b: bake W2^T and W1e bf16 hi/lo --------------------------
__global__ void w2prep_kernel(const float* __restrict__ edge_w2,
                              const float* __restrict__ edge_w1)
{
    int l = blockIdx.x >> 7, nr = blockIdx.x & 127, k = threadIdx.x;
    float v = edge_w2[((size_t)l*H + k)*H + nr];
    __nv_bfloat16 hb = __float2bfloat16(v);
    float r = v - __bfloat162float(hb);
    __nv_bfloat16 lb = __float2bfloat16(r);
    g_w2bf[(l*2+0)*16384 + nr*128 + k] = __bfloat16_as_ushort(hb);
    g_w2bf[(l*2+1)*16384 + nr*128 + k] = __bfloat16_as_ushort(lb);
    if (k < 32) {
        float w = (k < GG) ? edge_w1[(size_t)l*276*H + k*H + nr] : 0.f;
        __nv_bfloat16 wh = __float2bfloat16(w);
        float wr = w - __bfloat162float(wh);
        __nv_bfloat16 wl = __float2bfloat16(wr);
        g_w1ebf[(l*2+0)*4096 + nr*32 + k] = __bfloat16_as_ushort(wh);
        g_w1ebf[(l*2+1)*4096 + nr*32 + k] = __bfloat16_as_ushort(wl);
    }
}

// ---------------- K3c: bake augmented [W1i|W1j] (+bias row) ------------------
__global__ void w1abprep_kernel(const float* __restrict__ edge_w1,
                                const float* __restrict__ edge_b1)
{
    int l = blockIdx.x >> 8, n = blockIdx.x & 255, k = threadIdx.x;  // k 0..143
    float v = 0.f;
    if (k < 128) {
        v = (n < 128) ? edge_w1[(size_t)l*276*H + (GG+k)*H + n]
                      : edge_w1[(size_t)l*276*H + (GG+128+k)*H + (n-128)];
    } else if (k == 128 && n < 128) {
        v = edge_b1[l*H + n];
    }
    __nv_bfloat16 hb = __float2bfloat16(v);
    float r = v - __bfloat162float(hb);
    __nv_bfloat16 lb = __float2bfloat16(r);
    g_w1ab[((size_t)(l*2+0)*256 + n)*144 + k] = __bfloat16_as_ushort(hb);
    g_w1ab[((size_t)(l*2+1)*256 + n)*144 + k] = __bfloat16_as_ushort(lb);
}

// ---------------- K4: A|B via WMMA (bias folded into k=128) ------------------
#define ABK 144
#define LDH 152
__global__ void __launch_bounds__(256) ab_kernel(int l)
{
    __shared__ __align__(16) __nv_bfloat16 sHhi[64*LDH];
    __shared__ __align__(16) __nv_bfloat16 sHlo[64*LDH];
    int tid = threadIdx.x;
    int nb = blockIdx.x*64;
    // stage h hi/lo (k 0..127)
    for (int i = tid; i < 2048; i += 256) {
        int row = i >> 5, k4 = (i & 31)*4;
        float4 hv = *(const float4*)(g_h + (size_t)(nb+row)*H + k4);
        float x[4] = {hv.x, hv.y, hv.z, hv.w};
#pragma unroll
        for (int q = 0; q < 4; ++q) {
            __nv_bfloat16 hb = __float2bfloat16(x[q]);
            sHhi[row*LDH + k4 + q] = hb;
            sHlo[row*LDH + k4 + q] = __float2bfloat16(x[q] - __bfloat162float(hb));
        }
    }
    // aug region k 128..151 (1.0 at k=128, else 0; pad zeroed)
    for (int i = tid; i < 64*24; i += 256) {
        int row = i / 24, k = 128 + (i % 24);
        __nv_bfloat16 hv = (k == 128) ? __float2bfloat16(1.0f) : __float2bfloat16(0.0f);
        sHhi[row*LDH + k] = hv;
        sHlo[row*LDH + k] = __float2bfloat16(0.0f);
    }
    __syncthreads();

    int wrp = tid >> 5;
    int rowg = wrp >> 2, colg = wrp & 3;
    int er = rowg*32, nc = colg*64;
    const __nv_bfloat16* Wh = (const __nv_bfloat16*)g_w1ab + (size_t)(l*2+0)*256*144;
    const __nv_bfloat16* Wl = (const __nv_bfloat16*)g_w1ab + (size_t)(l*2+1)*256*144;

    wmma::fragment<wmma::accumulator,16,16,16,float> acc[2][4];
#pragma unroll
    for (int i = 0; i < 2; ++i)
#pragma unroll
        for (int j = 0; j < 4; ++j) wmma::fill_fragment(acc[i][j], 0.f);

#pragma unroll
    for (int k0 = 0; k0 < ABK; k0 += 16) {
        wmma::fragment<wmma::matrix_a,16,16,16,__nv_bfloat16,wmma::row_major> ah[2], al[2];
#pragma unroll
        for (int i = 0; i < 2; ++i) {
            wmma::load_matrix_sync(ah[i], sHhi + (er + i*16)*LDH + k0, LDH);
            wmma::load_matrix_sync(al[i], sHlo + (er + i*16)*LDH + k0, LDH);
        }
#pragma unroll
        for (int j = 0; j < 4; ++j) {
            wmma::fragment<wmma::matrix_b,16,16,16,__nv_bfloat16,wmma::col_major> bh, bl;
            wmma::load_matrix_sync(bh, Wh + (size_t)(nc + j*16)*144 + k0, 144);
            wmma::load_matrix_sync(bl, Wl + (size_t)(nc + j*16)*144 + k0, 144);
#pragma unroll
            for (int i = 0; i < 2; ++i) {
                wmma::mma_sync(acc[i][j], ah[i], bh, acc[i][j]);
                wmma::mma_sync(acc[i][j], ah[i], bl, acc[i][j]);
                wmma::mma_sync(acc[i][j], al[i], bh, acc[i][j]);
            }
        }
    }
    // store direct to global: cols 0..127 -> g_A, 128..255 -> g_B
#pragma unroll
    for (int i = 0; i < 2; ++i)
#pragma unroll
        for (int j = 0; j < 4; ++j) {
            int c = nc + j*16;
            float* dstp = (c < 128) ? (g_A + (size_t)(nb + er + i*16)*H + c)
                                    : (g_B + (size_t)(nb + er + i*16)*H + (c - 128));
            wmma::store_matrix_sync(dstp, acc[i][j], H, wmma::mem_row_major);
        }
}

// ---------------- K5: edge MLP, both GEMMs on WMMA + cp.async W2 -------------
#define D_OFF     0
#define B_HI_OFF  67584
#define B_LO_OFF  102400
#define M1_HI_OFF 137216
#define M1_LO_OFF 172032
#define ATTRH_OFF 137216
#define ATTRL_OFF 147456
#define W1EH_OFF  157696
#define W1EL_OFF  167936
#define SA_OFF    206848
#define SB2_OFF   208896
#define SINFW_OFF 209408
#define SGATE_OFF 209920
#define SMI_OFF   210432
#define SSRC_OFF  212480
#define EDGE_SMEM 212992
#define LDAB  136
#define LDATT 40

__global__ void __launch_bounds__(256,1) edge_kernel(const float* __restrict__ edge_b2,
                                                     const float* __restrict__ inf_w,
                                                     const float* __restrict__ inf_b, int l)
{
    extern __shared__ __align__(16) char sh[];
    float* D = (float*)(sh + D_OFF);                    // [128][132] f32
    __nv_bfloat16* sBhi = (__nv_bfloat16*)(sh + B_HI_OFF);
    __nv_bfloat16* sBlo = (__nv_bfloat16*)(sh + B_LO_OFF);
    __nv_bfloat16* sM1hi = (__nv_bfloat16*)(sh + M1_HI_OFF);
    __nv_bfloat16* sM1lo = (__nv_bfloat16*)(sh + M1_LO_OFF);
    __nv_bfloat16* sAtH = (__nv_bfloat16*)(sh + ATTRH_OFF);
    __nv_bfloat16* sAtL = (__nv_bfloat16*)(sh + ATTRL_OFF);
    __nv_bfloat16* sWeH = (__nv_bfloat16*)(sh + W1EH_OFF);
    __nv_bfloat16* sWeL = (__nv_bfloat16*)(sh + W1EL_OFF);
    float* sAv   = (float*)(sh + SA_OFF);
    float* sb2   = (float*)(sh + SB2_OFF);
    float* sinfw = (float*)(sh + SINFW_OFF);
    float* sgate = (float*)(sh + SGATE_OFF);
    float* smi   = (float*)(sh + SMI_OFF);
    int*   ssrc  = (int*)(sh + SSRC_OFF);

    int tid = threadIdx.x;
    int wrp = tid >> 5;
    int e0 = blockIdx.x * 128;
    int d0 = e0 >> 5;
    unsigned sbase = smem_u32(sh);

    // async-stage W2^T hi/lo (row-padded to 272B); waited before GEMM2
    {
        const uint4* gh = (const uint4*)(g_w2bf + (size_t)(l*2+0)*16384);
        const uint4* gl = (const uint4*)(g_w2bf + (size_t)(l*2+1)*16384);
        for (int i = tid; i < 2048; i += 256) {
            int row = i >> 4, q = i & 15;
            cp16(sbase + B_HI_OFF + row*272 + q*16, gh + row*16 + q);
            cp16(sbase + B_LO_OFF + row*272 + q*16, gl + row*16 + q);
        }
        asm volatile("cp.async.commit_group;" ::: "memory");
    }
    // stage W1e hi/lo (gmem ld=32 -> smem ld=40)
    {
        const char* gwh = (const char*)(g_w1ebf + (size_t)(l*2+0)*4096);
        const char* gwl = (const char*)(g_w1ebf + (size_t)(l*2+1)*4096);
        for (int i = tid; i < 2048; i += 256) {
            int nr = i >> 4, k2 = i & 15;
            *(unsigned*)((char*)sWeH + nr*80 + k2*4) = *(const unsigned*)(gwh + nr*64 + k2*4);
            *(unsigned*)((char*)sWeL + nr*80 + k2*4) = *(const unsigned*)(gwl + nr*64 + k2*4);
        }
    }
    // convert attr -> bf16 hi/lo tiles [e][kpad=32], ld=40
    for (int i = tid; i < 2048; i += 256) {
        int el = i >> 4, k2 = i & 15;
        int k = k2*2;
        float f0 = (k   < GG) ? g_attr[(size_t)(e0+el)*GG + k]     : 0.f;
        float f1 = (k+1 < GG) ? g_attr[(size_t)(e0+el)*GG + k + 1] : 0.f;
        __nv_bfloat16 h0 = __float2bfloat16(f0), h1 = __float2bfloat16(f1);
        __nv_bfloat16 l0 = __float2bfloat16(f0 - __bfloat162float(h0));
        __nv_bfloat16 l1 = __float2bfloat16(f1 - __bfloat162float(h1));
        *(unsigned*)((char*)sAtH + el*80 + k2*4) =
            ((unsigned)__bfloat16_as_ushort(h1) << 16) | __bfloat16_as_ushort(h0);
        *(unsigned*)((char*)sAtL + el*80 + k2*4) =
            ((unsigned)__bfloat16_as_ushort(l1) << 16) | __bfloat16_as_ushort(l0);
    }
    for (int i = tid; i < 4*H; i += 256) { sAv[i] = g_A[(size_t)d0*H + i]; smi[i] = 0.f; }
    if (tid < H) { sb2[tid] = edge_b2[l*H+tid]; sinfw[tid] = inf_w[l*H+tid]; sgate[tid] = inf_b[l]; }
    if (tid < 128) ssrc[tid] = g_nbr[e0 + tid];
    __syncthreads();

    // GEMM1: G = attr @ W1e  (k=32, 3 hi/lo products) -> D f32
    {
        int rg = wrp & 3, cgf = wrp >> 2;
        int er = rg*32, nc = cgf*64;
        wmma::fragment<wmma::accumulator,16,16,16,float> acc[2][4];
#pragma unroll
        for (int i = 0; i < 2; ++i)
#pragma unroll
            for (int j = 0; j < 4; ++j) wmma::fill_fragment(acc[i][j], 0.f);
#pragma unroll
        for (int k0 = 0; k0 < 32; k0 += 16) {
            wmma::fragment<wmma::matrix_a,16,16,16,__nv_bfloat16,wmma::row_major> ah[2], al[2];
            wmma::fragment<wmma::matrix_b,16,16,16,__nv_bfloat16,wmma::col_major> bh[4], bl[4];
#pragma unroll
            for (int i = 0; i < 2; ++i) {
                wmma::load_matrix_sync(ah[i], sAtH + (er + i*16)*LDATT + k0, LDATT);
                wmma::load_matrix_sync(al[i], sAtL + (er + i*16)*LDATT + k0, LDATT);
            }
#pragma unroll
            for (int j = 0; j < 4; ++j) {
                wmma::load_matrix_sync(bh[j], sWeH + (nc + j*16)*LDATT + k0, LDATT);
                wmma::load_matrix_sync(bl[j], sWeL + (nc + j*16)*LDATT + k0, LDATT);
            }
#pragma unroll
            for (int i = 0; i < 2; ++i)
#pragma unroll
                for (int j = 0; j < 4; ++j) {
                    wmma::mma_sync(acc[i][j], ah[i], bh[j], acc[i][j]);
                    wmma::mma_sync(acc[i][j], ah[i], bl[j], acc[i][j]);
                    wmma::mma_sync(acc[i][j], al[i], bh[j], acc[i][j]);
                }
        }
#pragma unroll
        for (int i = 0; i < 2; ++i)
#pragma unroll
            for (int j = 0; j < 4; ++j)
                wmma::store_matrix_sync(D + (er + i*16)*132 + nc + j*16, acc[i][j],
                                        132, wmma::mem_row_major);
    }
    __syncthreads();

    // lite pass: m1 = relu(G + A[dst] + B[src]) -> bf16 hi/lo tiles
    {
        int e = tid >> 1, half = tid & 1;
        int srcA = ssrc[e];
        const float4* Brow = (const float4*)(g_B + (size_t)srcA*H);
        const float* sAd = sAv + (e>>5)*H;
#pragma unroll 4
        for (int i4 = 0; i4 < 16; ++i4) {
            int k0 = half*64 + i4*4;
            float4 bv = Brow[k0 >> 2];
            float4 gv = *(const float4*)(D + e*132 + k0);
            float x0 = fmaxf(gv.x + sAd[k0]   + bv.x, 0.f);
            float x1 = fmaxf(gv.y + sAd[k0+1] + bv.y, 0.f);
            float x2 = fmaxf(gv.z + sAd[k0+2] + bv.z, 0.f);
            float x3 = fmaxf(gv.w + sAd[k0+3] + bv.w, 0.f);
            __nv_bfloat16 h0 = __float2bfloat16(x0), h1 = __float2bfloat16(x1);
            __nv_bfloat16 h2 = __float2bfloat16(x2), h3 = __float2bfloat16(x3);
            __nv_bfloat16 l0 = __float2bfloat16(x0 - __bfloat162float(h0));
            __nv_bfloat16 l1 = __float2bfloat16(x1 - __bfloat162float(h1));
            __nv_bfloat16 l2 = __float2bfloat16(x2 - __bfloat162float(h2));
            __nv_bfloat16 l3 = __float2bfloat16(x3 - __bfloat162float(h3));
            unsigned hi01 = ((unsigned)__bfloat16_as_ushort(h1) << 16) | __bfloat16_as_ushort(h0);
            unsigned hi23 = ((unsigned)__bfloat16_as_ushort(h3) << 16) | __bfloat16_as_ushort(h2);
            unsigned lo01 = ((unsigned)__bfloat16_as_ushort(l1) << 16) | __bfloat16_as_ushort(l0);
            unsigned lo23 = ((unsigned)__bfloat16_as_ushort(l3) << 16) | __bfloat16_as_ushort(l2);
            unsigned boff = e*272 + k0*2;
            *(uint2*)((char*)sM1hi + boff) = make_uint2(hi01, hi23);
            *(uint2*)((char*)sM1lo + boff) = make_uint2(lo01, lo23);
        }
    }
    asm volatile("cp.async.wait_group 0;" ::: "memory");
    __syncthreads();

    // GEMM2: m = m1 @ W2  (k=128, 3 hi/lo products) -> D f32
    {
        int rg = wrp & 3, cgf = wrp >> 2;
        int er = rg*32, nc = cgf*64;
        wmma::fragment<wmma::accumulator,16,16,16,float> acc[2][4];
#pragma unroll
        for (int i = 0; i < 2; ++i)
#pragma unroll
            for (int j = 0; j < 4; ++j) wmma::fill_fragment(acc[i][j], 0.f);
#pragma unroll
        for (int k0 = 0; k0 < 128; k0 += 16) {
            wmma::fragment<wmma::matrix_a,16,16,16,__nv_bfloat16,wmma::row_major> ah[2], al[2];
            wmma::fragment<wmma::matrix_b,16,16,16,__nv_bfloat16,wmma::col_major> bh[4], bl[4];
#pragma unroll
            for (int i = 0; i < 2; ++i) {
                wmma::load_matrix_sync(ah[i], sM1hi + (er + i*16)*LDAB + k0, LDAB);
                wmma::load_matrix_sync(al[i], sM1lo + (er + i*16)*LDAB + k0, LDAB);
            }
#pragma unroll
            for (int j = 0; j < 4; ++j) {
                wmma::load_matrix_sync(bh[j], sBhi + (nc + j*16)*LDAB + k0, LDAB);
                wmma::load_matrix_sync(bl[j], sBlo + (nc + j*16)*LDAB + k0, LDAB);
            }
#pragma unroll
            for (int i = 0; i < 2; ++i)
#pragma unroll
                for (int j = 0; j < 4; ++j) {
                    wmma::mma_sync(acc[i][j], ah[i], bh[j], acc[i][j]);
                    wmma::mma_sync(acc[i][j], ah[i], bl[j], acc[i][j]);
                    wmma::mma_sync(acc[i][j], al[i], bh[j], acc[i][j]);
                }
        }
#pragma unroll
        for (int i = 0; i < 2; ++i)
#pragma unroll
            for (int j = 0; j < 4; ++j)
                wmma::store_matrix_sync(D + (er + i*16)*132 + nc + j*16, acc[i][j],
                                        132, wmma::mem_row_major);
    }
    __syncthreads();

    // epilogue stage 1: bias + relu + gate logits (2 threads per edge)
    {
        int e = tid >> 1, c0 = (tid & 1)*64;
        float p = 0.f;
#pragma unroll 8
        for (int c = 0; c < 64; ++c) {
            float v = D[e*132 + c0 + c] + sb2[c0 + c];
            v = fmaxf(v, 0.f);
            D[e*132 + c0 + c] = v;
            p += v * sinfw[c0 + c];
        }
        atomicAdd(&sgate[e], p);
    }
    __syncthreads();
    if (tid < 128) sgate[tid] = 1.f/(1.f + expf(-sgate[tid]));
    __syncthreads();

    // epilogue stage 2: mi[d][c] = sum_e m[e][c]*gate[e]
    {
        int c = tid & 127, hf = tid >> 7;
#pragma unroll
        for (int d = 0; d < 4; ++d) {
            float s = 0.f;
#pragma unroll 4
            for (int j = 0; j < 16; ++j) {
                int e = d*32 + hf*16 + j;
                s += D[e*132 + c] * sgate[e];
            }
            atomicAdd(&smi[d*H + c], s);
        }
    }
    __syncthreads();
    for (int i = tid; i < 4*H; i += 256) g_mi[(size_t)d0*H + i] = smi[i];
}

// ---------------- K6: node MLP + residual, 64-node tiles ---------------------
#define LDZ 68
#define NODE_SMEM (256*LDZ*4)
__global__ void __launch_bounds__(256) node_kernel(const float* __restrict__ nw1,
                                                   const float* __restrict__ nb1,
                                                   const float* __restrict__ nw2,
                                                   const float* __restrict__ nb2, int l)
{
    extern __shared__ float sZ[];   // [256 k][68]  ([mi | h] k-major; reused for u)
    int tid = threadIdx.x;
    int nb = blockIdx.x*64;
    for (int i = tid; i < 64*H; i += 256) {
        int nn = i>>7, k = i&127;
        sZ[k*LDZ + nn]     = g_mi[(size_t)(nb+nn)*H + k];
        sZ[(H+k)*LDZ + nn] = g_h [(size_t)(nb+nn)*H + k];
    }
    __syncthreads();
    int cg = tid & 15, ng = tid >> 4, col = cg*8;
    const ulonglong2* W1a = (const ulonglong2*)(nw1 + (size_t)l*2*H*H);
    const ulonglong2* W1b = W1a + H*H/4;
    unsigned long long acc[4][4];
#pragma unroll
    for (int c2 = 0; c2 < 4; ++c2) {
        unsigned long long b = pack2(nb1[l*H + col + 2*c2], nb1[l*H + col + 2*c2 + 1]);
#pragma unroll
        for (int r = 0; r < 4; ++r) acc[r][c2] = b;
    }
#pragma unroll 2
    for (int k = 0; k < H; ++k) {
        float4 am = *(const float4*)(sZ + k*LDZ + ng*4);
        float4 ah = *(const float4*)(sZ + (H+k)*LDZ + ng*4);
        ulonglong2 wa0 = __ldg(W1a + k*32 + cg*2);
        ulonglong2 wa1 = __ldg(W1a + k*32 + cg*2 + 1);
        ulonglong2 wb0 = __ldg(W1b + k*32 + cg*2);
        ulonglong2 wb1 = __ldg(W1b + k*32 + cg*2 + 1);
        unsigned long long mm[4] = {dup2(am.x), dup2(am.y), dup2(am.z), dup2(am.w)};
        unsigned long long hh[4] = {dup2(ah.x), dup2(ah.y), dup2(ah.z), dup2(ah.w)};
        unsigned long long wap[4] = {wa0.x, wa0.y, wa1.x, wa1.y};
        unsigned long long wbp[4] = {wb0.x, wb0.y, wb1.x, wb1.y};
#pragma unroll
        for (int r = 0; r < 4; ++r)
#pragma unroll
            for (int c2 = 0; c2 < 4; ++c2) {
                acc[r][c2] = fma2(mm[r], wap[c2], acc[r][c2]);
                acc[r][c2] = fma2(hh[r], wbp[c2], acc[r][c2]);
            }
    }
    __syncthreads();   // done reading sZ
#pragma unroll
    for (int r = 0; r < 4; ++r)
#pragma unroll
        for (int c2 = 0; c2 < 4; ++c2) {
            float lo, hi;
            unpack2(acc[r][c2], lo, hi);
            sZ[(col + 2*c2)*LDZ + ng*4 + r]     = fmaxf(lo, 0.f);
            sZ[(col + 2*c2 + 1)*LDZ + ng*4 + r] = fmaxf(hi, 0.f);
        }
    __syncthreads();
    const ulonglong2* W2 = (const ulonglong2*)(nw2 + (size_t)l*H*H);
    unsigned long long acc2[4][4];
#pragma unroll
    for (int c2 = 0; c2 < 4; ++c2) {
        unsigned long long b = pack2(nb2[l*H + col + 2*c2], nb2[l*H + col + 2*c2 + 1]);
#pragma unroll
        for (int r = 0; r < 4; ++r) acc2[r][c2] = b;
    }
#pragma unroll 4
    for (int k = 0; k < H; ++k) {
        float4 a = *(const float4*)(sZ + k*LDZ + ng*4);
        ulonglong2 w0 = __ldg(W2 + k*32 + cg*2);
        ulonglong2 w1 = __ldg(W2 + k*32 + cg*2 + 1);
        unsigned long long ad[4] = {dup2(a.x), dup2(a.y), dup2(a.z), dup2(a.w)};
        unsigned long long wp[4] = {w0.x, w0.y, w1.x, w1.y};
#pragma unroll
        for (int r = 0; r < 4; ++r)
#pragma unroll
            for (int c2 = 0; c2 < 4; ++c2) acc2[r][c2] = fma2(ad[r], wp[c2], acc2[r][c2]);
    }
#pragma unroll
    for (int r = 0; r < 4; ++r) {
        float v[8];
#pragma unroll
        for (int c2 = 0; c2 < 4; ++c2) unpack2(acc2[r][c2], v[2*c2], v[2*c2+1]);
        size_t o = (size_t)(nb + ng*4 + r)*H + col;
        float4* hp = (float4*)(g_h + o);
        float4 h0 = hp[0], h1 = hp[1];
        h0.x += v[0]; h0.y += v[1]; h0.z += v[2]; h0.w += v[3];
        h1.x += v[4]; h1.y += v[5]; h1.z += v[6]; h1.w += v[7];
        hp[0] = h0; hp[1] = h1;
    }
}

// ---------------- K7/K8 ------------------------------------------------------
__global__ void pool_kernel(int n)
{
    int b = blockIdx.x >> 4, s = blockIdx.x & 15;
    int c = threadIdx.x;
    float acc = 0.f;
    for (int i = s; i < n; i += 16) acc += g_h[((size_t)b*n + i)*H + c];
    atomicAdd(&g_pre[b*H + c], acc);
}

__global__ void out_kernel(const float* __restrict__ w1, const float* __restrict__ b1,
                           const float* __restrict__ w2, const float* __restrict__ b2,
                           const int* __restrict__ kind, float* __restrict__ out, int B)
{
    __shared__ float sU[H]; __shared__ float so[3];
    int t = threadIdx.x;
    for (int b = 0; b < B; ++b) {
        float x = b1[t];
        for (int k = 0; k < H; ++k) x += g_pre[b*H + k]*w1[k*H + t];
        float sp = (x > 0.f) ? x + log1pf(expf(-x)) : log1pf(expf(x));
        sU[t] = sp - 0.6931471805599453f;
        __syncthreads();
        if (t < 3) { float s = b2[t]; for (int k = 0; k < H; ++k) s += sU[k]*w2[k*3 + t]; so[t] = s; }
        __syncthreads();
        if (t == 0) out[b] = so[kind[b] - 1];
        __syncthreads();
    }
}

// ---------------- host ------------------------------------------------------
extern "C" void kernel_launch(void* const* d_in, const int* in_sizes, int n_in,
                              void* d_out, int out_size)
{
    const float* protein_pos  = (const float*)d_in[0];
    const float* protein_feat = (const float*)d_in[1];
    const float* ligand_pos   = (const float*)d_in[2];
    const float* ligand_feat  = (const float*)d_in[3];
    const int*   output_kind  = (const int*)d_in[6];
    const float* prot_w = (const float*)d_in[7];  const float* prot_b = (const float*)d_in[8];
    const float* lig_w  = (const float*)d_in[9];  const float* lig_b  = (const float*)d_in[10];
    const float* edge_w1 = (const float*)d_in[11]; const float* edge_b1 = (const float*)d_in[12];
    const float* edge_w2 = (const float*)d_in[13]; const float* edge_b2 = (const float*)d_in[14];
    const float* inf_w   = (const float*)d_in[15]; const float* inf_b   = (const float*)d_in[16];
    const float* node_w1 = (const float*)d_in[17]; const float* node_b1 = (const float*)d_in[18];
    const float* node_w2 = (const float*)d_in[19]; const float* node_b2 = (const float*)d_in[20];
    const float* out_w1  = (const float*)d_in[21]; const float* out_b1  = (const float*)d_in[22];
    const float* out_w2  = (const float*)d_in[23]; const float* out_b2  = (const float*)d_in[24];
    float* out = (float*)d_out;

    int Np = in_sizes[0]/3, Nl = in_sizes[2]/3;
    int B  = in_sizes[6];
    int Fp = in_sizes[1]/Np, Fl = in_sizes[3]/Nl;
    int n_prot = Np/B, n_lig = Nl/B;
    int n = n_prot + n_lig;
    int N = Np + Nl;
    int E = N*KNN;

    cudaFuncSetAttribute(edge_kernel, cudaFuncAttributeMaxDynamicSharedMemorySize, EDGE_SMEM);
    cudaFuncSetAttribute(node_kernel, cudaFuncAttributeMaxDynamicSharedMemorySize, NODE_SMEM);

    embed_kernel<<<N, 128>>>(protein_pos, protein_feat, ligand_pos, ligand_feat,
                             prot_w, prot_b, lig_w, lig_b, n_prot, n_lig, n, Fp, Fl);

    knn_kernel<<<dim3((n + 127)/128, B), 128, n*(int)sizeof(float4)>>>(n);

    w2prep_kernel<<<3*128, 128>>>(edge_w2, edge_w1);
    w1abprep_kernel<<<3*256, 144>>>(edge_w1, edge_b1);

    float step  = 10.0f/19.0f;
    float coeff = -0.5f/(step*step);
    attr_kernel<<<(E + 255)/256, 256>>>(E, step, coeff);

    ab_kernel<<<N/64, 256>>>(0);
    for (int l = 0; l < 3; ++l) {
        edge_kernel<<<E/128, 256, EDGE_SMEM>>>(edge_b2, inf_w, inf_b, l);
        node_kernel<<<N/64, 256, NODE_SMEM>>>(node_w1, node_b1, node_w2, node_b2, l);
        if (l < 2) ab_kernel<<<N/64, 256>>>(l + 1);
    }

    pool_kernel<<<B*16, 128>>>(n);
    out_kernel<<<1, 128>>>(out_w1, out_b1, out_w2, out_b2, output_kind, out, B);
}

// round 14
// speedup vs baseline: 1.7246x; 1.1462x over previous
#include <cuda_runtime.h>
#include <cuda_bf16.h>
#include <mma.h>
#include <math.h>

#define H   128
#define GG  20
#define KNN 32
#define MAXN 24000
#define MAXE (MAXN*KNN)

using namespace nvcuda;

// ---------------- f32x2 packed helpers --------------------------------------
__device__ __forceinline__ unsigned long long pack2(float lo, float hi) {
    unsigned long long r;
    asm("mov.b64 %0, {%1, %2};" : "=l"(r) : "f"(lo), "f"(hi));
    return r;
}
__device__ __forceinline__ unsigned long long dup2(float v) {
    unsigned long long r;
    asm("mov.b64 %0, {%1, %1};" : "=l"(r) : "f"(v));
    return r;
}
__device__ __forceinline__ void unpack2(unsigned long long p, float& lo, float& hi) {
    asm("mov.b64 {%0, %1}, %2;" : "=f"(lo), "=f"(hi) : "l"(p));
}
__device__ __forceinline__ unsigned long long fma2(unsigned long long a, unsigned long long b, unsigned long long c) {
    unsigned long long d;
    asm("fma.rn.f32x2 %0, %1, %2, %3;" : "=l"(d) : "l"(a), "l"(b), "l"(c));
    return d;
}
__device__ __forceinline__ unsigned smem_u32(const void* p) {
    unsigned a;
    asm("{ .reg .u64 t; cvta.to.shared.u64 t, %1; cvt.u32.u64 %0, t; }" : "=r"(a) : "l"(p));
    return a;
}
__device__ __forceinline__ void cp16(unsigned dst, const void* src) {
    asm volatile("cp.async.cg.shared.global [%0], [%1], 16;" :: "r"(dst), "l"(src) : "memory");
}

// ---------------- scratch ----------------------------------------------------
__device__ __align__(16) float g_pos[MAXN*3];
__device__ __align__(16) float g_h  [MAXN*H];
__device__ __align__(16) float g_A  [MAXN*H];
__device__ __align__(16) float g_B  [MAXN*H];
__device__ __align__(16) float g_mi [MAXN*H];
__device__ int   g_nbr[MAXE];
__device__ float g_attr[(size_t)MAXE*GG];
__device__ float g_pre[16*H];
__device__ __align__(16) unsigned short g_w2bf[3*2*16384];
__device__ __align__(16) unsigned short g_w1ebf[3*2*4096];
__device__ __align__(16) unsigned short g_w1ab[3*2*256*144];

// ---------------- K1: embeddings --------------------------------------------
__global__ void embed_kernel(const float* __restrict__ ppos, const float* __restrict__ pfeat,
                             const float* __restrict__ lpos, const float* __restrict__ lfeat,
                             const float* __restrict__ pw, const float* __restrict__ pb,
                             const float* __restrict__ lw, const float* __restrict__ lb,
                             int n_prot, int n_lig, int n, int Fp, int Fl)
{
    __shared__ float sf[32];
    int i = blockIdx.x, t = threadIdx.x;
    int b = i / n, j = i - b * n;
    const float *feat, *w, *bias, *pos; int F;
    if (j < n_prot) { int r = b*n_prot + j;            feat = pfeat + (size_t)r*Fp; w = pw; bias = pb; pos = ppos + (size_t)r*3; F = Fp; }
    else            { int r = b*n_lig  + (j - n_prot); feat = lfeat + (size_t)r*Fl; w = lw; bias = lb; pos = lpos + (size_t)r*3; F = Fl; }
    if (t < F) sf[t] = feat[t];
    __syncthreads();
    float acc = bias[t];
    for (int f = 0; f < F; ++f) acc += sf[f] * w[f*H + t];
    g_h[(size_t)i*H + t] = acc;
    if (t < 3) g_pos[i*3 + t] = pos[t];
}

// ---------------- K2: kNN ----------------------------------------------------
__global__ void knn_kernel(int n)
{
    extern __shared__ float4 spos4[];
    int b = blockIdx.y, tid = threadIdx.x;
    const float* gp = g_pos + (size_t)b*n*3;
    for (int i = tid; i < n; i += blockDim.x)
        spos4[i] = make_float4(gp[i*3], gp[i*3+1], gp[i*3+2], 0.f);
    __syncthreads();
    int c = blockIdx.x*blockDim.x + tid;
    if (c >= n) return;
    float4 pc = spos4[c];
    float bd[KNN]; int bi[KNN];
#pragma unroll
    for (int s = 0; s < KNN; ++s) { bd[s] = 3.402823466e38f; bi[s] = 0x7fffffff; }
    float wd = 3.402823466e38f; int wi = 0x7fffffff; int ws = 0;
    for (int j = 0; j < n; ++j) {
        if (j == c) continue;
        float4 pj = spos4[j];
        float dx = pc.x - pj.x, dy = pc.y - pj.y, dz = pc.z - pj.z;
        float d2 = dx*dx + dy*dy + dz*dz;
        if (d2 < wd || (d2 == wd && j < wi)) {
            bd[ws] = d2; bi[ws] = j;
            wd = bd[0]; wi = bi[0]; ws = 0;
#pragma unroll
            for (int s = 1; s < KNN; ++s)
                if (bd[s] > wd || (bd[s] == wd && bi[s] > wi)) { wd = bd[s]; wi = bi[s]; ws = s; }
        }
    }
    size_t base = ((size_t)(b*n + c))*KNN;
#pragma unroll
    for (int s = 0; s < KNN; ++s) g_nbr[base + s] = b*n + bi[s];
}

// ---------------- K3: Gaussian smearing + zero g_pre ------------------------
__global__ void attr_kernel(int E, float step, float coeff)
{
    int e = blockIdx.x*blockDim.x + threadIdx.x;
    if (e >= E) return;
    if (e < 16*H) g_pre[e] = 0.f;
    int dst = e >> 5;
    int src = g_nbr[e];
    float dx = g_pos[dst*3]   - g_pos[src*3];
    float dy = g_pos[dst*3+1] - g_pos[src*3+1];
    float dz = g_pos[dst*3+2] - g_pos[src*3+2];
    float d = sqrtf(dx*dx + dy*dy + dz*dz);
    size_t o = (size_t)e*GG;
#pragma unroll
    for (int g = 0; g < GG; ++g) {
        float t = d - g*step;
        g_attr[o + g] = expf(coeff*t*t);
    }
}

// ---------------- K3b: bake W2^T and W1e bf16 hi/lo --------------------------
__global__ void w2prep_kernel(const float* __restrict__ edge_w2,
                              const float* __restrict__ edge_w1)
{
    int l = blockIdx.x >> 7, nr = blockIdx.x & 127, k = threadIdx.x;
    float v = edge_w2[((size_t)l*H + k)*H + nr];
    __nv_bfloat16 hb = __float2bfloat16(v);
    float r = v - __bfloat162float(hb);
    __nv_bfloat16 lb = __float2bfloat16(r);
    g_w2bf[(l*2+0)*16384 + nr*128 + k] = __bfloat16_as_ushort(hb);
    g_w2bf[(l*2+1)*16384 + nr*128 + k] = __bfloat16_as_ushort(lb);
    if (k < 32) {
        float w = (k < GG) ? edge_w1[(size_t)l*276*H + k*H + nr] : 0.f;
        __nv_bfloat16 wh = __float2bfloat16(w);
        float wr = w - __bfloat162float(wh);
        __nv_bfloat16 wl = __float2bfloat16(wr);
        g_w1ebf[(l*2+0)*4096 + nr*32 + k] = __bfloat16_as_ushort(wh);
        g_w1ebf[(l*2+1)*4096 + nr*32 + k] = __bfloat16_as_ushort(wl);
    }
}

// ---------------- K3c: bake augmented [W1i|W1j] (+bias row) ------------------
__global__ void w1abprep_kernel(const float* __restrict__ edge_w1,
                                const float* __restrict__ edge_b1)
{
    int l = blockIdx.x >> 8, n = blockIdx.x & 255, k = threadIdx.x;
    float v = 0.f;
    if (k < 128) {
        v = (n < 128) ? edge_w1[(size_t)l*276*H + (GG+k)*H + n]
                      : edge_w1[(size_t)l*276*H + (GG+128+k)*H + (n-128)];
    } else if (k == 128 && n < 128) {
        v = edge_b1[l*H + n];
    }
    __nv_bfloat16 hb = __float2bfloat16(v);
    float r = v - __bfloat162float(hb);
    __nv_bfloat16 lb = __float2bfloat16(r);
    g_w1ab[((size_t)(l*2+0)*256 + n)*144 + k] = __bfloat16_as_ushort(hb);
    g_w1ab[((size_t)(l*2+1)*256 + n)*144 + k] = __bfloat16_as_ushort(lb);
}

// ---------------- K4: A|B via WMMA (bias folded into k=128) ------------------
#define ABK 144
#define LDH 152
__global__ void __launch_bounds__(256) ab_kernel(int l)
{
    __shared__ __align__(16) __nv_bfloat16 sHhi[64*LDH];
    __shared__ __align__(16) __nv_bfloat16 sHlo[64*LDH];
    int tid = threadIdx.x;
    int nb = blockIdx.x*64;
    for (int i = tid; i < 2048; i += 256) {
        int row = i >> 5, k4 = (i & 31)*4;
        float4 hv = *(const float4*)(g_h + (size_t)(nb+row)*H + k4);
        float x[4] = {hv.x, hv.y, hv.z, hv.w};
#pragma unroll
        for (int q = 0; q < 4; ++q) {
            __nv_bfloat16 hb = __float2bfloat16(x[q]);
            sHhi[row*LDH + k4 + q] = hb;
            sHlo[row*LDH + k4 + q] = __float2bfloat16(x[q] - __bfloat162float(hb));
        }
    }
    for (int i = tid; i < 64*24; i += 256) {
        int row = i / 24, k = 128 + (i % 24);
        __nv_bfloat16 hv = (k == 128) ? __float2bfloat16(1.0f) : __float2bfloat16(0.0f);
        sHhi[row*LDH + k] = hv;
        sHlo[row*LDH + k] = __float2bfloat16(0.0f);
    }
    __syncthreads();

    int wrp = tid >> 5;
    int rowg = wrp >> 2, colg = wrp & 3;
    int er = rowg*32, nc = colg*64;
    const __nv_bfloat16* Wh = (const __nv_bfloat16*)g_w1ab + (size_t)(l*2+0)*256*144;
    const __nv_bfloat16* Wl = (const __nv_bfloat16*)g_w1ab + (size_t)(l*2+1)*256*144;

    wmma::fragment<wmma::accumulator,16,16,16,float> acc[2][4];
#pragma unroll
    for (int i = 0; i < 2; ++i)
#pragma unroll
        for (int j = 0; j < 4; ++j) wmma::fill_fragment(acc[i][j], 0.f);

#pragma unroll
    for (int k0 = 0; k0 < ABK; k0 += 16) {
        wmma::fragment<wmma::matrix_a,16,16,16,__nv_bfloat16,wmma::row_major> ah[2], al[2];
#pragma unroll
        for (int i = 0; i < 2; ++i) {
            wmma::load_matrix_sync(ah[i], sHhi + (er + i*16)*LDH + k0, LDH);
            wmma::load_matrix_sync(al[i], sHlo + (er + i*16)*LDH + k0, LDH);
        }
#pragma unroll
        for (int j = 0; j < 4; ++j) {
            wmma::fragment<wmma::matrix_b,16,16,16,__nv_bfloat16,wmma::col_major> bh, bl;
            wmma::load_matrix_sync(bh, Wh + (size_t)(nc + j*16)*144 + k0, 144);
            wmma::load_matrix_sync(bl, Wl + (size_t)(nc + j*16)*144 + k0, 144);
#pragma unroll
            for (int i = 0; i < 2; ++i) {
                wmma::mma_sync(acc[i][j], ah[i], bh, acc[i][j]);
                wmma::mma_sync(acc[i][j], ah[i], bl, acc[i][j]);
                wmma::mma_sync(acc[i][j], al[i], bh, acc[i][j]);
            }
        }
    }
#pragma unroll
    for (int i = 0; i < 2; ++i)
#pragma unroll
        for (int j = 0; j < 4; ++j) {
            int c = nc + j*16;
            float* dstp = (c < 128) ? (g_A + (size_t)(nb + er + i*16)*H + c)
                                    : (g_B + (size_t)(nb + er + i*16)*H + (c - 128));
            wmma::store_matrix_sync(dstp, acc[i][j], H, wmma::mem_row_major);
        }
}

// ---------------- K5: persistent edge kernel (resident weights) --------------
#define D1_OFF    0
#define LD1 68
#define M1_HI_OFF 34816
#define M1_LO_OFF 69632
#define D2_OFF    34816
#define B_HI_OFF  104448
#define B_LO_OFF  139264
#define W1EH_OFF  174080
#define W1EL_OFF  184320
#define ATTRH_OFF 194560
#define ATTRL_OFF 204800
#define SA_OFF    215040
#define SB2_OFF   217088
#define SINFW_OFF 217600
#define SGATE_OFF 218112
#define SMI_OFF   218624
#define SSRC_OFF  220672
#define RAW_OFF   221184
#define EDGE_SMEM 231424
#define LDAB  136
#define LDATT 40

__device__ __forceinline__ void edge_prefetch(unsigned sbase, int t, int tid)
{
    const char* attrp = (const char*)g_attr + (size_t)t*128*GG*4;
    for (int i = tid; i < 640; i += 256) cp16(sbase + RAW_OFF + i*16, attrp + i*16);
    const char* ap = (const char*)g_A + (size_t)t*4*H*4;
    for (int i = tid; i < 128; i += 256) cp16(sbase + SA_OFF + i*16, ap + i*16);
    if (tid < 32) cp16(sbase + SSRC_OFF + tid*16, (const char*)g_nbr + (size_t)t*128*4 + tid*16);
    asm volatile("cp.async.commit_group;" ::: "memory");
}

__global__ void __launch_bounds__(256,1) edge_kernel(const float* __restrict__ edge_b2,
                                                     const float* __restrict__ inf_w,
                                                     const float* __restrict__ inf_b,
                                                     int l, int ntiles)
{
    extern __shared__ __align__(16) char sh[];
    float* D1 = (float*)(sh + D1_OFF);
    float* D2 = (float*)(sh + D2_OFF);
    __nv_bfloat16* sM1hi = (__nv_bfloat16*)(sh + M1_HI_OFF);
    __nv_bfloat16* sM1lo = (__nv_bfloat16*)(sh + M1_LO_OFF);
    __nv_bfloat16* sBhi  = (__nv_bfloat16*)(sh + B_HI_OFF);
    __nv_bfloat16* sBlo  = (__nv_bfloat16*)(sh + B_LO_OFF);
    __nv_bfloat16* sWeH  = (__nv_bfloat16*)(sh + W1EH_OFF);
    __nv_bfloat16* sWeL  = (__nv_bfloat16*)(sh + W1EL_OFF);
    __nv_bfloat16* sAtH  = (__nv_bfloat16*)(sh + ATTRH_OFF);
    __nv_bfloat16* sAtL  = (__nv_bfloat16*)(sh + ATTRL_OFF);
    float* sAv   = (float*)(sh + SA_OFF);
    float* sb2   = (float*)(sh + SB2_OFF);
    float* sinfw = (float*)(sh + SINFW_OFF);
    float* sgate = (float*)(sh + SGATE_OFF);
    float* smi   = (float*)(sh + SMI_OFF);
    int*   ssrc  = (int*)(sh + SSRC_OFF);
    float* raw   = (float*)(sh + RAW_OFF);

    int tid = threadIdx.x;
    int wrp = tid >> 5;
    unsigned sbase = smem_u32(sh);
    float infb = inf_b[l];

    // resident staging: W2^T hi/lo + W1e hi/lo (once per CTA)
    {
        const uint4* gh = (const uint4*)(g_w2bf + (size_t)(l*2+0)*16384);
        const uint4* gl = (const uint4*)(g_w2bf + (size_t)(l*2+1)*16384);
        for (int i = tid; i < 2048; i += 256) {
            int row = i >> 4, q = i & 15;
            cp16(sbase + B_HI_OFF + row*272 + q*16, gh + row*16 + q);
            cp16(sbase + B_LO_OFF + row*272 + q*16, gl + row*16 + q);
        }
        const char* gwh = (const char*)(g_w1ebf + (size_t)(l*2+0)*4096);
        const char* gwl = (const char*)(g_w1ebf + (size_t)(l*2+1)*4096);
        for (int i = tid; i < 512; i += 256) {
            int nr = i >> 2, q = i & 3;
            cp16(sbase + W1EH_OFF + nr*80 + q*16, gwh + nr*64 + q*16);
            cp16(sbase + W1EL_OFF + nr*80 + q*16, gwl + nr*64 + q*16);
        }
        asm volatile("cp.async.commit_group;" ::: "memory");
        if (tid < H) { sb2[tid] = edge_b2[l*H+tid]; sinfw[tid] = inf_w[l*H+tid]; }
    }
    int t = blockIdx.x;
    if (t < ntiles) edge_prefetch(sbase, t, tid);
    asm volatile("cp.async.wait_group 0;" ::: "memory");
    __syncthreads();

    for (; t < ntiles; t += gridDim.x) {
        int e0 = t * 128;
        int d0 = t * 4;

        // convert raw attr -> bf16 hi/lo tiles; init smi/sgate
        for (int i = tid; i < 2048; i += 256) {
            int el = i >> 4, k2 = i & 15;
            int k = k2*2;
            float f0 = (k   < GG) ? raw[el*GG + k]     : 0.f;
            float f1 = (k+1 < GG) ? raw[el*GG + k + 1] : 0.f;
            __nv_bfloat16 h0 = __float2bfloat16(f0), h1 = __float2bfloat16(f1);
            __nv_bfloat16 l0 = __float2bfloat16(f0 - __bfloat162float(h0));
            __nv_bfloat16 l1 = __float2bfloat16(f1 - __bfloat162float(h1));
            *(unsigned*)((char*)sAtH + el*80 + k2*4) =
                ((unsigned)__bfloat16_as_ushort(h1) << 16) | __bfloat16_as_ushort(h0);
            *(unsigned*)((char*)sAtL + el*80 + k2*4) =
                ((unsigned)__bfloat16_as_ushort(l1) << 16) | __bfloat16_as_ushort(l0);
        }
        for (int i = tid; i < 512; i += 256) smi[i] = 0.f;
        if (tid < 128) sgate[tid] = infb;
        __syncthreads();

        // two halves: GEMM1 (attr@W1e cols 64h..64h+63) then lite pass for that k-half
        for (int h = 0; h < 2; ++h) {
            {
                int er = wrp*16;
                wmma::fragment<wmma::accumulator,16,16,16,float> a1[4];
#pragma unroll
                for (int j = 0; j < 4; ++j) wmma::fill_fragment(a1[j], 0.f);
#pragma unroll
                for (int k0 = 0; k0 < 32; k0 += 16) {
                    wmma::fragment<wmma::matrix_a,16,16,16,__nv_bfloat16,wmma::row_major> ah, al;
                    wmma::load_matrix_sync(ah, sAtH + er*LDATT + k0, LDATT);
                    wmma::load_matrix_sync(al, sAtL + er*LDATT + k0, LDATT);
#pragma unroll
                    for (int j = 0; j < 4; ++j) {
                        wmma::fragment<wmma::matrix_b,16,16,16,__nv_bfloat16,wmma::col_major> bh, bl;
                        wmma::load_matrix_sync(bh, sWeH + (h*64 + j*16)*LDATT + k0, LDATT);
                        wmma::load_matrix_sync(bl, sWeL + (h*64 + j*16)*LDATT + k0, LDATT);
                        wmma::mma_sync(a1[j], ah, bh, a1[j]);
                        wmma::mma_sync(a1[j], ah, bl, a1[j]);
                        wmma::mma_sync(a1[j], al, bh, a1[j]);
                    }
                }
#pragma unroll
                for (int j = 0; j < 4; ++j)
                    wmma::store_matrix_sync(D1 + er*LD1 + j*16, a1[j], LD1, wmma::mem_row_major);
            }
            __syncthreads();
            // lite: m1 = relu(G + A[dst] + B[src]) for k in [64h, 64h+64)
            {
                int e = tid >> 1, q = tid & 1;
                int srcA = ssrc[e];
                const float4* Brow = (const float4*)(g_B + (size_t)srcA*H);
                const float* sAd = sAv + (e>>5)*H;
#pragma unroll 4
                for (int i4 = 0; i4 < 8; ++i4) {
                    int kl = q*32 + i4*4;
                    int kg = h*64 + kl;
                    float4 bv = Brow[kg >> 2];
                    float4 gv = *(const float4*)(D1 + e*LD1 + kl);
                    float x0 = fmaxf(gv.x + sAd[kg]   + bv.x, 0.f);
                    float x1 = fmaxf(gv.y + sAd[kg+1] + bv.y, 0.f);
                    float x2 = fmaxf(gv.z + sAd[kg+2] + bv.z, 0.f);
                    float x3 = fmaxf(gv.w + sAd[kg+3] + bv.w, 0.f);
                    __nv_bfloat16 h0 = __float2bfloat16(x0), h1 = __float2bfloat16(x1);
                    __nv_bfloat16 h2 = __float2bfloat16(x2), h3 = __float2bfloat16(x3);
                    __nv_bfloat16 l0 = __float2bfloat16(x0 - __bfloat162float(h0));
                    __nv_bfloat16 l1 = __float2bfloat16(x1 - __bfloat162float(h1));
                    __nv_bfloat16 l2 = __float2bfloat16(x2 - __bfloat162float(h2));
                    __nv_bfloat16 l3 = __float2bfloat16(x3 - __bfloat162float(h3));
                    unsigned hi01 = ((unsigned)__bfloat16_as_ushort(h1) << 16) | __bfloat16_as_ushort(h0);
                    unsigned hi23 = ((unsigned)__bfloat16_as_ushort(h3) << 16) | __bfloat16_as_ushort(h2);
                    unsigned lo01 = ((unsigned)__bfloat16_as_ushort(l1) << 16) | __bfloat16_as_ushort(l0);
                    unsigned lo23 = ((unsigned)__bfloat16_as_ushort(l3) << 16) | __bfloat16_as_ushort(l2);
                    unsigned boff = e*272 + kg*2;
                    *(uint2*)((char*)sM1hi + boff) = make_uint2(hi01, hi23);
                    *(uint2*)((char*)sM1lo + boff) = make_uint2(lo01, lo23);
                }
            }
            __syncthreads();
        }

        // prefetch next tile's inputs (attr raw, A rows, nbr) — overlaps GEMM2
        int tn = t + gridDim.x;
        if (tn < ntiles) edge_prefetch(sbase, tn, tid);

        // GEMM2: m = m1 @ W2 (k=128, 3 products), accum in regs
        {
            int rg = wrp & 3, cgf = wrp >> 2;
            int er = rg*32, nc = cgf*64;
            wmma::fragment<wmma::accumulator,16,16,16,float> acc[2][4];
#pragma unroll
            for (int i = 0; i < 2; ++i)
#pragma unroll
                for (int j = 0; j < 4; ++j) wmma::fill_fragment(acc[i][j], 0.f);
#pragma unroll
            for (int k0 = 0; k0 < 128; k0 += 16) {
                wmma::fragment<wmma::matrix_a,16,16,16,__nv_bfloat16,wmma::row_major> ah[2], al[2];
                wmma::fragment<wmma::matrix_b,16,16,16,__nv_bfloat16,wmma::col_major> bh[4], bl[4];
#pragma unroll
                for (int i = 0; i < 2; ++i) {
                    wmma::load_matrix_sync(ah[i], sM1hi + (er + i*16)*LDAB + k0, LDAB);
                    wmma::load_matrix_sync(al[i], sM1lo + (er + i*16)*LDAB + k0, LDAB);
                }
#pragma unroll
                for (int j = 0; j < 4; ++j) {
                    wmma::load_matrix_sync(bh[j], sBhi + (nc + j*16)*LDAB + k0, LDAB);
                    wmma::load_matrix_sync(bl[j], sBlo + (nc + j*16)*LDAB + k0, LDAB);
                }
#pragma unroll
                for (int i = 0; i < 2; ++i)
#pragma unroll
                    for (int j = 0; j < 4; ++j) {
                        wmma::mma_sync(acc[i][j], ah[i], bh[j], acc[i][j]);
                        wmma::mma_sync(acc[i][j], ah[i], bl[j], acc[i][j]);
                        wmma::mma_sync(acc[i][j], al[i], bh[j], acc[i][j]);
                    }
            }
            __syncthreads();   // all warps done reading M1 before D2 overwrites it
#pragma unroll
            for (int i = 0; i < 2; ++i)
#pragma unroll
                for (int j = 0; j < 4; ++j)
                    wmma::store_matrix_sync(D2 + (er + i*16)*132 + nc + j*16, acc[i][j],
                                            132, wmma::mem_row_major);
        }
        __syncthreads();

        // epilogue stage 1: bias + relu + gate logits
        {
            int e = tid >> 1, c0 = (tid & 1)*64;
            float p = 0.f;
#pragma unroll 8
            for (int c = 0; c < 64; ++c) {
                float v = D2[e*132 + c0 + c] + sb2[c0 + c];
                v = fmaxf(v, 0.f);
                D2[e*132 + c0 + c] = v;
                p += v * sinfw[c0 + c];
            }
            atomicAdd(&sgate[e], p);
        }
        __syncthreads();
        if (tid < 128) sgate[tid] = 1.f/(1.f + expf(-sgate[tid]));
        __syncthreads();

        // epilogue stage 2: mi[d][c] = sum_e m[e][c]*gate[e]
        {
            int c = tid & 127, hf = tid >> 7;
#pragma unroll
            for (int d = 0; d < 4; ++d) {
                float s = 0.f;
#pragma unroll 4
                for (int j = 0; j < 16; ++j) {
                    int e = d*32 + hf*16 + j;
                    s += D2[e*132 + c] * sgate[e];
                }
                atomicAdd(&smi[d*H + c], s);
            }
        }
        __syncthreads();
        for (int i = tid; i < 4*H; i += 256) g_mi[(size_t)d0*H + i] = smi[i];
        asm volatile("cp.async.wait_group 0;" ::: "memory");
        __syncthreads();
    }
}

// ---------------- K6: node MLP + residual, 64-node tiles ---------------------
#define LDZ 68
#define NODE_SMEM (256*LDZ*4)
__global__ void __launch_bounds__(256) node_kernel(const float* __restrict__ nw1,
                                                   const float* __restrict__ nb1,
                                                   const float* __restrict__ nw2,
                                                   const float* __restrict__ nb2, int l)
{
    extern __shared__ float sZ[];
    int tid = threadIdx.x;
    int nb = blockIdx.x*64;
    for (int i = tid; i < 64*H; i += 256) {
        int nn = i>>7, k = i&127;
        sZ[k*LDZ + nn]     = g_mi[(size_t)(nb+nn)*H + k];
        sZ[(H+k)*LDZ + nn] = g_h [(size_t)(nb+nn)*H + k];
    }
    __syncthreads();
    int cg = tid & 15, ng = tid >> 4, col = cg*8;
    const ulonglong2* W1a = (const ulonglong2*)(nw1 + (size_t)l*2*H*H);
    const ulonglong2* W1b = W1a + H*H/4;
    unsigned long long acc[4][4];
#pragma unroll
    for (int c2 = 0; c2 < 4; ++c2) {
        unsigned long long b = pack2(nb1[l*H + col + 2*c2], nb1[l*H + col + 2*c2 + 1]);
#pragma unroll
        for (int r = 0; r < 4; ++r) acc[r][c2] = b;
    }
#pragma unroll 2
    for (int k = 0; k < H; ++k) {
        float4 am = *(const float4*)(sZ + k*LDZ + ng*4);
        float4 ah = *(const float4*)(sZ + (H+k)*LDZ + ng*4);
        ulonglong2 wa0 = __ldg(W1a + k*32 + cg*2);
        ulonglong2 wa1 = __ldg(W1a + k*32 + cg*2 + 1);
        ulonglong2 wb0 = __ldg(W1b + k*32 + cg*2);
        ulonglong2 wb1 = __ldg(W1b + k*32 + cg*2 + 1);
        unsigned long long mm[4] = {dup2(am.x), dup2(am.y), dup2(am.z), dup2(am.w)};
        unsigned long long hh[4] = {dup2(ah.x), dup2(ah.y), dup2(ah.z), dup2(ah.w)};
        unsigned long long wap[4] = {wa0.x, wa0.y, wa1.x, wa1.y};
        unsigned long long wbp[4] = {wb0.x, wb0.y, wb1.x, wb1.y};
#pragma unroll
        for (int r = 0; r < 4; ++r)
#pragma unroll
            for (int c2 = 0; c2 < 4; ++c2) {
                acc[r][c2] = fma2(mm[r], wap[c2], acc[r][c2]);
                acc[r][c2] = fma2(hh[r], wbp[c2], acc[r][c2]);
            }
    }
    __syncthreads();
#pragma unroll
    for (int r = 0; r < 4; ++r)
#pragma unroll
        for (int c2 = 0; c2 < 4; ++c2) {
            float lo, hi;
            unpack2(acc[r][c2], lo, hi);
            sZ[(col + 2*c2)*LDZ + ng*4 + r]     = fmaxf(lo, 0.f);
            sZ[(col + 2*c2 + 1)*LDZ + ng*4 + r] = fmaxf(hi, 0.f);
        }
    __syncthreads();
    const ulonglong2* W2 = (const ulonglong2*)(nw2 + (size_t)l*H*H);
    unsigned long long acc2[4][4];
#pragma unroll
    for (int c2 = 0; c2 < 4; ++c2) {
        unsigned long long b = pack2(nb2[l*H + col + 2*c2], nb2[l*H + col + 2*c2 + 1]);
#pragma unroll
        for (int r = 0; r < 4; ++r) acc2[r][c2] = b;
    }
#pragma unroll 4
    for (int k = 0; k < H; ++k) {
        float4 a = *(const float4*)(sZ + k*LDZ + ng*4);
        ulonglong2 w0 = __ldg(W2 + k*32 + cg*2);
        ulonglong2 w1 = __ldg(W2 + k*32 + cg*2 + 1);
        unsigned long long ad[4] = {dup2(a.x), dup2(a.y), dup2(a.z), dup2(a.w)};
        unsigned long long wp[4] = {w0.x, w0.y, w1.x, w1.y};
#pragma unroll
        for (int r = 0; r < 4; ++r)
#pragma unroll
            for (int c2 = 0; c2 < 4; ++c2) acc2[r][c2] = fma2(ad[r], wp[c2], acc2[r][c2]);
    }
#pragma unroll
    for (int r = 0; r < 4; ++r) {
        float v[8];
#pragma unroll
        for (int c2 = 0; c2 < 4; ++c2) unpack2(acc2[r][c2], v[2*c2], v[2*c2+1]);
        size_t o = (size_t)(nb + ng*4 + r)*H + col;
        float4* hp = (float4*)(g_h + o);
        float4 h0 = hp[0], h1 = hp[1];
        h0.x += v[0]; h0.y += v[1]; h0.z += v[2]; h0.w += v[3];
        h1.x += v[4]; h1.y += v[5]; h1.z += v[6]; h1.w += v[7];
        hp[0] = h0; hp[1] = h1;
    }
}

// ---------------- K7/K8 ------------------------------------------------------
__global__ void pool_kernel(int n)
{
    int b = blockIdx.x >> 4, s = blockIdx.x & 15;
    int c = threadIdx.x;
    float acc = 0.f;
    for (int i = s; i < n; i += 16) acc += g_h[((size_t)b*n + i)*H + c];
    atomicAdd(&g_pre[b*H + c], acc);
}

__global__ void out_kernel(const float* __restrict__ w1, const float* __restrict__ b1,
                           const float* __restrict__ w2, const float* __restrict__ b2,
                           const int* __restrict__ kind, float* __restrict__ out, int B)
{
    __shared__ float sU[H]; __shared__ float so[3];
    int t = threadIdx.x;
    for (int b = 0; b < B; ++b) {
        float x = b1[t];
        for (int k = 0; k < H; ++k) x += g_pre[b*H + k]*w1[k*H + t];
        float sp = (x > 0.f) ? x + log1pf(expf(-x)) : log1pf(expf(x));
        sU[t] = sp - 0.6931471805599453f;
        __syncthreads();
        if (t < 3) { float s = b2[t]; for (int k = 0; k < H; ++k) s += sU[k]*w2[k*3 + t]; so[t] = s; }
        __syncthreads();
        if (t == 0) out[b] = so[kind[b] - 1];
        __syncthreads();
    }
}

// ---------------- host ------------------------------------------------------
extern "C" void kernel_launch(void* const* d_in, const int* in_sizes, int n_in,
                              void* d_out, int out_size)
{
    const float* protein_pos  = (const float*)d_in[0];
    const float* protein_feat = (const float*)d_in[1];
    const float* ligand_pos   = (const float*)d_in[2];
    const float* ligand_feat  = (const float*)d_in[3];
    const int*   output_kind  = (const int*)d_in[6];
    const float* prot_w = (const float*)d_in[7];  const float* prot_b = (const float*)d_in[8];
    const float* lig_w  = (const float*)d_in[9];  const float* lig_b  = (const float*)d_in[10];
    const float* edge_w1 = (const float*)d_in[11]; const float* edge_b1 = (const float*)d_in[12];
    const float* edge_w2 = (const float*)d_in[13]; const float* edge_b2 = (const float*)d_in[14];
    const float* inf_w   = (const float*)d_in[15]; const float* inf_b   = (const float*)d_in[16];
    const float* node_w1 = (const float*)d_in[17]; const float* node_b1 = (const float*)d_in[18];
    const float* node_w2 = (const float*)d_in[19]; const float* node_b2 = (const float*)d_in[20];
    const float* out_w1  = (const float*)d_in[21]; const float* out_b1  = (const float*)d_in[22];
    const float* out_w2  = (const float*)d_in[23]; const float* out_b2  = (const float*)d_in[24];
    float* out = (float*)d_out;

    int Np = in_sizes[0]/3, Nl = in_sizes[2]/3;
    int B  = in_sizes[6];
    int Fp = in_sizes[1]/Np, Fl = in_sizes[3]/Nl;
    int n_prot = Np/B, n_lig = Nl/B;
    int n = n_prot + n_lig;
    int N = Np + Nl;
    int E = N*KNN;
    int ntiles = E/128;

    int nsm = 148;
    cudaDeviceGetAttribute(&nsm, cudaDevAttrMultiProcessorCount, 0);

    cudaFuncSetAttribute(edge_kernel, cudaFuncAttributeMaxDynamicSharedMemorySize, EDGE_SMEM);
    cudaFuncSetAttribute(node_kernel, cudaFuncAttributeMaxDynamicSharedMemorySize, NODE_SMEM);

    embed_kernel<<<N, 128>>>(protein_pos, protein_feat, ligand_pos, ligand_feat,
                             prot_w, prot_b, lig_w, lig_b, n_prot, n_lig, n, Fp, Fl);

    knn_kernel<<<dim3((n + 127)/128, B), 128, n*(int)sizeof(float4)>>>(n);

    w2prep_kernel<<<3*128, 128>>>(edge_w2, edge_w1);
    w1abprep_kernel<<<3*256, 144>>>(edge_w1, edge_b1);

    float step  = 10.0f/19.0f;
    float coeff = -0.5f/(step*step);
    attr_kernel<<<(E + 255)/256, 256>>>(E, step, coeff);

    ab_kernel<<<N/64, 256>>>(0);
    for (int l = 0; l < 3; ++l) {
        edge_kernel<<<nsm, 256, EDGE_SMEM>>>(edge_b2, inf_w, inf_b, l, ntiles);
        node_kernel<<<N/64, 256, NODE_SMEM>>>(node_w1, node_b1, node_w2, node_b2, l);
        if (l < 2) ab_kernel<<<N/64, 256>>>(l + 1);
    }

    pool_kernel<<<B*16, 128>>>(n);
    out_kernel<<<1, 128>>>(out_w1, out_b1, out_w2, out_b2, output_kind, out, B);
}

// round 15
// speedup vs baseline: 1.7974x; 1.0422x over previous
#include <cuda_runtime.h>
#include <cuda_bf16.h>
#include <mma.h>
#include <math.h>

#define H   128
#define GG  20
#define KNN 32
#define MAXN 24000
#define MAXE (MAXN*KNN)

using namespace nvcuda;

// ---------------- helpers ----------------------------------------------------
__device__ __forceinline__ unsigned smem_u32(const void* p) {
    unsigned a;
    asm("{ .reg .u64 t; cvta.to.shared.u64 t, %1; cvt.u32.u64 %0, t; }" : "=r"(a) : "l"(p));
    return a;
}
__device__ __forceinline__ void cp16(unsigned dst, const void* src) {
    asm volatile("cp.async.cg.shared.global [%0], [%1], 16;" :: "r"(dst), "l"(src) : "memory");
}

// ---------------- scratch ----------------------------------------------------
__device__ __align__(16) float g_pos[MAXN*3];
__device__ __align__(16) float g_h  [MAXN*H];
__device__ __align__(16) float g_A  [MAXN*H];
__device__ __align__(16) float g_B  [MAXN*H];
__device__ __align__(16) float g_mi [MAXN*H];
__device__ int   g_nbr[MAXE];
__device__ float g_attr[(size_t)MAXE*GG];
__device__ float g_pre[16*H];
__device__ __align__(16) unsigned short g_w2bf[3*2*16384];
__device__ __align__(16) unsigned short g_w1ebf[3*2*4096];
__device__ __align__(16) unsigned short g_w1ab[3*2*256*144];
// node weights: W1aug [l][p][n=128][k=272], W2aug [l][p][n=128][k=144]
__device__ __align__(16) unsigned short g_w1nb[3*2*128*272];
__device__ __align__(16) unsigned short g_w2nb[3*2*128*144];

// ---------------- K1: embeddings --------------------------------------------
__global__ void embed_kernel(const float* __restrict__ ppos, const float* __restrict__ pfeat,
                             const float* __restrict__ lpos, const float* __restrict__ lfeat,
                             const float* __restrict__ pw, const float* __restrict__ pb,
                             const float* __restrict__ lw, const float* __restrict__ lb,
                             int n_prot, int n_lig, int n, int Fp, int Fl)
{
    __shared__ float sf[32];
    int i = blockIdx.x, t = threadIdx.x;
    int b = i / n, j = i - b * n;
    const float *feat, *w, *bias, *pos; int F;
    if (j < n_prot) { int r = b*n_prot + j;            feat = pfeat + (size_t)r*Fp; w = pw; bias = pb; pos = ppos + (size_t)r*3; F = Fp; }
    else            { int r = b*n_lig  + (j - n_prot); feat = lfeat + (size_t)r*Fl; w = lw; bias = lb; pos = lpos + (size_t)r*3; F = Fl; }
    if (t < F) sf[t] = feat[t];
    __syncthreads();
    float acc = bias[t];
    for (int f = 0; f < F; ++f) acc += sf[f] * w[f*H + t];
    g_h[(size_t)i*H + t] = acc;
    if (t < 3) g_pos[i*3 + t] = pos[t];
}

// ---------------- K2: kNN ----------------------------------------------------
__global__ void knn_kernel(int n)
{
    extern __shared__ float4 spos4[];
    int b = blockIdx.y, tid = threadIdx.x;
    const float* gp = g_pos + (size_t)b*n*3;
    for (int i = tid; i < n; i += blockDim.x)
        spos4[i] = make_float4(gp[i*3], gp[i*3+1], gp[i*3+2], 0.f);
    __syncthreads();
    int c = blockIdx.x*blockDim.x + tid;
    if (c >= n) return;
    float4 pc = spos4[c];
    float bd[KNN]; int bi[KNN];
#pragma unroll
    for (int s = 0; s < KNN; ++s) { bd[s] = 3.402823466e38f; bi[s] = 0x7fffffff; }
    float wd = 3.402823466e38f; int wi = 0x7fffffff; int ws = 0;
    for (int j = 0; j < n; ++j) {
        if (j == c) continue;
        float4 pj = spos4[j];
        float dx = pc.x - pj.x, dy = pc.y - pj.y, dz = pc.z - pj.z;
        float d2 = dx*dx + dy*dy + dz*dz;
        if (d2 < wd || (d2 == wd && j < wi)) {
            bd[ws] = d2; bi[ws] = j;
            wd = bd[0]; wi = bi[0]; ws = 0;
#pragma unroll
            for (int s = 1; s < KNN; ++s)
                if (bd[s] > wd || (bd[s] == wd && bi[s] > wi)) { wd = bd[s]; wi = bi[s]; ws = s; }
        }
    }
    size_t base = ((size_t)(b*n + c))*KNN;
#pragma unroll
    for (int s = 0; s < KNN; ++s) g_nbr[base + s] = b*n + bi[s];
}

// ---------------- K3: Gaussian smearing + zero g_pre ------------------------
__global__ void attr_kernel(int E, float step, float coeff)
{
    int e = blockIdx.x*blockDim.x + threadIdx.x;
    if (e >= E) return;
    if (e < 16*H) g_pre[e] = 0.f;
    int dst = e >> 5;
    int src = g_nbr[e];
    float dx = g_pos[dst*3]   - g_pos[src*3];
    float dy = g_pos[dst*3+1] - g_pos[src*3+1];
    float dz = g_pos[dst*3+2] - g_pos[src*3+2];
    float d = sqrtf(dx*dx + dy*dy + dz*dz);
    size_t o = (size_t)e*GG;
#pragma unroll
    for (int g = 0; g < GG; ++g) {
        float t = d - g*step;
        g_attr[o + g] = expf(coeff*t*t);
    }
}

// ---------------- K3b: bake W2^T and W1e bf16 hi/lo --------------------------
__global__ void w2prep_kernel(const float* __restrict__ edge_w2,
                              const float* __restrict__ edge_w1)
{
    int l = blockIdx.x >> 7, nr = blockIdx.x & 127, k = threadIdx.x;
    float v = edge_w2[((size_t)l*H + k)*H + nr];
    __nv_bfloat16 hb = __float2bfloat16(v);
    float r = v - __bfloat162float(hb);
    __nv_bfloat16 lb = __float2bfloat16(r);
    g_w2bf[(l*2+0)*16384 + nr*128 + k] = __bfloat16_as_ushort(hb);
    g_w2bf[(l*2+1)*16384 + nr*128 + k] = __bfloat16_as_ushort(lb);
    if (k < 32) {
        float w = (k < GG) ? edge_w1[(size_t)l*276*H + k*H + nr] : 0.f;
        __nv_bfloat16 wh = __float2bfloat16(w);
        float wr = w - __bfloat162float(wh);
        __nv_bfloat16 wl = __float2bfloat16(wr);
        g_w1ebf[(l*2+0)*4096 + nr*32 + k] = __bfloat16_as_ushort(wh);
        g_w1ebf[(l*2+1)*4096 + nr*32 + k] = __bfloat16_as_ushort(wl);
    }
}

// ---------------- K3c: bake augmented [W1i|W1j] (+bias row) ------------------
__global__ void w1abprep_kernel(const float* __restrict__ edge_w1,
                                const float* __restrict__ edge_b1)
{
    int l = blockIdx.x >> 8, n = blockIdx.x & 255, k = threadIdx.x;
    float v = 0.f;
    if (k < 128) {
        v = (n < 128) ? edge_w1[(size_t)l*276*H + (GG+k)*H + n]
                      : edge_w1[(size_t)l*276*H + (GG+128+k)*H + (n-128)];
    } else if (k == 128 && n < 128) {
        v = edge_b1[l*H + n];
    }
    __nv_bfloat16 hb = __float2bfloat16(v);
    float r = v - __bfloat162float(hb);
    __nv_bfloat16 lb = __float2bfloat16(r);
    g_w1ab[((size_t)(l*2+0)*256 + n)*144 + k] = __bfloat16_as_ushort(hb);
    g_w1ab[((size_t)(l*2+1)*256 + n)*144 + k] = __bfloat16_as_ushort(lb);
}

// ---------------- K3d: bake node weights (bias-in-K augmented) ---------------
__global__ void w1nprep_kernel(const float* __restrict__ nw1, const float* __restrict__ nb1)
{
    int l = blockIdx.x >> 7, n = blockIdx.x & 127, k = threadIdx.x;  // k 0..271
    float v = 0.f;
    if (k < 256)      v = nw1[(size_t)l*256*H + (size_t)k*H + n];
    else if (k == 256) v = nb1[l*H + n];
    __nv_bfloat16 hb = __float2bfloat16(v);
    __nv_bfloat16 lb = __float2bfloat16(v - __bfloat162float(hb));
    g_w1nb[((size_t)(l*2+0)*128 + n)*272 + k] = __bfloat16_as_ushort(hb);
    g_w1nb[((size_t)(l*2+1)*128 + n)*272 + k] = __bfloat16_as_ushort(lb);
}
__global__ void w2nprep_kernel(const float* __restrict__ nw2, const float* __restrict__ nb2)
{
    int l = blockIdx.x >> 7, n = blockIdx.x & 127, k = threadIdx.x;  // k 0..143
    float v = 0.f;
    if (k < 128)      v = nw2[(size_t)l*H*H + (size_t)k*H + n];
    else if (k == 128) v = nb2[l*H + n];
    __nv_bfloat16 hb = __float2bfloat16(v);
    __nv_bfloat16 lb = __float2bfloat16(v - __bfloat162float(hb));
    g_w2nb[((size_t)(l*2+0)*128 + n)*144 + k] = __bfloat16_as_ushort(hb);
    g_w2nb[((size_t)(l*2+1)*128 + n)*144 + k] = __bfloat16_as_ushort(lb);
}

// ---------------- K4: A|B via WMMA (bias folded into k=128) ------------------
#define ABK 144
#define LDH 152
__global__ void __launch_bounds__(256) ab_kernel(int l)
{
    __shared__ __align__(16) __nv_bfloat16 sHhi[64*LDH];
    __shared__ __align__(16) __nv_bfloat16 sHlo[64*LDH];
    int tid = threadIdx.x;
    int nb = blockIdx.x*64;
    for (int i = tid; i < 2048; i += 256) {
        int row = i >> 5, k4 = (i & 31)*4;
        float4 hv = *(const float4*)(g_h + (size_t)(nb+row)*H + k4);
        float x[4] = {hv.x, hv.y, hv.z, hv.w};
#pragma unroll
        for (int q = 0; q < 4; ++q) {
            __nv_bfloat16 hb = __float2bfloat16(x[q]);
            sHhi[row*LDH + k4 + q] = hb;
            sHlo[row*LDH + k4 + q] = __float2bfloat16(x[q] - __bfloat162float(hb));
        }
    }
    for (int i = tid; i < 64*24; i += 256) {
        int row = i / 24, k = 128 + (i % 24);
        __nv_bfloat16 hv = (k == 128) ? __float2bfloat16(1.0f) : __float2bfloat16(0.0f);
        sHhi[row*LDH + k] = hv;
        sHlo[row*LDH + k] = __float2bfloat16(0.0f);
    }
    __syncthreads();

    int wrp = tid >> 5;
    int rowg = wrp >> 2, colg = wrp & 3;
    int er = rowg*32, nc = colg*64;
    const __nv_bfloat16* Wh = (const __nv_bfloat16*)g_w1ab + (size_t)(l*2+0)*256*144;
    const __nv_bfloat16* Wl = (const __nv_bfloat16*)g_w1ab + (size_t)(l*2+1)*256*144;

    wmma::fragment<wmma::accumulator,16,16,16,float> acc[2][4];
#pragma unroll
    for (int i = 0; i < 2; ++i)
#pragma unroll
        for (int j = 0; j < 4; ++j) wmma::fill_fragment(acc[i][j], 0.f);

#pragma unroll
    for (int k0 = 0; k0 < ABK; k0 += 16) {
        wmma::fragment<wmma::matrix_a,16,16,16,__nv_bfloat16,wmma::row_major> ah[2], al[2];
#pragma unroll
        for (int i = 0; i < 2; ++i) {
            wmma::load_matrix_sync(ah[i], sHhi + (er + i*16)*LDH + k0, LDH);
            wmma::load_matrix_sync(al[i], sHlo + (er + i*16)*LDH + k0, LDH);
        }
#pragma unroll
        for (int j = 0; j < 4; ++j) {
            wmma::fragment<wmma::matrix_b,16,16,16,__nv_bfloat16,wmma::col_major> bh, bl;
            wmma::load_matrix_sync(bh, Wh + (size_t)(nc + j*16)*144 + k0, 144);
            wmma::load_matrix_sync(bl, Wl + (size_t)(nc + j*16)*144 + k0, 144);
#pragma unroll
            for (int i = 0; i < 2; ++i) {
                wmma::mma_sync(acc[i][j], ah[i], bh, acc[i][j]);
                wmma::mma_sync(acc[i][j], ah[i], bl, acc[i][j]);
                wmma::mma_sync(acc[i][j], al[i], bh, acc[i][j]);
            }
        }
    }
#pragma unroll
    for (int i = 0; i < 2; ++i)
#pragma unroll
        for (int j = 0; j < 4; ++j) {
            int c = nc + j*16;
            float* dstp = (c < 128) ? (g_A + (size_t)(nb + er + i*16)*H + c)
                                    : (g_B + (size_t)(nb + er + i*16)*H + (c - 128));
            wmma::store_matrix_sync(dstp, acc[i][j], H, wmma::mem_row_major);
        }
}

// ---------------- K5: persistent edge kernel (resident weights) --------------
#define D1_OFF    0
#define LD1 68
#define M1_HI_OFF 34816
#define M1_LO_OFF 69632
#define D2_OFF    34816
#define B_HI_OFF  104448
#define B_LO_OFF  139264
#define W1EH_OFF  174080
#define W1EL_OFF  184320
#define ATTRH_OFF 194560
#define ATTRL_OFF 204800
#define SA_OFF    215040
#define SB2_OFF   217088
#define SINFW_OFF 217600
#define SGATE_OFF 218112
#define SMI_OFF   218624
#define SSRC_OFF  220672
#define RAW_OFF   221184
#define EDGE_SMEM 231424
#define LDAB  136
#define LDATT 40

__device__ __forceinline__ void edge_prefetch(unsigned sbase, int t, int tid)
{
    const char* attrp = (const char*)g_attr + (size_t)t*128*GG*4;
    for (int i = tid; i < 640; i += 256) cp16(sbase + RAW_OFF + i*16, attrp + i*16);
    const char* ap = (const char*)g_A + (size_t)t*4*H*4;
    for (int i = tid; i < 128; i += 256) cp16(sbase + SA_OFF + i*16, ap + i*16);
    if (tid < 32) cp16(sbase + SSRC_OFF + tid*16, (const char*)g_nbr + (size_t)t*128*4 + tid*16);
    asm volatile("cp.async.commit_group;" ::: "memory");
}

__global__ void __launch_bounds__(256,1) edge_kernel(const float* __restrict__ edge_b2,
                                                     const float* __restrict__ inf_w,
                                                     const float* __restrict__ inf_b,
                                                     int l, int ntiles)
{
    extern __shared__ __align__(16) char sh[];
    float* D1 = (float*)(sh + D1_OFF);
    float* D2 = (float*)(sh + D2_OFF);
    __nv_bfloat16* sM1hi = (__nv_bfloat16*)(sh + M1_HI_OFF);
    __nv_bfloat16* sM1lo = (__nv_bfloat16*)(sh + M1_LO_OFF);
    __nv_bfloat16* sBhi  = (__nv_bfloat16*)(sh + B_HI_OFF);
    __nv_bfloat16* sBlo  = (__nv_bfloat16*)(sh + B_LO_OFF);
    __nv_bfloat16* sWeH  = (__nv_bfloat16*)(sh + W1EH_OFF);
    __nv_bfloat16* sWeL  = (__nv_bfloat16*)(sh + W1EL_OFF);
    __nv_bfloat16* sAtH  = (__nv_bfloat16*)(sh + ATTRH_OFF);
    __nv_bfloat16* sAtL  = (__nv_bfloat16*)(sh + ATTRL_OFF);
    float* sAv   = (float*)(sh + SA_OFF);
    float* sb2   = (float*)(sh + SB2_OFF);
    float* sinfw = (float*)(sh + SINFW_OFF);
    float* sgate = (float*)(sh + SGATE_OFF);
    float* smi   = (float*)(sh + SMI_OFF);
    int*   ssrc  = (int*)(sh + SSRC_OFF);
    float* raw   = (float*)(sh + RAW_OFF);

    int tid = threadIdx.x;
    int wrp = tid >> 5;
    unsigned sbase = smem_u32(sh);
    float infb = inf_b[l];

    {
        const uint4* gh = (const uint4*)(g_w2bf + (size_t)(l*2+0)*16384);
        const uint4* gl = (const uint4*)(g_w2bf + (size_t)(l*2+1)*16384);
        for (int i = tid; i < 2048; i += 256) {
            int row = i >> 4, q = i & 15;
            cp16(sbase + B_HI_OFF + row*272 + q*16, gh + row*16 + q);
            cp16(sbase + B_LO_OFF + row*272 + q*16, gl + row*16 + q);
        }
        const char* gwh = (const char*)(g_w1ebf + (size_t)(l*2+0)*4096);
        const char* gwl = (const char*)(g_w1ebf + (size_t)(l*2+1)*4096);
        for (int i = tid; i < 512; i += 256) {
            int nr = i >> 2, q = i & 3;
            cp16(sbase + W1EH_OFF + nr*80 + q*16, gwh + nr*64 + q*16);
            cp16(sbase + W1EL_OFF + nr*80 + q*16, gwl + nr*64 + q*16);
        }
        asm volatile("cp.async.commit_group;" ::: "memory");
        if (tid < H) { sb2[tid] = edge_b2[l*H+tid]; sinfw[tid] = inf_w[l*H+tid]; }
    }
    int t = blockIdx.x;
    if (t < ntiles) edge_prefetch(sbase, t, tid);
    asm volatile("cp.async.wait_group 0;" ::: "memory");
    __syncthreads();

    for (; t < ntiles; t += gridDim.x) {
        int d0 = t * 4;

        for (int i = tid; i < 2048; i += 256) {
            int el = i >> 4, k2 = i & 15;
            int k = k2*2;
            float f0 = (k   < GG) ? raw[el*GG + k]     : 0.f;
            float f1 = (k+1 < GG) ? raw[el*GG + k + 1] : 0.f;
            __nv_bfloat16 h0 = __float2bfloat16(f0), h1 = __float2bfloat16(f1);
            __nv_bfloat16 l0 = __float2bfloat16(f0 - __bfloat162float(h0));
            __nv_bfloat16 l1 = __float2bfloat16(f1 - __bfloat162float(h1));
            *(unsigned*)((char*)sAtH + el*80 + k2*4) =
                ((unsigned)__bfloat16_as_ushort(h1) << 16) | __bfloat16_as_ushort(h0);
            *(unsigned*)((char*)sAtL + el*80 + k2*4) =
                ((unsigned)__bfloat16_as_ushort(l1) << 16) | __bfloat16_as_ushort(l0);
        }
        for (int i = tid; i < 512; i += 256) smi[i] = 0.f;
        if (tid < 128) sgate[tid] = infb;
        __syncthreads();

        for (int h = 0; h < 2; ++h) {
            {
                int er = wrp*16;
                wmma::fragment<wmma::accumulator,16,16,16,float> a1[4];
#pragma unroll
                for (int j = 0; j < 4; ++j) wmma::fill_fragment(a1[j], 0.f);
#pragma unroll
                for (int k0 = 0; k0 < 32; k0 += 16) {
                    wmma::fragment<wmma::matrix_a,16,16,16,__nv_bfloat16,wmma::row_major> ah, al;
                    wmma::load_matrix_sync(ah, sAtH + er*LDATT + k0, LDATT);
                    wmma::load_matrix_sync(al, sAtL + er*LDATT + k0, LDATT);
#pragma unroll
                    for (int j = 0; j < 4; ++j) {
                        wmma::fragment<wmma::matrix_b,16,16,16,__nv_bfloat16,wmma::col_major> bh, bl;
                        wmma::load_matrix_sync(bh, sWeH + (h*64 + j*16)*LDATT + k0, LDATT);
                        wmma::load_matrix_sync(bl, sWeL + (h*64 + j*16)*LDATT + k0, LDATT);
                        wmma::mma_sync(a1[j], ah, bh, a1[j]);
                        wmma::mma_sync(a1[j], ah, bl, a1[j]);
                        wmma::mma_sync(a1[j], al, bh, a1[j]);
                    }
                }
#pragma unroll
                for (int j = 0; j < 4; ++j)
                    wmma::store_matrix_sync(D1 + er*LD1 + j*16, a1[j], LD1, wmma::mem_row_major);
            }
            __syncthreads();
            {
                int e = tid >> 1, q = tid & 1;
                int srcA = ssrc[e];
                const float4* Brow = (const float4*)(g_B + (size_t)srcA*H);
                const float* sAd = sAv + (e>>5)*H;
#pragma unroll 4
                for (int i4 = 0; i4 < 8; ++i4) {
                    int kl = q*32 + i4*4;
                    int kg = h*64 + kl;
                    float4 bv = Brow[kg >> 2];
                    float4 gv = *(const float4*)(D1 + e*LD1 + kl);
                    float x0 = fmaxf(gv.x + sAd[kg]   + bv.x, 0.f);
                    float x1 = fmaxf(gv.y + sAd[kg+1] + bv.y, 0.f);
                    float x2 = fmaxf(gv.z + sAd[kg+2] + bv.z, 0.f);
                    float x3 = fmaxf(gv.w + sAd[kg+3] + bv.w, 0.f);
                    __nv_bfloat16 h0 = __float2bfloat16(x0), h1 = __float2bfloat16(x1);
                    __nv_bfloat16 h2 = __float2bfloat16(x2), h3 = __float2bfloat16(x3);
                    __nv_bfloat16 l0 = __float2bfloat16(x0 - __bfloat162float(h0));
                    __nv_bfloat16 l1 = __float2bfloat16(x1 - __bfloat162float(h1));
                    __nv_bfloat16 l2 = __float2bfloat16(x2 - __bfloat162float(h2));
                    __nv_bfloat16 l3 = __float2bfloat16(x3 - __bfloat162float(h3));
                    unsigned hi01 = ((unsigned)__bfloat16_as_ushort(h1) << 16) | __bfloat16_as_ushort(h0);
                    unsigned hi23 = ((unsigned)__bfloat16_as_ushort(h3) << 16) | __bfloat16_as_ushort(h2);
                    unsigned lo01 = ((unsigned)__bfloat16_as_ushort(l1) << 16) | __bfloat16_as_ushort(l0);
                    unsigned lo23 = ((unsigned)__bfloat16_as_ushort(l3) << 16) | __bfloat16_as_ushort(l2);
                    unsigned boff = e*272 + kg*2;
                    *(uint2*)((char*)sM1hi + boff) = make_uint2(hi01, hi23);
                    *(uint2*)((char*)sM1lo + boff) = make_uint2(lo01, lo23);
                }
            }
            __syncthreads();
        }

        int tn = t + gridDim.x;
        if (tn < ntiles) edge_prefetch(sbase, tn, tid);

        {
            int rg = wrp & 3, cgf = wrp >> 2;
            int er = rg*32, nc = cgf*64;
            wmma::fragment<wmma::accumulator,16,16,16,float> acc[2][4];
#pragma unroll
            for (int i = 0; i < 2; ++i)
#pragma unroll
                for (int j = 0; j < 4; ++j) wmma::fill_fragment(acc[i][j], 0.f);
#pragma unroll
            for (int k0 = 0; k0 < 128; k0 += 16) {
                wmma::fragment<wmma::matrix_a,16,16,16,__nv_bfloat16,wmma::row_major> ah[2], al[2];
                wmma::fragment<wmma::matrix_b,16,16,16,__nv_bfloat16,wmma::col_major> bh[4], bl[4];
#pragma unroll
                for (int i = 0; i < 2; ++i) {
                    wmma::load_matrix_sync(ah[i], sM1hi + (er + i*16)*LDAB + k0, LDAB);
                    wmma::load_matrix_sync(al[i], sM1lo + (er + i*16)*LDAB + k0, LDAB);
                }
#pragma unroll
                for (int j = 0; j < 4; ++j) {
                    wmma::load_matrix_sync(bh[j], sBhi + (nc + j*16)*LDAB + k0, LDAB);
                    wmma::load_matrix_sync(bl[j], sBlo + (nc + j*16)*LDAB + k0, LDAB);
                }
#pragma unroll
                for (int i = 0; i < 2; ++i)
#pragma unroll
                    for (int j = 0; j < 4; ++j) {
                        wmma::mma_sync(acc[i][j], ah[i], bh[j], acc[i][j]);
                        wmma::mma_sync(acc[i][j], ah[i], bl[j], acc[i][j]);
                        wmma::mma_sync(acc[i][j], al[i], bh[j], acc[i][j]);
                    }
            }
            __syncthreads();
#pragma unroll
            for (int i = 0; i < 2; ++i)
#pragma unroll
                for (int j = 0; j < 4; ++j)
                    wmma::store_matrix_sync(D2 + (er + i*16)*132 + nc + j*16, acc[i][j],
                                            132, wmma::mem_row_major);
        }
        __syncthreads();

        {
            int e = tid >> 1, c0 = (tid & 1)*64;
            float p = 0.f;
#pragma unroll 8
            for (int c = 0; c < 64; ++c) {
                float v = D2[e*132 + c0 + c] + sb2[c0 + c];
                v = fmaxf(v, 0.f);
                D2[e*132 + c0 + c] = v;
                p += v * sinfw[c0 + c];
            }
            atomicAdd(&sgate[e], p);
        }
        __syncthreads();
        if (tid < 128) sgate[tid] = 1.f/(1.f + expf(-sgate[tid]));
        __syncthreads();

        {
            int c = tid & 127, hf = tid >> 7;
#pragma unroll
            for (int d = 0; d < 4; ++d) {
                float s = 0.f;
#pragma unroll 4
                for (int j = 0; j < 16; ++j) {
                    int e = d*32 + hf*16 + j;
                    s += D2[e*132 + c] * sgate[e];
                }
                atomicAdd(&smi[d*H + c], s);
            }
        }
        __syncthreads();
        for (int i = tid; i < 4*H; i += 256) g_mi[(size_t)d0*H + i] = smi[i];
        asm volatile("cp.async.wait_group 0;" ::: "memory");
        __syncthreads();
    }
}

// ---------------- K6: node MLP via WMMA (bias-in-K), 64-node tiles -----------
#define NLDZ 280   // z row: 272 used k-elems, padded
#define NLDU 152   // u row: 144 used
#define NZHI_OFF 0
#define NZLO_OFF 35840
#define ND1_OFF  35840      // f32 [64][132] aliases zLo after GEMM1
#define NUHI_OFF 71680
#define NULO_OFF 91136
#define ND2_OFF  0          // f32 [64][132] aliases zHi after GEMM2
#define NODE_SMEM 110592

__global__ void __launch_bounds__(256) node_kernel(int l)
{
    extern __shared__ __align__(16) char shn[];
    __nv_bfloat16* zHi = (__nv_bfloat16*)(shn + NZHI_OFF);
    __nv_bfloat16* zLo = (__nv_bfloat16*)(shn + NZLO_OFF);
    float* D1 = (float*)(shn + ND1_OFF);
    __nv_bfloat16* uHi = (__nv_bfloat16*)(shn + NUHI_OFF);
    __nv_bfloat16* uLo = (__nv_bfloat16*)(shn + NULO_OFF);
    float* D2 = (float*)(shn + ND2_OFF);

    int tid = threadIdx.x;
    int nb = blockIdx.x*64;

    // stage z = [mi | h] as bf16 hi/lo, k 0..255; aug k=256 -> 1.0, 257..271 -> 0
    for (int i = tid; i < 2048; i += 256) {
        int row = i >> 5, k4 = (i & 31)*4;
        float4 mv = *(const float4*)(g_mi + (size_t)(nb+row)*H + k4);
        float4 hv = *(const float4*)(g_h  + (size_t)(nb+row)*H + k4);
        float xm[4] = {mv.x, mv.y, mv.z, mv.w};
        float xh[4] = {hv.x, hv.y, hv.z, hv.w};
#pragma unroll
        for (int q = 0; q < 4; ++q) {
            __nv_bfloat16 mb = __float2bfloat16(xm[q]);
            zHi[row*NLDZ + k4 + q] = mb;
            zLo[row*NLDZ + k4 + q] = __float2bfloat16(xm[q] - __bfloat162float(mb));
            __nv_bfloat16 hb = __float2bfloat16(xh[q]);
            zHi[row*NLDZ + 128 + k4 + q] = hb;
            zLo[row*NLDZ + 128 + k4 + q] = __float2bfloat16(xh[q] - __bfloat162float(hb));
        }
    }
    for (int i = tid; i < 64*16; i += 256) {
        int row = i >> 4, k = 256 + (i & 15);
        zHi[row*NLDZ + k] = (k == 256) ? __float2bfloat16(1.0f) : __float2bfloat16(0.0f);
        zLo[row*NLDZ + k] = __float2bfloat16(0.0f);
    }
    __syncthreads();

    int wrp = tid >> 5;
    int rowg = wrp >> 2, colg = wrp & 3;   // 2 x 4 warp grid
    int er = rowg*32, nc = colg*32;
    const __nv_bfloat16* W1h = (const __nv_bfloat16*)g_w1nb + (size_t)(l*2+0)*128*272;
    const __nv_bfloat16* W1l = (const __nv_bfloat16*)g_w1nb + (size_t)(l*2+1)*128*272;

    // GEMM1: u = z @ W1aug  (k=272)
    wmma::fragment<wmma::accumulator,16,16,16,float> acc[2][2];
#pragma unroll
    for (int i = 0; i < 2; ++i)
#pragma unroll
        for (int j = 0; j < 2; ++j) wmma::fill_fragment(acc[i][j], 0.f);
#pragma unroll
    for (int k0 = 0; k0 < 272; k0 += 16) {
        wmma::fragment<wmma::matrix_a,16,16,16,__nv_bfloat16,wmma::row_major> ah[2], al[2];
#pragma unroll
        for (int i = 0; i < 2; ++i) {
            wmma::load_matrix_sync(ah[i], zHi + (er + i*16)*NLDZ + k0, NLDZ);
            wmma::load_matrix_sync(al[i], zLo + (er + i*16)*NLDZ + k0, NLDZ);
        }
#pragma unroll
        for (int j = 0; j < 2; ++j) {
            wmma::fragment<wmma::matrix_b,16,16,16,__nv_bfloat16,wmma::col_major> bh, bl;
            wmma::load_matrix_sync(bh, W1h + (size_t)(nc + j*16)*272 + k0, 272);
            wmma::load_matrix_sync(bl, W1l + (size_t)(nc + j*16)*272 + k0, 272);
#pragma unroll
            for (int i = 0; i < 2; ++i) {
                wmma::mma_sync(acc[i][j], ah[i], bh, acc[i][j]);
                wmma::mma_sync(acc[i][j], ah[i], bl, acc[i][j]);
                wmma::mma_sync(acc[i][j], al[i], bh, acc[i][j]);
            }
        }
    }
    __syncthreads();   // all warps done reading zLo before D1 overwrites it
#pragma unroll
    for (int i = 0; i < 2; ++i)
#pragma unroll
        for (int j = 0; j < 2; ++j)
            wmma::store_matrix_sync(D1 + (er + i*16)*132 + nc + j*16, acc[i][j],
                                    132, wmma::mem_row_major);
    __syncthreads();

    // u = relu(D1) -> bf16 hi/lo; aug k=128 -> 1.0, 129..143 -> 0
    for (int i = tid; i < 2048; i += 256) {
        int row = i >> 5, k4 = (i & 31)*4;
        float4 uv = *(const float4*)(D1 + row*132 + k4);
        float x[4] = {fmaxf(uv.x,0.f), fmaxf(uv.y,0.f), fmaxf(uv.z,0.f), fmaxf(uv.w,0.f)};
#pragma unroll
        for (int q = 0; q < 4; ++q) {
            __nv_bfloat16 ub = __float2bfloat16(x[q]);
            uHi[row*NLDU + k4 + q] = ub;
            uLo[row*NLDU + k4 + q] = __float2bfloat16(x[q] - __bfloat162float(ub));
        }
    }
    for (int i = tid; i < 64*16; i += 256) {
        int row = i >> 4, k = 128 + (i & 15);
        uHi[row*NLDU + k] = (k == 128) ? __float2bfloat16(1.0f) : __float2bfloat16(0.0f);
        uLo[row*NLDU + k] = __float2bfloat16(0.0f);
    }
    __syncthreads();

    // GEMM2: o = u @ W2aug  (k=144)
    const __nv_bfloat16* W2h = (const __nv_bfloat16*)g_w2nb + (size_t)(l*2+0)*128*144;
    const __nv_bfloat16* W2l = (const __nv_bfloat16*)g_w2nb + (size_t)(l*2+1)*128*144;
#pragma unroll
    for (int i = 0; i < 2; ++i)
#pragma unroll
        for (int j = 0; j < 2; ++j) wmma::fill_fragment(acc[i][j], 0.f);
#pragma unroll
    for (int k0 = 0; k0 < 144; k0 += 16) {
        wmma::fragment<wmma::matrix_a,16,16,16,__nv_bfloat16,wmma::row_major> ah[2], al[2];
#pragma unroll
        for (int i = 0; i < 2; ++i) {
            wmma::load_matrix_sync(ah[i], uHi + (er + i*16)*NLDU + k0, NLDU);
            wmma::load_matrix_sync(al[i], uLo + (er + i*16)*NLDU + k0, NLDU);
        }
#pragma unroll
        for (int j = 0; j < 2; ++j) {
            wmma::fragment<wmma::matrix_b,16,16,16,__nv_bfloat16,wmma::col_major> bh, bl;
            wmma::load_matrix_sync(bh, W2h + (size_t)(nc + j*16)*144 + k0, 144);
            wmma::load_matrix_sync(bl, W2l + (size_t)(nc + j*16)*144 + k0, 144);
#pragma unroll
            for (int i = 0; i < 2; ++i) {
                wmma::mma_sync(acc[i][j], ah[i], bh, acc[i][j]);
                wmma::mma_sync(acc[i][j], ah[i], bl, acc[i][j]);
                wmma::mma_sync(acc[i][j], al[i], bh, acc[i][j]);
            }
        }
    }
#pragma unroll
    for (int i = 0; i < 2; ++i)
#pragma unroll
        for (int j = 0; j < 2; ++j)
            wmma::store_matrix_sync(D2 + (er + i*16)*132 + nc + j*16, acc[i][j],
                                    132, wmma::mem_row_major);
    __syncthreads();

    // residual: h += o
    for (int i = tid; i < 2048; i += 256) {
        int row = i >> 5, k4 = (i & 31)*4;
        float4 ov = *(const float4*)(D2 + row*132 + k4);
        float4* hp = (float4*)(g_h + (size_t)(nb+row)*H + k4);
        float4 hv = *hp;
        hv.x += ov.x; hv.y += ov.y; hv.z += ov.z; hv.w += ov.w;
        *hp = hv;
    }
}

// ---------------- K7/K8 ------------------------------------------------------
__global__ void pool_kernel(int n)
{
    int b = blockIdx.x >> 4, s = blockIdx.x & 15;
    int c = threadIdx.x;
    float acc = 0.f;
    for (int i = s; i < n; i += 16) acc += g_h[((size_t)b*n + i)*H + c];
    atomicAdd(&g_pre[b*H + c], acc);
}

__global__ void out_kernel(const float* __restrict__ w1, const float* __restrict__ b1,
                           const float* __restrict__ w2, const float* __restrict__ b2,
                           const int* __restrict__ kind, float* __restrict__ out, int B)
{
    __shared__ float sU[H]; __shared__ float so[3];
    int t = threadIdx.x;
    for (int b = 0; b < B; ++b) {
        float x = b1[t];
        for (int k = 0; k < H; ++k) x += g_pre[b*H + k]*w1[k*H + t];
        float sp = (x > 0.f) ? x + log1pf(expf(-x)) : log1pf(expf(x));
        sU[t] = sp - 0.6931471805599453f;
        __syncthreads();
        if (t < 3) { float s = b2[t]; for (int k = 0; k < H; ++k) s += sU[k]*w2[k*3 + t]; so[t] = s; }
        __syncthreads();
        if (t == 0) out[b] = so[kind[b] - 1];
        __syncthreads();
    }
}

// ---------------- host ------------------------------------------------------
extern "C" void kernel_launch(void* const* d_in, const int* in_sizes, int n_in,
                              void* d_out, int out_size)
{
    const float* protein_pos  = (const float*)d_in[0];
    const float* protein_feat = (const float*)d_in[1];
    const float* ligand_pos   = (const float*)d_in[2];
    const float* ligand_feat  = (const float*)d_in[3];
    const int*   output_kind  = (const int*)d_in[6];
    const float* prot_w = (const float*)d_in[7];  const float* prot_b = (const float*)d_in[8];
    const float* lig_w  = (const float*)d_in[9];  const float* lig_b  = (const float*)d_in[10];
    const float* edge_w1 = (const float*)d_in[11]; const float* edge_b1 = (const float*)d_in[12];
    const float* edge_w2 = (const float*)d_in[13]; const float* edge_b2 = (const float*)d_in[14];
    const float* inf_w   = (const float*)d_in[15]; const float* inf_b   = (const float*)d_in[16];
    const float* node_w1 = (const float*)d_in[17]; const float* node_b1 = (const float*)d_in[18];
    const float* node_w2 = (const float*)d_in[19]; const float* node_b2 = (const float*)d_in[20];
    const float* out_w1  = (const float*)d_in[21]; const float* out_b1  = (const float*)d_in[22];
    const float* out_w2  = (const float*)d_in[23]; const float* out_b2  = (const float*)d_in[24];
    float* out = (float*)d_out;

    int Np = in_sizes[0]/3, Nl = in_sizes[2]/3;
    int B  = in_sizes[6];
    int Fp = in_sizes[1]/Np, Fl = in_sizes[3]/Nl;
    int n_prot = Np/B, n_lig = Nl/B;
    int n = n_prot + n_lig;
    int N = Np + Nl;
    int E = N*KNN;
    int ntiles = E/128;

    int nsm = 148;
    cudaDeviceGetAttribute(&nsm, cudaDevAttrMultiProcessorCount, 0);

    cudaFuncSetAttribute(edge_kernel, cudaFuncAttributeMaxDynamicSharedMemorySize, EDGE_SMEM);
    cudaFuncSetAttribute(node_kernel, cudaFuncAttributeMaxDynamicSharedMemorySize, NODE_SMEM);

    embed_kernel<<<N, 128>>>(protein_pos, protein_feat, ligand_pos, ligand_feat,
                             prot_w, prot_b, lig_w, lig_b, n_prot, n_lig, n, Fp, Fl);

    knn_kernel<<<dim3((n + 127)/128, B), 128, n*(int)sizeof(float4)>>>(n);

    w2prep_kernel<<<3*128, 128>>>(edge_w2, edge_w1);
    w1abprep_kernel<<<3*256, 144>>>(edge_w1, edge_b1);
    w1nprep_kernel<<<3*128, 272>>>(node_w1, node_b1);
    w2nprep_kernel<<<3*128, 144>>>(node_w2, node_b2);

    float step  = 10.0f/19.0f;
    float coeff = -0.5f/(step*step);
    attr_kernel<<<(E + 255)/256, 256>>>(E, step, coeff);

    ab_kernel<<<N/64, 256>>>(0);
    for (int l = 0; l < 3; ++l) {
        edge_kernel<<<nsm, 256, EDGE_SMEM>>>(edge_b2, inf_w, inf_b, l, ntiles);
        node_kernel<<<N/64, 256, NODE_SMEM>>>(l);
        if (l < 2) ab_kernel<<<N/64, 256>>>(l + 1);
    }

    pool_kernel<<<B*16, 128>>>(n);
    out_kernel<<<1, 128>>>(out_w1, out_b1, out_w2, out_b2, output_kind, out, B);
}

// round 16
// speedup vs baseline: 1.7987x; 1.0007x over previous
#include <cuda_runtime.h>
#include <cuda_bf16.h>
#include <mma.h>
#include <math.h>

#define H   128
#define GG  20
#define KNN 32
#define MAXN 24000
#define MAXE (MAXN*KNN)

using namespace nvcuda;

// ---------------- helpers ----------------------------------------------------
__device__ __forceinline__ unsigned smem_u32(const void* p) {
    unsigned a;
    asm("{ .reg .u64 t; cvta.to.shared.u64 t, %1; cvt.u32.u64 %0, t; }" : "=r"(a) : "l"(p));
    return a;
}
__device__ __forceinline__ void cp16(unsigned dst, const void* src) {
    asm volatile("cp.async.cg.shared.global [%0], [%1], 16;" :: "r"(dst), "l"(src) : "memory");
}

// ---------------- scratch ----------------------------------------------------
__device__ __align__(16) float g_pos[MAXN*3];
__device__ __align__(16) float g_h  [MAXN*H];
__device__ __align__(16) float g_A  [MAXN*H];
__device__ __align__(16) float g_B  [MAXN*H];
__device__ __align__(16) float g_mi [MAXN*H];
__device__ int   g_nbr[MAXE];
__device__ float g_attr[(size_t)MAXE*GG];
__device__ float g_pre[16*H];
__device__ __align__(16) unsigned short g_w2bf[3*2*16384];
__device__ __align__(16) unsigned short g_w1ebf[3*2*4096];
__device__ __align__(16) unsigned short g_w1ab[3*2*256*144];
__device__ __align__(16) unsigned short g_w1nb[3*2*128*272];
__device__ __align__(16) unsigned short g_w2nb[3*2*128*144];

// ---------------- K1: embeddings --------------------------------------------
__global__ void embed_kernel(const float* __restrict__ ppos, const float* __restrict__ pfeat,
                             const float* __restrict__ lpos, const float* __restrict__ lfeat,
                             const float* __restrict__ pw, const float* __restrict__ pb,
                             const float* __restrict__ lw, const float* __restrict__ lb,
                             int n_prot, int n_lig, int n, int Fp, int Fl)
{
    __shared__ float sf[32];
    int i = blockIdx.x, t = threadIdx.x;
    int b = i / n, j = i - b * n;
    const float *feat, *w, *bias, *pos; int F;
    if (j < n_prot) { int r = b*n_prot + j;            feat = pfeat + (size_t)r*Fp; w = pw; bias = pb; pos = ppos + (size_t)r*3; F = Fp; }
    else            { int r = b*n_lig  + (j - n_prot); feat = lfeat + (size_t)r*Fl; w = lw; bias = lb; pos = lpos + (size_t)r*3; F = Fl; }
    if (t < F) sf[t] = feat[t];
    __syncthreads();
    float acc = bias[t];
    for (int f = 0; f < F; ++f) acc += sf[f] * w[f*H + t];
    g_h[(size_t)i*H + t] = acc;
    if (t < 3) g_pos[i*3 + t] = pos[t];
}

// ---------------- K2: kNN ----------------------------------------------------
__global__ void knn_kernel(int n)
{
    extern __shared__ float4 spos4[];
    int b = blockIdx.y, tid = threadIdx.x;
    const float* gp = g_pos + (size_t)b*n*3;
    for (int i = tid; i < n; i += blockDim.x)
        spos4[i] = make_float4(gp[i*3], gp[i*3+1], gp[i*3+2], 0.f);
    __syncthreads();
    int c = blockIdx.x*blockDim.x + tid;
    if (c >= n) return;
    float4 pc = spos4[c];
    float bd[KNN]; int bi[KNN];
#pragma unroll
    for (int s = 0; s < KNN; ++s) { bd[s] = 3.402823466e38f; bi[s] = 0x7fffffff; }
    float wd = 3.402823466e38f; int wi = 0x7fffffff; int ws = 0;
    for (int j = 0; j < n; ++j) {
        if (j == c) continue;
        float4 pj = spos4[j];
        float dx = pc.x - pj.x, dy = pc.y - pj.y, dz = pc.z - pj.z;
        float d2 = dx*dx + dy*dy + dz*dz;
        if (d2 < wd || (d2 == wd && j < wi)) {
            bd[ws] = d2; bi[ws] = j;
            wd = bd[0]; wi = bi[0]; ws = 0;
#pragma unroll
            for (int s = 1; s < KNN; ++s)
                if (bd[s] > wd || (bd[s] == wd && bi[s] > wi)) { wd = bd[s]; wi = bi[s]; ws = s; }
        }
    }
    size_t base = ((size_t)(b*n + c))*KNN;
#pragma unroll
    for (int s = 0; s < KNN; ++s) g_nbr[base + s] = b*n + bi[s];
}

// ---------------- K3: Gaussian smearing + zero g_pre ------------------------
__global__ void attr_kernel(int E, float step, float coeff)
{
    int e = blockIdx.x*blockDim.x + threadIdx.x;
    if (e >= E) return;
    if (e < 16*H) g_pre[e] = 0.f;
    int dst = e >> 5;
    int src = g_nbr[e];
    float dx = g_pos[dst*3]   - g_pos[src*3];
    float dy = g_pos[dst*3+1] - g_pos[src*3+1];
    float dz = g_pos[dst*3+2] - g_pos[src*3+2];
    float d = sqrtf(dx*dx + dy*dy + dz*dz);
    size_t o = (size_t)e*GG;
#pragma unroll
    for (int g = 0; g < GG; ++g) {
        float t = d - g*step;
        g_attr[o + g] = expf(coeff*t*t);
    }
}

// ---------------- K3b: bake W2^T and W1e bf16 hi/lo --------------------------
__global__ void w2prep_kernel(const float* __restrict__ edge_w2,
                              const float* __restrict__ edge_w1)
{
    int l = blockIdx.x >> 7, nr = blockIdx.x & 127, k = threadIdx.x;
    float v = edge_w2[((size_t)l*H + k)*H + nr];
    __nv_bfloat16 hb = __float2bfloat16(v);
    float r = v - __bfloat162float(hb);
    __nv_bfloat16 lb = __float2bfloat16(r);
    g_w2bf[(l*2+0)*16384 + nr*128 + k] = __bfloat16_as_ushort(hb);
    g_w2bf[(l*2+1)*16384 + nr*128 + k] = __bfloat16_as_ushort(lb);
    if (k < 32) {
        float w = (k < GG) ? edge_w1[(size_t)l*276*H + k*H + nr] : 0.f;
        __nv_bfloat16 wh = __float2bfloat16(w);
        float wr = w - __bfloat162float(wh);
        __nv_bfloat16 wl = __float2bfloat16(wr);
        g_w1ebf[(l*2+0)*4096 + nr*32 + k] = __bfloat16_as_ushort(wh);
        g_w1ebf[(l*2+1)*4096 + nr*32 + k] = __bfloat16_as_ushort(wl);
    }
}

// ---------------- K3c: bake augmented [W1i|W1j] (+bias row) ------------------
__global__ void w1abprep_kernel(const float* __restrict__ edge_w1,
                                const float* __restrict__ edge_b1)
{
    int l = blockIdx.x >> 8, n = blockIdx.x & 255, k = threadIdx.x;
    float v = 0.f;
    if (k < 128) {
        v = (n < 128) ? edge_w1[(size_t)l*276*H + (GG+k)*H + n]
                      : edge_w1[(size_t)l*276*H + (GG+128+k)*H + (n-128)];
    } else if (k == 128 && n < 128) {
        v = edge_b1[l*H + n];
    }
    __nv_bfloat16 hb = __float2bfloat16(v);
    float r = v - __bfloat162float(hb);
    __nv_bfloat16 lb = __float2bfloat16(r);
    g_w1ab[((size_t)(l*2+0)*256 + n)*144 + k] = __bfloat16_as_ushort(hb);
    g_w1ab[((size_t)(l*2+1)*256 + n)*144 + k] = __bfloat16_as_ushort(lb);
}

// ---------------- K3d: bake node weights (bias-in-K augmented) ---------------
__global__ void w1nprep_kernel(const float* __restrict__ nw1, const float* __restrict__ nb1)
{
    int l = blockIdx.x >> 7, n = blockIdx.x & 127, k = threadIdx.x;
    float v = 0.f;
    if (k < 256)      v = nw1[(size_t)l*256*H + (size_t)k*H + n];
    else if (k == 256) v = nb1[l*H + n];
    __nv_bfloat16 hb = __float2bfloat16(v);
    __nv_bfloat16 lb = __float2bfloat16(v - __bfloat162float(hb));
    g_w1nb[((size_t)(l*2+0)*128 + n)*272 + k] = __bfloat16_as_ushort(hb);
    g_w1nb[((size_t)(l*2+1)*128 + n)*272 + k] = __bfloat16_as_ushort(lb);
}
__global__ void w2nprep_kernel(const float* __restrict__ nw2, const float* __restrict__ nb2)
{
    int l = blockIdx.x >> 7, n = blockIdx.x & 127, k = threadIdx.x;
    float v = 0.f;
    if (k < 128)      v = nw2[(size_t)l*H*H + (size_t)k*H + n];
    else if (k == 128) v = nb2[l*H + n];
    __nv_bfloat16 hb = __float2bfloat16(v);
    __nv_bfloat16 lb = __float2bfloat16(v - __bfloat162float(hb));
    g_w2nb[((size_t)(l*2+0)*128 + n)*144 + k] = __bfloat16_as_ushort(hb);
    g_w2nb[((size_t)(l*2+1)*128 + n)*144 + k] = __bfloat16_as_ushort(lb);
}

// ---------------- K4: A|B via WMMA (bias folded into k=128) ------------------
#define ABK 144
#define LDH 152
__global__ void __launch_bounds__(256) ab_kernel(int l)
{
    __shared__ __align__(16) __nv_bfloat16 sHhi[64*LDH];
    __shared__ __align__(16) __nv_bfloat16 sHlo[64*LDH];
    int tid = threadIdx.x;
    int nb = blockIdx.x*64;
    for (int i = tid; i < 2048; i += 256) {
        int row = i >> 5, k4 = (i & 31)*4;
        float4 hv = *(const float4*)(g_h + (size_t)(nb+row)*H + k4);
        float x[4] = {hv.x, hv.y, hv.z, hv.w};
#pragma unroll
        for (int q = 0; q < 4; ++q) {
            __nv_bfloat16 hb = __float2bfloat16(x[q]);
            sHhi[row*LDH + k4 + q] = hb;
            sHlo[row*LDH + k4 + q] = __float2bfloat16(x[q] - __bfloat162float(hb));
        }
    }
    for (int i = tid; i < 64*24; i += 256) {
        int row = i / 24, k = 128 + (i % 24);
        __nv_bfloat16 hv = (k == 128) ? __float2bfloat16(1.0f) : __float2bfloat16(0.0f);
        sHhi[row*LDH + k] = hv;
        sHlo[row*LDH + k] = __float2bfloat16(0.0f);
    }
    __syncthreads();

    int wrp = tid >> 5;
    int rowg = wrp >> 2, colg = wrp & 3;
    int er = rowg*32, nc = colg*64;
    const __nv_bfloat16* Wh = (const __nv_bfloat16*)g_w1ab + (size_t)(l*2+0)*256*144;
    const __nv_bfloat16* Wl = (const __nv_bfloat16*)g_w1ab + (size_t)(l*2+1)*256*144;

    wmma::fragment<wmma::accumulator,16,16,16,float> acc[2][4];
#pragma unroll
    for (int i = 0; i < 2; ++i)
#pragma unroll
        for (int j = 0; j < 4; ++j) wmma::fill_fragment(acc[i][j], 0.f);

#pragma unroll
    for (int k0 = 0; k0 < ABK; k0 += 16) {
        wmma::fragment<wmma::matrix_a,16,16,16,__nv_bfloat16,wmma::row_major> ah[2], al[2];
#pragma unroll
        for (int i = 0; i < 2; ++i) {
            wmma::load_matrix_sync(ah[i], sHhi + (er + i*16)*LDH + k0, LDH);
            wmma::load_matrix_sync(al[i], sHlo + (er + i*16)*LDH + k0, LDH);
        }
#pragma unroll
        for (int j = 0; j < 4; ++j) {
            wmma::fragment<wmma::matrix_b,16,16,16,__nv_bfloat16,wmma::col_major> bh, bl;
            wmma::load_matrix_sync(bh, Wh + (size_t)(nc + j*16)*144 + k0, 144);
            wmma::load_matrix_sync(bl, Wl + (size_t)(nc + j*16)*144 + k0, 144);
#pragma unroll
            for (int i = 0; i < 2; ++i) {
                wmma::mma_sync(acc[i][j], ah[i], bh, acc[i][j]);
                wmma::mma_sync(acc[i][j], ah[i], bl, acc[i][j]);
                wmma::mma_sync(acc[i][j], al[i], bh, acc[i][j]);
            }
        }
    }
#pragma unroll
    for (int i = 0; i < 2; ++i)
#pragma unroll
        for (int j = 0; j < 4; ++j) {
            int c = nc + j*16;
            float* dstp = (c < 128) ? (g_A + (size_t)(nb + er + i*16)*H + c)
                                    : (g_B + (size_t)(nb + er + i*16)*H + (c - 128));
            wmma::store_matrix_sync(dstp, acc[i][j], H, wmma::mem_row_major);
        }
}

// ---------------- K5: persistent edge kernel, 512 threads --------------------
#define D1_OFF    0
#define LD1 68
#define M1_HI_OFF 34816
#define M1_LO_OFF 69632
#define D2_OFF    34816
#define B_HI_OFF  104448
#define B_LO_OFF  139264
#define W1EH_OFF  174080
#define W1EL_OFF  184320
#define ATTRH_OFF 194560
#define ATTRL_OFF 204800
#define SA_OFF    215040
#define SB2_OFF   217088
#define SINFW_OFF 217600
#define SGATE_OFF 218112
#define SMI_OFF   218624
#define SSRC_OFF  220672
#define RAW_OFF   221184
#define EDGE_SMEM 231424
#define LDAB  136
#define LDATT 40
#define ETH 512

__device__ __forceinline__ void edge_prefetch(unsigned sbase, int t, int tid)
{
    const char* attrp = (const char*)g_attr + (size_t)t*128*GG*4;
    for (int i = tid; i < 640; i += ETH) cp16(sbase + RAW_OFF + i*16, attrp + i*16);
    const char* ap = (const char*)g_A + (size_t)t*4*H*4;
    for (int i = tid; i < 128; i += ETH) cp16(sbase + SA_OFF + i*16, ap + i*16);
    if (tid < 32) cp16(sbase + SSRC_OFF + tid*16, (const char*)g_nbr + (size_t)t*128*4 + tid*16);
    asm volatile("cp.async.commit_group;" ::: "memory");
}

__global__ void __launch_bounds__(ETH,1) edge_kernel(const float* __restrict__ edge_b2,
                                                     const float* __restrict__ inf_w,
                                                     const float* __restrict__ inf_b,
                                                     int l, int ntiles)
{
    extern __shared__ __align__(16) char sh[];
    float* D1 = (float*)(sh + D1_OFF);
    float* D2 = (float*)(sh + D2_OFF);
    __nv_bfloat16* sM1hi = (__nv_bfloat16*)(sh + M1_HI_OFF);
    __nv_bfloat16* sM1lo = (__nv_bfloat16*)(sh + M1_LO_OFF);
    __nv_bfloat16* sBhi  = (__nv_bfloat16*)(sh + B_HI_OFF);
    __nv_bfloat16* sBlo  = (__nv_bfloat16*)(sh + B_LO_OFF);
    __nv_bfloat16* sWeH  = (__nv_bfloat16*)(sh + W1EH_OFF);
    __nv_bfloat16* sWeL  = (__nv_bfloat16*)(sh + W1EL_OFF);
    __nv_bfloat16* sAtH  = (__nv_bfloat16*)(sh + ATTRH_OFF);
    __nv_bfloat16* sAtL  = (__nv_bfloat16*)(sh + ATTRL_OFF);
    float* sAv   = (float*)(sh + SA_OFF);
    float* sb2   = (float*)(sh + SB2_OFF);
    float* sinfw = (float*)(sh + SINFW_OFF);
    float* sgate = (float*)(sh + SGATE_OFF);
    float* smi   = (float*)(sh + SMI_OFF);
    int*   ssrc  = (int*)(sh + SSRC_OFF);
    float* raw   = (float*)(sh + RAW_OFF);

    int tid = threadIdx.x;
    int wrp = tid >> 5;
    unsigned sbase = smem_u32(sh);
    float infb = inf_b[l];

    {
        const uint4* gh = (const uint4*)(g_w2bf + (size_t)(l*2+0)*16384);
        const uint4* gl = (const uint4*)(g_w2bf + (size_t)(l*2+1)*16384);
        for (int i = tid; i < 2048; i += ETH) {
            int row = i >> 4, q = i & 15;
            cp16(sbase + B_HI_OFF + row*272 + q*16, gh + row*16 + q);
            cp16(sbase + B_LO_OFF + row*272 + q*16, gl + row*16 + q);
        }
        const char* gwh = (const char*)(g_w1ebf + (size_t)(l*2+0)*4096);
        const char* gwl = (const char*)(g_w1ebf + (size_t)(l*2+1)*4096);
        for (int i = tid; i < 512; i += ETH) {
            int nr = i >> 2, q = i & 3;
            cp16(sbase + W1EH_OFF + nr*80 + q*16, gwh + nr*64 + q*16);
            cp16(sbase + W1EL_OFF + nr*80 + q*16, gwl + nr*64 + q*16);
        }
        asm volatile("cp.async.commit_group;" ::: "memory");
        if (tid < H) { sb2[tid] = edge_b2[l*H+tid]; sinfw[tid] = inf_w[l*H+tid]; }
    }
    int t = blockIdx.x;
    if (t < ntiles) edge_prefetch(sbase, t, tid);
    asm volatile("cp.async.wait_group 0;" ::: "memory");
    __syncthreads();

    for (; t < ntiles; t += gridDim.x) {
        int d0 = t * 4;

        for (int i = tid; i < 2048; i += ETH) {
            int el = i >> 4, k2 = i & 15;
            int k = k2*2;
            float f0 = (k   < GG) ? raw[el*GG + k]     : 0.f;
            float f1 = (k+1 < GG) ? raw[el*GG + k + 1] : 0.f;
            __nv_bfloat16 h0 = __float2bfloat16(f0), h1 = __float2bfloat16(f1);
            __nv_bfloat16 l0 = __float2bfloat16(f0 - __bfloat162float(h0));
            __nv_bfloat16 l1 = __float2bfloat16(f1 - __bfloat162float(h1));
            *(unsigned*)((char*)sAtH + el*80 + k2*4) =
                ((unsigned)__bfloat16_as_ushort(h1) << 16) | __bfloat16_as_ushort(h0);
            *(unsigned*)((char*)sAtL + el*80 + k2*4) =
                ((unsigned)__bfloat16_as_ushort(l1) << 16) | __bfloat16_as_ushort(l0);
        }
        for (int i = tid; i < 512; i += ETH) smi[i] = 0.f;
        if (tid < 128) sgate[tid] = infb;
        __syncthreads();

        for (int h = 0; h < 2; ++h) {
            {
                int er = (wrp & 7)*16, jb = (wrp >> 3)*2;
                wmma::fragment<wmma::accumulator,16,16,16,float> a1[2];
#pragma unroll
                for (int j = 0; j < 2; ++j) wmma::fill_fragment(a1[j], 0.f);
#pragma unroll
                for (int k0 = 0; k0 < 32; k0 += 16) {
                    wmma::fragment<wmma::matrix_a,16,16,16,__nv_bfloat16,wmma::row_major> ah, al;
                    wmma::load_matrix_sync(ah, sAtH + er*LDATT + k0, LDATT);
                    wmma::load_matrix_sync(al, sAtL + er*LDATT + k0, LDATT);
#pragma unroll
                    for (int j = 0; j < 2; ++j) {
                        wmma::fragment<wmma::matrix_b,16,16,16,__nv_bfloat16,wmma::col_major> bh, bl;
                        wmma::load_matrix_sync(bh, sWeH + (h*64 + (jb+j)*16)*LDATT + k0, LDATT);
                        wmma::load_matrix_sync(bl, sWeL + (h*64 + (jb+j)*16)*LDATT + k0, LDATT);
                        wmma::mma_sync(a1[j], ah, bh, a1[j]);
                        wmma::mma_sync(a1[j], ah, bl, a1[j]);
                        wmma::mma_sync(a1[j], al, bh, a1[j]);
                    }
                }
#pragma unroll
                for (int j = 0; j < 2; ++j)
                    wmma::store_matrix_sync(D1 + er*LD1 + (jb+j)*16, a1[j], LD1, wmma::mem_row_major);
            }
            __syncthreads();
            {
                int e = tid >> 2, q = tid & 3;
                int srcA = ssrc[e];
                const float4* Brow = (const float4*)(g_B + (size_t)srcA*H);
                const float* sAd = sAv + (e>>5)*H;
#pragma unroll
                for (int i4 = 0; i4 < 4; ++i4) {
                    int kl = q*16 + i4*4;
                    int kg = h*64 + kl;
                    float4 bv = Brow[kg >> 2];
                    float4 gv = *(const float4*)(D1 + e*LD1 + kl);
                    float x0 = fmaxf(gv.x + sAd[kg]   + bv.x, 0.f);
                    float x1 = fmaxf(gv.y + sAd[kg+1] + bv.y, 0.f);
                    float x2 = fmaxf(gv.z + sAd[kg+2] + bv.z, 0.f);
                    float x3 = fmaxf(gv.w + sAd[kg+3] + bv.w, 0.f);
                    __nv_bfloat16 h0 = __float2bfloat16(x0), h1 = __float2bfloat16(x1);
                    __nv_bfloat16 h2 = __float2bfloat16(x2), h3 = __float2bfloat16(x3);
                    __nv_bfloat16 l0 = __float2bfloat16(x0 - __bfloat162float(h0));
                    __nv_bfloat16 l1 = __float2bfloat16(x1 - __bfloat162float(h1));
                    __nv_bfloat16 l2 = __float2bfloat16(x2 - __bfloat162float(h2));
                    __nv_bfloat16 l3 = __float2bfloat16(x3 - __bfloat162float(h3));
                    unsigned hi01 = ((unsigned)__bfloat16_as_ushort(h1) << 16) | __bfloat16_as_ushort(h0);
                    unsigned hi23 = ((unsigned)__bfloat16_as_ushort(h3) << 16) | __bfloat16_as_ushort(h2);
                    unsigned lo01 = ((unsigned)__bfloat16_as_ushort(l1) << 16) | __bfloat16_as_ushort(l0);
                    unsigned lo23 = ((unsigned)__bfloat16_as_ushort(l3) << 16) | __bfloat16_as_ushort(l2);
                    unsigned boff = e*272 + kg*2;
                    *(uint2*)((char*)sM1hi + boff) = make_uint2(hi01, hi23);
                    *(uint2*)((char*)sM1lo + boff) = make_uint2(lo01, lo23);
                }
            }
            __syncthreads();
        }

        int tn = t + gridDim.x;
        if (tn < ntiles) edge_prefetch(sbase, tn, tid);

        {
            int rg = wrp & 3, cgf = wrp >> 2;   // 4 x 4 warp grid
            int er = rg*32, nc = cgf*32;
            wmma::fragment<wmma::accumulator,16,16,16,float> acc[2][2];
#pragma unroll
            for (int i = 0; i < 2; ++i)
#pragma unroll
                for (int j = 0; j < 2; ++j) wmma::fill_fragment(acc[i][j], 0.f);
#pragma unroll
            for (int k0 = 0; k0 < 128; k0 += 16) {
                wmma::fragment<wmma::matrix_a,16,16,16,__nv_bfloat16,wmma::row_major> ah[2], al[2];
                wmma::fragment<wmma::matrix_b,16,16,16,__nv_bfloat16,wmma::col_major> bh[2], bl[2];
#pragma unroll
                for (int i = 0; i < 2; ++i) {
                    wmma::load_matrix_sync(ah[i], sM1hi + (er + i*16)*LDAB + k0, LDAB);
                    wmma::load_matrix_sync(al[i], sM1lo + (er + i*16)*LDAB + k0, LDAB);
                }
#pragma unroll
                for (int j = 0; j < 2; ++j) {
                    wmma::load_matrix_sync(bh[j], sBhi + (nc + j*16)*LDAB + k0, LDAB);
                    wmma::load_matrix_sync(bl[j], sBlo + (nc + j*16)*LDAB + k0, LDAB);
                }
#pragma unroll
                for (int i = 0; i < 2; ++i)
#pragma unroll
                    for (int j = 0; j < 2; ++j) {
                        wmma::mma_sync(acc[i][j], ah[i], bh[j], acc[i][j]);
                        wmma::mma_sync(acc[i][j], ah[i], bl[j], acc[i][j]);
                        wmma::mma_sync(acc[i][j], al[i], bh[j], acc[i][j]);
                    }
            }
            __syncthreads();
#pragma unroll
            for (int i = 0; i < 2; ++i)
#pragma unroll
                for (int j = 0; j < 2; ++j)
                    wmma::store_matrix_sync(D2 + (er + i*16)*132 + nc + j*16, acc[i][j],
                                            132, wmma::mem_row_major);
        }
        __syncthreads();

        {
            int e = tid >> 2, c0 = (tid & 3)*32;
            float p = 0.f;
#pragma unroll 8
            for (int c = 0; c < 32; ++c) {
                float v = D2[e*132 + c0 + c] + sb2[c0 + c];
                v = fmaxf(v, 0.f);
                D2[e*132 + c0 + c] = v;
                p += v * sinfw[c0 + c];
            }
            atomicAdd(&sgate[e], p);
        }
        __syncthreads();
        if (tid < 128) sgate[tid] = 1.f/(1.f + expf(-sgate[tid]));
        __syncthreads();

        {
            int c = tid & 127, hf = tid >> 7;   // 4-way edge split
#pragma unroll
            for (int d = 0; d < 4; ++d) {
                float s = 0.f;
#pragma unroll 4
                for (int j = 0; j < 8; ++j) {
                    int e = d*32 + hf*8 + j;
                    s += D2[e*132 + c] * sgate[e];
                }
                atomicAdd(&smi[d*H + c], s);
            }
        }
        __syncthreads();
        for (int i = tid; i < 4*H; i += ETH) g_mi[(size_t)d0*H + i] = smi[i];
        asm volatile("cp.async.wait_group 0;" ::: "memory");
        __syncthreads();
    }
}

// ---------------- K6: node MLP via WMMA (bias-in-K), 64-node tiles -----------
#define NLDZ 280
#define NLDU 152
#define NZHI_OFF 0
#define NZLO_OFF 35840
#define ND1_OFF  35840
#define NUHI_OFF 71680
#define NULO_OFF 91136
#define ND2_OFF  0
#define NODE_SMEM 110592

__global__ void __launch_bounds__(256) node_kernel(int l)
{
    extern __shared__ __align__(16) char shn[];
    __nv_bfloat16* zHi = (__nv_bfloat16*)(shn + NZHI_OFF);
    __nv_bfloat16* zLo = (__nv_bfloat16*)(shn + NZLO_OFF);
    float* D1 = (float*)(shn + ND1_OFF);
    __nv_bfloat16* uHi = (__nv_bfloat16*)(shn + NUHI_OFF);
    __nv_bfloat16* uLo = (__nv_bfloat16*)(shn + NULO_OFF);
    float* D2 = (float*)(shn + ND2_OFF);

    int tid = threadIdx.x;
    int nb = blockIdx.x*64;

    for (int i = tid; i < 2048; i += 256) {
        int row = i >> 5, k4 = (i & 31)*4;
        float4 mv = *(const float4*)(g_mi + (size_t)(nb+row)*H + k4);
        float4 hv = *(const float4*)(g_h  + (size_t)(nb+row)*H + k4);
        float xm[4] = {mv.x, mv.y, mv.z, mv.w};
        float xh[4] = {hv.x, hv.y, hv.z, hv.w};
#pragma unroll
        for (int q = 0; q < 4; ++q) {
            __nv_bfloat16 mb = __float2bfloat16(xm[q]);
            zHi[row*NLDZ + k4 + q] = mb;
            zLo[row*NLDZ + k4 + q] = __float2bfloat16(xm[q] - __bfloat162float(mb));
            __nv_bfloat16 hb = __float2bfloat16(xh[q]);
            zHi[row*NLDZ + 128 + k4 + q] = hb;
            zLo[row*NLDZ + 128 + k4 + q] = __float2bfloat16(xh[q] - __bfloat162float(hb));
        }
    }
    for (int i = tid; i < 64*16; i += 256) {
        int row = i >> 4, k = 256 + (i & 15);
        zHi[row*NLDZ + k] = (k == 256) ? __float2bfloat16(1.0f) : __float2bfloat16(0.0f);
        zLo[row*NLDZ + k] = __float2bfloat16(0.0f);
    }
    __syncthreads();

    int wrp = tid >> 5;
    int rowg = wrp >> 2, colg = wrp & 3;
    int er = rowg*32, nc = colg*32;
    const __nv_bfloat16* W1h = (const __nv_bfloat16*)g_w1nb + (size_t)(l*2+0)*128*272;
    const __nv_bfloat16* W1l = (const __nv_bfloat16*)g_w1nb + (size_t)(l*2+1)*128*272;

    wmma::fragment<wmma::accumulator,16,16,16,float> acc[2][2];
#pragma unroll
    for (int i = 0; i < 2; ++i)
#pragma unroll
        for (int j = 0; j < 2; ++j) wmma::fill_fragment(acc[i][j], 0.f);
#pragma unroll
    for (int k0 = 0; k0 < 272; k0 += 16) {
        wmma::fragment<wmma::matrix_a,16,16,16,__nv_bfloat16,wmma::row_major> ah[2], al[2];
#pragma unroll
        for (int i = 0; i < 2; ++i) {
            wmma::load_matrix_sync(ah[i], zHi + (er + i*16)*NLDZ + k0, NLDZ);
            wmma::load_matrix_sync(al[i], zLo + (er + i*16)*NLDZ + k0, NLDZ);
        }
#pragma unroll
        for (int j = 0; j < 2; ++j) {
            wmma::fragment<wmma::matrix_b,16,16,16,__nv_bfloat16,wmma::col_major> bh, bl;
            wmma::load_matrix_sync(bh, W1h + (size_t)(nc + j*16)*272 + k0, 272);
            wmma::load_matrix_sync(bl, W1l + (size_t)(nc + j*16)*272 + k0, 272);
#pragma unroll
            for (int i = 0; i < 2; ++i) {
                wmma::mma_sync(acc[i][j], ah[i], bh, acc[i][j]);
                wmma::mma_sync(acc[i][j], ah[i], bl, acc[i][j]);
                wmma::mma_sync(acc[i][j], al[i], bh, acc[i][j]);
            }
        }
    }
    __syncthreads();
#pragma unroll
    for (int i = 0; i < 2; ++i)
#pragma unroll
        for (int j = 0; j < 2; ++j)
            wmma::store_matrix_sync(D1 + (er + i*16)*132 + nc + j*16, acc[i][j],
                                    132, wmma::mem_row_major);
    __syncthreads();

    for (int i = tid; i < 2048; i += 256) {
        int row = i >> 5, k4 = (i & 31)*4;
        float4 uv = *(const float4*)(D1 + row*132 + k4);
        float x[4] = {fmaxf(uv.x,0.f), fmaxf(uv.y,0.f), fmaxf(uv.z,0.f), fmaxf(uv.w,0.f)};
#pragma unroll
        for (int q = 0; q < 4; ++q) {
            __nv_bfloat16 ub = __float2bfloat16(x[q]);
            uHi[row*NLDU + k4 + q] = ub;
            uLo[row*NLDU + k4 + q] = __float2bfloat16(x[q] - __bfloat162float(ub));
        }
    }
    for (int i = tid; i < 64*16; i += 256) {
        int row = i >> 4, k = 128 + (i & 15);
        uHi[row*NLDU + k] = (k == 128) ? __float2bfloat16(1.0f) : __float2bfloat16(0.0f);
        uLo[row*NLDU + k] = __float2bfloat16(0.0f);
    }
    __syncthreads();

    const __nv_bfloat16* W2h = (const __nv_bfloat16*)g_w2nb + (size_t)(l*2+0)*128*144;
    const __nv_bfloat16* W2l = (const __nv_bfloat16*)g_w2nb + (size_t)(l*2+1)*128*144;
#pragma unroll
    for (int i = 0; i < 2; ++i)
#pragma unroll
        for (int j = 0; j < 2; ++j) wmma::fill_fragment(acc[i][j], 0.f);
#pragma unroll
    for (int k0 = 0; k0 < 144; k0 += 16) {
        wmma::fragment<wmma::matrix_a,16,16,16,__nv_bfloat16,wmma::row_major> ah[2], al[2];
#pragma unroll
        for (int i = 0; i < 2; ++i) {
            wmma::load_matrix_sync(ah[i], uHi + (er + i*16)*NLDU + k0, NLDU);
            wmma::load_matrix_sync(al[i], uLo + (er + i*16)*NLDU + k0, NLDU);
        }
#pragma unroll
        for (int j = 0; j < 2; ++j) {
            wmma::fragment<wmma::matrix_b,16,16,16,__nv_bfloat16,wmma::col_major> bh, bl;
            wmma::load_matrix_sync(bh, W2h + (size_t)(nc + j*16)*144 + k0, 144);
            wmma::load_matrix_sync(bl, W2l + (size_t)(nc + j*16)*144 + k0, 144);
#pragma unroll
            for (int i = 0; i < 2; ++i) {
                wmma::mma_sync(acc[i][j], ah[i], bh, acc[i][j]);
                wmma::mma_sync(acc[i][j], ah[i], bl, acc[i][j]);
                wmma::mma_sync(acc[i][j], al[i], bh, acc[i][j]);
            }
        }
    }
#pragma unroll
    for (int i = 0; i < 2; ++i)
#pragma unroll
        for (int j = 0; j < 2; ++j)
            wmma::store_matrix_sync(D2 + (er + i*16)*132 + nc + j*16, acc[i][j],
                                    132, wmma::mem_row_major);
    __syncthreads();

    for (int i = tid; i < 2048; i += 256) {
        int row = i >> 5, k4 = (i & 31)*4;
        float4 ov = *(const float4*)(D2 + row*132 + k4);
        float4* hp = (float4*)(g_h + (size_t)(nb+row)*H + k4);
        float4 hv = *hp;
        hv.x += ov.x; hv.y += ov.y; hv.z += ov.z; hv.w += ov.w;
        *hp = hv;
    }
}

// ---------------- K7/K8 ------------------------------------------------------
__global__ void pool_kernel(int n)
{
    int b = blockIdx.x >> 4, s = blockIdx.x & 15;
    int c = threadIdx.x;
    float acc = 0.f;
    for (int i = s; i < n; i += 16) acc += g_h[((size_t)b*n + i)*H + c];
    atomicAdd(&g_pre[b*H + c], acc);
}

__global__ void out_kernel(const float* __restrict__ w1, const float* __restrict__ b1,
                           const float* __restrict__ w2, const float* __restrict__ b2,
                           const int* __restrict__ kind, float* __restrict__ out, int B)
{
    __shared__ float sU[H]; __shared__ float so[3];
    int t = threadIdx.x;
    for (int b = 0; b < B; ++b) {
        float x = b1[t];
        for (int k = 0; k < H; ++k) x += g_pre[b*H + k]*w1[k*H + t];
        float sp = (x > 0.f) ? x + log1pf(expf(-x)) : log1pf(expf(x));
        sU[t] = sp - 0.6931471805599453f;
        __syncthreads();
        if (t < 3) { float s = b2[t]; for (int k = 0; k < H; ++k) s += sU[k]*w2[k*3 + t]; so[t] = s; }
        __syncthreads();
        if (t == 0) out[b] = so[kind[b] - 1];
        __syncthreads();
    }
}

// ---------------- host ------------------------------------------------------
extern "C" void kernel_launch(void* const* d_in, const int* in_sizes, int n_in,
                              void* d_out, int out_size)
{
    const float* protein_pos  = (const float*)d_in[0];
    const float* protein_feat = (const float*)d_in[1];
    const float* ligand_pos   = (const float*)d_in[2];
    const float* ligand_feat  = (const float*)d_in[3];
    const int*   output_kind  = (const int*)d_in[6];
    const float* prot_w = (const float*)d_in[7];  const float* prot_b = (const float*)d_in[8];
    const float* lig_w  = (const float*)d_in[9];  const float* lig_b  = (const float*)d_in[10];
    const float* edge_w1 = (const float*)d_in[11]; const float* edge_b1 = (const float*)d_in[12];
    const float* edge_w2 = (const float*)d_in[13]; const float* edge_b2 = (const float*)d_in[14];
    const float* inf_w   = (const float*)d_in[15]; const float* inf_b   = (const float*)d_in[16];
    const float* node_w1 = (const float*)d_in[17]; const float* node_b1 = (const float*)d_in[18];
    const float* node_w2 = (const float*)d_in[19]; const float* node_b2 = (const float*)d_in[20];
    const float* out_w1  = (const float*)d_in[21]; const float* out_b1  = (const float*)d_in[22];
    const float* out_w2  = (const float*)d_in[23]; const float* out_b2  = (const float*)d_in[24];
    float* out = (float*)d_out;

    int Np = in_sizes[0]/3, Nl = in_sizes[2]/3;
    int B  = in_sizes[6];
    int Fp = in_sizes[1]/Np, Fl = in_sizes[3]/Nl;
    int n_prot = Np/B, n_lig = Nl/B;
    int n = n_prot + n_lig;
    int N = Np + Nl;
    int E = N*KNN;
    int ntiles = E/128;

    int nsm = 148;
    cudaDeviceGetAttribute(&nsm, cudaDevAttrMultiProcessorCount, 0);

    cudaFuncSetAttribute(edge_kernel, cudaFuncAttributeMaxDynamicSharedMemorySize, EDGE_SMEM);
    cudaFuncSetAttribute(node_kernel, cudaFuncAttributeMaxDynamicSharedMemorySize, NODE_SMEM);

    embed_kernel<<<N, 128>>>(protein_pos, protein_feat, ligand_pos, ligand_feat,
                             prot_w, prot_b, lig_w, lig_b, n_prot, n_lig, n, Fp, Fl);

    knn_kernel<<<dim3((n + 127)/128, B), 128, n*(int)sizeof(float4)>>>(n);

    w2prep_kernel<<<3*128, 128>>>(edge_w2, edge_w1);
    w1abprep_kernel<<<3*256, 144>>>(edge_w1, edge_b1);
    w1nprep_kernel<<<3*128, 272>>>(node_w1, node_b1);
    w2nprep_kernel<<<3*128, 144>>>(node_w2, node_b2);

    float step  = 10.0f/19.0f;
    float coeff = -0.5f/(step*step);
    attr_kernel<<<(E + 255)/256, 256>>>(E, step, coeff);

    ab_kernel<<<N/64, 256>>>(0);
    for (int l = 0; l < 3; ++l) {
        edge_kernel<<<nsm, ETH, EDGE_SMEM>>>(edge_b2, inf_w, inf_b, l, ntiles);
        node_kernel<<<N/64, 256, NODE_SMEM>>>(l);
        if (l < 2) ab_kernel<<<N/64, 256>>>(l + 1);
    }

    pool_kernel<<<B*16, 128>>>(n);
    out_kernel<<<1, 128>>>(out_w1, out_b1, out_w2, out_b2, output_kind, out, B);
}